// round 2
// baseline (speedup 1.0000x reference)
#include <cuda_runtime.h>
#include <math.h>

// ---------------- problem constants ----------------
#define D_MODEL 1024
#define N_HEADc 16
#define D_HEADc 64
#define FFN_H   4096
#define Bb      4
#define Tt      2048
#define Mm      2048
#define KK      4096            // M + T
#define ROWS_X  (Bb*Tt)         // 8192
#define ROWS_C  (Bb*KK)         // 16384

// ---------------- scratch (static device memory; no runtime alloc) ----------------
static __device__ float g_P   [(size_t)KK*D_MODEL];
static __device__ float g_r   [(size_t)KK*D_MODEL];
static __device__ float g_q   [(size_t)ROWS_X*D_MODEL];
static __device__ float g_c   [(size_t)ROWS_C*D_MODEL];
static __device__ float g_k   [(size_t)ROWS_C*D_MODEL];
static __device__ float g_v   [(size_t)ROWS_C*D_MODEL];
static __device__ float g_attn[(size_t)ROWS_X*D_MODEL];
static __device__ float g_s   [(size_t)ROWS_X*D_MODEL];
static __device__ float g_h   [(size_t)ROWS_X*D_MODEL];
static __device__ float g_f1  [(size_t)ROWS_X*FFN_H];

// ---------------- helpers ----------------
__device__ __forceinline__ float gelu_f(float x) {
    // jax.nn.gelu default: approximate=True (tanh form)
    float x3 = x * x * x;
    float t  = tanhf(0.7978845608028654f * (x + 0.044715f * x3));
    return 0.5f * x * (1.0f + t);
}

// ---------------- sinusoid positional table P[K, D] ----------------
__global__ void fill_pos(float* __restrict__ P) {
    int idx = blockIdx.x * blockDim.x + threadIdx.x;
    if (idx >= KK * D_MODEL) return;
    int m   = idx / D_MODEL;
    int col = idx - m * D_MODEL;
    float pos = (float)(KK - 1 - m);
    int f = (col < D_MODEL / 2) ? col : col - D_MODEL / 2;
    // inv_freq computed in double so our only mismatch vs JAX's fp32 pow is JAX's own ulp
    double invf = exp(-((double)(2 * f) / (double)D_MODEL) * log(10000.0));
    float ang = pos * (float)invf;
    P[idx] = (col < D_MODEL / 2) ? sinf(ang) : cosf(ang);
}

// ---------------- concat c = [mem, x] along seq ----------------
__global__ void concat_kernel(const float* __restrict__ x, const float* __restrict__ mem,
                              float* __restrict__ c) {
    int idx = blockIdx.x * blockDim.x + threadIdx.x;     // float4 units
    const int row_f4 = D_MODEL / 4;                      // 256
    if (idx >= ROWS_C * row_f4) return;
    int row = idx / row_f4;
    int col = idx - row * row_f4;
    int b = row / KK;
    int t = row - b * KK;
    const float4* src;
    if (t < Mm) src = (const float4*)mem + ((size_t)(b * Mm + t)) * row_f4 + col;
    else        src = (const float4*)x   + ((size_t)(b * Tt + (t - Mm))) * row_f4 + col;
    ((float4*)c)[idx] = *src;
}

// ---------------- generic 128x128x16 SGEMM, 8x8 per thread ----------------
// EPI: 0 = +bias ; 1 = gelu(+bias) ; 2 = +bias +res
template <int EPI>
__global__ void __launch_bounds__(256)
sgemm(const float* __restrict__ A, const float* __restrict__ Bm,
      const float* __restrict__ bias, const float* __restrict__ res,
      float* __restrict__ C, int Mdim, int Ndim, int Kdim) {
    __shared__ float As[16][128];   // As[k][m]
    __shared__ float Bs[16][128];   // Bs[k][n]
    const int tid = threadIdx.x;
    const int bm = blockIdx.y * 128, bn = blockIdx.x * 128;
    const int trow = (tid / 16) * 8, tcol = (tid % 16) * 8;

    float acc[8][8];
#pragma unroll
    for (int i = 0; i < 8; i++)
#pragma unroll
        for (int j = 0; j < 8; j++) acc[i][j] = 0.f;

    for (int k0 = 0; k0 < Kdim; k0 += 16) {
#pragma unroll
        for (int p = 0; p < 2; p++) {
            int idx = tid + p * 256;                    // 0..511
            int r  = idx >> 2, ca = (idx & 3) << 2;     // A: 128 rows x 16 cols
            float4 av = *(const float4*)&A[(size_t)(bm + r) * Kdim + k0 + ca];
            As[ca + 0][r] = av.x; As[ca + 1][r] = av.y;
            As[ca + 2][r] = av.z; As[ca + 3][r] = av.w;
            int rb = idx >> 5, cb = (idx & 31) << 2;    // B: 16 rows x 128 cols
            *(float4*)&Bs[rb][cb] = *(const float4*)&Bm[(size_t)(k0 + rb) * Ndim + bn + cb];
        }
        __syncthreads();
#pragma unroll
        for (int kk = 0; kk < 16; kk++) {
            float a[8], b[8];
            *(float4*)(a)     = *(float4*)&As[kk][trow];
            *(float4*)(a + 4) = *(float4*)&As[kk][trow + 4];
            *(float4*)(b)     = *(float4*)&Bs[kk][tcol];
            *(float4*)(b + 4) = *(float4*)&Bs[kk][tcol + 4];
#pragma unroll
            for (int i = 0; i < 8; i++)
#pragma unroll
                for (int j = 0; j < 8; j++) acc[i][j] += a[i] * b[j];
        }
        __syncthreads();
    }

#pragma unroll
    for (int i = 0; i < 8; i++) {
        size_t rowoff = (size_t)(bm + trow + i) * Ndim + bn + tcol;
#pragma unroll
        for (int j = 0; j < 8; j++) {
            float val = acc[i][j];
            if (bias) val += bias[bn + tcol + j];
            if (EPI == 1) val = gelu_f(val);
            if (EPI == 2) val += res[rowoff + j];
            C[rowoff + j] = val;
        }
    }
}

// ---------------- flash attention with Transformer-XL relative term ----------------
// Grid: (T/64, H, B). 256 threads viewed as (ty=tid>>3 in [0,32), tx=tid&7 in [0,8)).
// Each thread: 2 rows (ty*2, ty*2+1) x 8 cols (tx*8..tx*8+7) of the 64x64 score tile,
// and 2 rows x 8 d-cols (d = tx*8+dd) of the output accumulator.
__global__ void __launch_bounds__(256)
flash_xl(const float* __restrict__ qg, const float* __restrict__ kg,
         const float* __restrict__ vg, const float* __restrict__ rg,
         const float* __restrict__ ug, const float* __restrict__ vpg,
         const int* __restrict__ iscp, float* __restrict__ outg) {
    extern __shared__ float sm[];
    float* Qs  = sm;                  // [64][65]
    float* Us  = Qs  + 64 * 65;       // [64]
    float* Vps = Us  + 64;            // [64]
    float* Kst = Vps + 64;            // [64 d][65] (transposed, padded)
    float* Rs  = Kst + 64 * 65;       // [128 m][65]
    float* Vs  = Rs  + 128 * 65;      // [64 j][64 d]
    float* Ps  = Vs  + 64 * 64;       // [64 r][65]

    const int tid = threadIdx.x;
    const int tx = tid & 7, ty = tid >> 3;
    const int i0 = blockIdx.x * 64, h = blockIdx.y, b = blockIdx.z;
    const int r0l = ty * 2, r1l = r0l + 1;
    const int causal = iscp[0];

    // load Q tile (raw; u/v added in the S loop) + u/v vectors
    {
        const float* qbase = qg + ((size_t)(b * Tt + i0)) * D_MODEL + h * D_HEADc;
#pragma unroll
        for (int p = 0; p < 4; p++) {
            int idx = tid + p * 256;            // 1024 float4 over 64x64
            int rl = idx >> 4; int ca = (idx & 15) << 2;
            float4 v4 = *(const float4*)&qbase[(size_t)rl * D_MODEL + ca];
            Qs[rl * 65 + ca]     = v4.x; Qs[rl * 65 + ca + 1] = v4.y;
            Qs[rl * 65 + ca + 2] = v4.z; Qs[rl * 65 + ca + 3] = v4.w;
        }
        if (tid < 64) { Us[tid] = ug[h * D_HEADc + tid]; Vps[tid] = vpg[h * D_HEADc + tid]; }
    }

    float mi0 = -1e30f, mi1 = -1e30f, li0 = 0.f, li1 = 0.f;
    float o0[8], o1[8];
#pragma unroll
    for (int d = 0; d < 8; d++) { o0[d] = 0.f; o1[d] = 0.f; }

    const int njt = (Mm + i0) / 64 + 1;     // covers all j <= i0+63+M
    const int mbase0 = Tt - 64 - i0;        // + j0 => lowest R row in window

    for (int jt = 0; jt < njt; jt++) {
        const int j0 = jt * 64;
        __syncthreads();   // protect Ps/Vs/Kst/Rs (prev iter readers done)

        {   // K tile transposed, V tile
            const float* kbase = kg + ((size_t)(b * KK + j0)) * D_MODEL + h * D_HEADc;
            const float* vbase = vg + ((size_t)(b * KK + j0)) * D_MODEL + h * D_HEADc;
#pragma unroll
            for (int p = 0; p < 4; p++) {
                int idx = tid + p * 256;
                int j = idx >> 4; int ca = (idx & 15) << 2;
                float4 kv = *(const float4*)&kbase[(size_t)j * D_MODEL + ca];
                Kst[(ca + 0) * 65 + j] = kv.x; Kst[(ca + 1) * 65 + j] = kv.y;
                Kst[(ca + 2) * 65 + j] = kv.z; Kst[(ca + 3) * 65 + j] = kv.w;
                *(float4*)&Vs[j * 64 + ca] = *(const float4*)&vbase[(size_t)j * D_MODEL + ca];
            }
            // R window: 128 rows (m_local = j + 63 - r), clamp only hits masked entries
            const int mb = mbase0 + j0;
#pragma unroll
            for (int p = 0; p < 8; p++) {
                int idx = tid + p * 256;          // 2048 float4 over 128x64
                int mmz = idx >> 4; int ca = (idx & 15) << 2;
                int mg = mb + mmz; if (mg > KK - 1) mg = KK - 1;
                float4 rv = *(const float4*)&rg[(size_t)mg * D_MODEL + h * D_HEADc + ca];
                Rs[mmz * 65 + ca]     = rv.x; Rs[mmz * 65 + ca + 1] = rv.y;
                Rs[mmz * 65 + ca + 2] = rv.z; Rs[mmz * 65 + ca + 3] = rv.w;
            }
        }
        __syncthreads();

        // S = (Q+u) K^T + (Q+v) R^T   (R row shifts with query row)
        float s0[8], s1[8];
#pragma unroll
        for (int jj = 0; jj < 8; jj++) { s0[jj] = 0.f; s1[jj] = 0.f; }
#pragma unroll 4
        for (int d = 0; d < 64; d++) {
            float q0 = Qs[r0l * 65 + d], q1 = Qs[r1l * 65 + d];
            float ud = Us[d], vd = Vps[d];
            float qu0 = q0 + ud, qu1 = q1 + ud;
            float qv0 = q0 + vd, qv1 = q1 + vd;
#pragma unroll
            for (int jj = 0; jj < 8; jj++) {
                int j = tx * 8 + jj;
                float kv = Kst[d * 65 + j];
                s0[jj] += qu0 * kv;
                s1[jj] += qu1 * kv;
                float rv0 = Rs[(j + 63 - r0l) * 65 + d];
                float rv1 = Rs[(j + 63 - r1l) * 65 + d];
                s0[jj] += qv0 * rv0;
                s1[jj] += qv1 * rv1;
            }
        }

        // scale + causal mask + online softmax
        const float scale = 0.125f;   // 1/sqrt(64)
        const int ig0 = i0 + r0l, ig1 = i0 + r1l;
        float rm0 = -1e30f, rm1 = -1e30f;
#pragma unroll
        for (int jj = 0; jj < 8; jj++) {
            int jgl = j0 + tx * 8 + jj;
            float v0 = s0[jj] * scale, v1 = s1[jj] * scale;
            if (causal && jgl > ig0 + Mm) v0 = -1e30f;
            if (causal && jgl > ig1 + Mm) v1 = -1e30f;
            s0[jj] = v0; s1[jj] = v1;
            rm0 = fmaxf(rm0, v0); rm1 = fmaxf(rm1, v1);
        }
#pragma unroll
        for (int off = 1; off < 8; off <<= 1) {
            rm0 = fmaxf(rm0, __shfl_xor_sync(0xffffffffu, rm0, off));
            rm1 = fmaxf(rm1, __shfl_xor_sync(0xffffffffu, rm1, off));
        }
        float mn0 = fmaxf(mi0, rm0), mn1 = fmaxf(mi1, rm1);
        float corr0 = (mi0 < -0.9e30f) ? 0.f : __expf(mi0 - mn0);
        float corr1 = (mi1 < -0.9e30f) ? 0.f : __expf(mi1 - mn1);
        float sum0 = 0.f, sum1 = 0.f;
#pragma unroll
        for (int jj = 0; jj < 8; jj++) {
            float p0 = (s0[jj] < -0.9e30f) ? 0.f : __expf(s0[jj] - mn0);
            float p1 = (s1[jj] < -0.9e30f) ? 0.f : __expf(s1[jj] - mn1);
            s0[jj] = p0; s1[jj] = p1;
            sum0 += p0; sum1 += p1;
        }
#pragma unroll
        for (int off = 1; off < 8; off <<= 1) {
            sum0 += __shfl_xor_sync(0xffffffffu, sum0, off);
            sum1 += __shfl_xor_sync(0xffffffffu, sum1, off);
        }
        li0 = li0 * corr0 + sum0; li1 = li1 * corr1 + sum1;
        mi0 = mn0; mi1 = mn1;
#pragma unroll
        for (int dd = 0; dd < 8; dd++) { o0[dd] *= corr0; o1[dd] *= corr1; }

        // stage P, then O += P V
#pragma unroll
        for (int jj = 0; jj < 8; jj++) {
            Ps[r0l * 65 + tx * 8 + jj] = s0[jj];
            Ps[r1l * 65 + tx * 8 + jj] = s1[jj];
        }
        __syncthreads();
#pragma unroll 4
        for (int j = 0; j < 64; j++) {
            float p0 = Ps[r0l * 65 + j], p1 = Ps[r1l * 65 + j];
            float4 va = *(const float4*)&Vs[j * 64 + tx * 8];
            float4 vb = *(const float4*)&Vs[j * 64 + tx * 8 + 4];
            o0[0] += p0 * va.x; o0[1] += p0 * va.y; o0[2] += p0 * va.z; o0[3] += p0 * va.w;
            o0[4] += p0 * vb.x; o0[5] += p0 * vb.y; o0[6] += p0 * vb.z; o0[7] += p0 * vb.w;
            o1[0] += p1 * va.x; o1[1] += p1 * va.y; o1[2] += p1 * va.z; o1[3] += p1 * va.w;
            o1[4] += p1 * vb.x; o1[5] += p1 * vb.y; o1[6] += p1 * vb.z; o1[7] += p1 * vb.w;
        }
    }

    float inv0 = 1.f / li0, inv1 = 1.f / li1;
    float* ob0 = outg + ((size_t)(b * Tt + i0 + r0l)) * D_MODEL + h * D_HEADc + tx * 8;
    float* ob1 = outg + ((size_t)(b * Tt + i0 + r1l)) * D_MODEL + h * D_HEADc + tx * 8;
    float4 w;
    w = make_float4(o0[0]*inv0, o0[1]*inv0, o0[2]*inv0, o0[3]*inv0); *(float4*)ob0 = w;
    w = make_float4(o0[4]*inv0, o0[5]*inv0, o0[6]*inv0, o0[7]*inv0); *(float4*)(ob0+4) = w;
    w = make_float4(o1[0]*inv1, o1[1]*inv1, o1[2]*inv1, o1[3]*inv1); *(float4*)ob1 = w;
    w = make_float4(o1[4]*inv1, o1[5]*inv1, o1[6]*inv1, o1[7]*inv1); *(float4*)(ob1+4) = w;
}

// ---------------- LayerNorm over last dim (D=1024), one block per row ----------------
__global__ void __launch_bounds__(256)
layernorm_k(const float* __restrict__ in, const float* __restrict__ g,
            const float* __restrict__ be, float* __restrict__ out) {
    __shared__ float red[34];
    const int row = blockIdx.x;
    const int tid = threadIdx.x;
    float4 v = ((const float4*)(in + (size_t)row * D_MODEL))[tid];

    float s = v.x + v.y + v.z + v.w;
    int lane = tid & 31, wid = tid >> 5;
#pragma unroll
    for (int off = 16; off >= 1; off >>= 1) s += __shfl_xor_sync(0xffffffffu, s, off);
    if (lane == 0) red[wid] = s;
    __syncthreads();
    if (tid == 0) {
        float t = 0.f;
#pragma unroll
        for (int w2 = 0; w2 < 8; w2++) t += red[w2];
        red[32] = t;
    }
    __syncthreads();
    float mu = red[32] * (1.f / (float)D_MODEL);

    float dx0 = v.x - mu, dx1 = v.y - mu, dx2 = v.z - mu, dx3 = v.w - mu;
    float sq = dx0 * dx0 + dx1 * dx1 + dx2 * dx2 + dx3 * dx3;
#pragma unroll
    for (int off = 16; off >= 1; off >>= 1) sq += __shfl_xor_sync(0xffffffffu, sq, off);
    if (lane == 0) red[wid] = sq;
    __syncthreads();
    if (tid == 0) {
        float t = 0.f;
#pragma unroll
        for (int w2 = 0; w2 < 8; w2++) t += red[w2];
        red[33] = t;
    }
    __syncthreads();
    float rstd = rsqrtf(red[33] * (1.f / (float)D_MODEL) + 1e-5f);

    float4 gv = ((const float4*)g)[tid];
    float4 bv = ((const float4*)be)[tid];
    float4 o;
    o.x = dx0 * rstd * gv.x + bv.x;
    o.y = dx1 * rstd * gv.y + bv.y;
    o.z = dx2 * rstd * gv.z + bv.z;
    o.w = dx3 * rstd * gv.w + bv.w;
    ((float4*)(out + (size_t)row * D_MODEL))[tid] = o;
}

// ---------------- launch ----------------
extern "C" void kernel_launch(void* const* d_in, const int* in_sizes, int n_in,
                              void* d_out, int out_size) {
    const float* x    = (const float*)d_in[0];
    const float* mem  = (const float*)d_in[1];
    const float* Wq   = (const float*)d_in[2];
    const float* bq   = (const float*)d_in[3];
    const float* Wk   = (const float*)d_in[4];
    const float* bk   = (const float*)d_in[5];
    const float* Wv   = (const float*)d_in[6];
    const float* bv   = (const float*)d_in[7];
    const float* Wo   = (const float*)d_in[8];
    const float* bo   = (const float*)d_in[9];
    const float* Wr   = (const float*)d_in[10];
    const float* u    = (const float*)d_in[11];
    const float* vpar = (const float*)d_in[12];
    const float* g1   = (const float*)d_in[13];
    const float* be1  = (const float*)d_in[14];
    const float* g2   = (const float*)d_in[15];
    const float* be2  = (const float*)d_in[16];
    const float* W1   = (const float*)d_in[17];
    const float* b1   = (const float*)d_in[18];
    const float* W2   = (const float*)d_in[19];
    const float* b2   = (const float*)d_in[20];
    const int*   isc  = (const int*)d_in[21];
    float* out = (float*)d_out;

    float *P, *r, *q, *c, *k, *vv, *attn, *s, *h, *f1;
    cudaGetSymbolAddress((void**)&P,    g_P);
    cudaGetSymbolAddress((void**)&r,    g_r);
    cudaGetSymbolAddress((void**)&q,    g_q);
    cudaGetSymbolAddress((void**)&c,    g_c);
    cudaGetSymbolAddress((void**)&k,    g_k);
    cudaGetSymbolAddress((void**)&vv,   g_v);
    cudaGetSymbolAddress((void**)&attn, g_attn);
    cudaGetSymbolAddress((void**)&s,    g_s);
    cudaGetSymbolAddress((void**)&h,    g_h);
    cudaGetSymbolAddress((void**)&f1,   g_f1);

    fill_pos<<<(KK * D_MODEL + 255) / 256, 256>>>(P);
    concat_kernel<<<(ROWS_C * (D_MODEL / 4) + 255) / 256, 256>>>(x, mem, c);

    // projections
    sgemm<0><<<dim3(D_MODEL / 128, ROWS_X / 128), 256>>>(x, Wq, bq, nullptr, q, ROWS_X, D_MODEL, D_MODEL);
    sgemm<0><<<dim3(D_MODEL / 128, ROWS_C / 128), 256>>>(c, Wk, bk, nullptr, k, ROWS_C, D_MODEL, D_MODEL);
    sgemm<0><<<dim3(D_MODEL / 128, ROWS_C / 128), 256>>>(c, Wv, bv, nullptr, vv, ROWS_C, D_MODEL, D_MODEL);
    sgemm<0><<<dim3(D_MODEL / 128, KK / 128), 256>>>(P, Wr, nullptr, nullptr, r, KK, D_MODEL, D_MODEL);

    // attention
    size_t smemB = (size_t)(64 * 65 + 64 + 64 + 64 * 65 + 128 * 65 + 64 * 64 + 64 * 65) * 4;
    cudaFuncSetAttribute(flash_xl, cudaFuncAttributeMaxDynamicSharedMemorySize, (int)smemB);
    flash_xl<<<dim3(Tt / 64, N_HEADc, Bb), 256, smemB>>>(q, k, vv, r, u, vpar, isc, attn);

    // o-proj + residual, LN1
    sgemm<2><<<dim3(D_MODEL / 128, ROWS_X / 128), 256>>>(attn, Wo, bo, x, s, ROWS_X, D_MODEL, D_MODEL);
    layernorm_k<<<ROWS_X, 256>>>(s, g1, be1, h);

    // FFN
    sgemm<1><<<dim3(FFN_H / 128, ROWS_X / 128), 256>>>(h, W1, b1, nullptr, f1, ROWS_X, FFN_H, D_MODEL);
    sgemm<2><<<dim3(D_MODEL / 128, ROWS_X / 128), 256>>>(f1, W2, b2, h, s, ROWS_X, D_MODEL, FFN_H);
    layernorm_k<<<ROWS_X, 256>>>(s, g2, be2, out);
}

// round 4
// speedup vs baseline: 1.3149x; 1.3149x over previous
#include <cuda_runtime.h>
#include <math.h>
#include <stdint.h>

// ---------------- problem constants ----------------
#define D_MODEL 1024
#define N_HEADc 16
#define D_HEADc 64
#define FFN_H   4096
#define Bb      4
#define Tt      2048
#define Mm      2048
#define KK      4096            // M + T
#define ROWS_X  (Bb*Tt)         // 8192
#define ROWS_C  (Bb*KK)         // 16384

// ---------------- scratch (static device memory; no runtime alloc) ----------------
static __device__ float g_P   [(size_t)KK*D_MODEL];
static __device__ float g_r   [(size_t)KK*D_MODEL];
static __device__ float g_q   [(size_t)ROWS_X*D_MODEL];
static __device__ float g_c   [(size_t)ROWS_C*D_MODEL];
static __device__ float g_k   [(size_t)ROWS_C*D_MODEL];
static __device__ float g_v   [(size_t)ROWS_C*D_MODEL];
static __device__ float g_attn[(size_t)ROWS_X*D_MODEL];
static __device__ float g_s   [(size_t)ROWS_X*D_MODEL];
static __device__ float g_h   [(size_t)ROWS_X*D_MODEL];
static __device__ float g_f1  [(size_t)ROWS_X*FFN_H];
static __device__ float g_invf[512];

// ---------------- helpers ----------------
__device__ __forceinline__ float gelu_f(float x) {
    float x3 = x * x * x;
    float t  = tanhf(0.7978845608028654f * (x + 0.044715f * x3));
    return 0.5f * x * (1.0f + t);
}

__device__ __forceinline__ uint32_t f2tf32(float x) {
    uint32_t r;
    asm("cvt.rna.tf32.f32 %0, %1;" : "=r"(r) : "f"(x));
    return r;
}

__device__ __forceinline__ void mma_tf32(float c[4], uint32_t a0, uint32_t a1,
                                         uint32_t a2, uint32_t a3,
                                         uint32_t b0, uint32_t b1) {
    asm volatile(
        "mma.sync.aligned.m16n8k8.row.col.f32.tf32.tf32.f32 "
        "{%0,%1,%2,%3},{%4,%5,%6,%7},{%8,%9},{%0,%1,%2,%3};"
        : "+f"(c[0]), "+f"(c[1]), "+f"(c[2]), "+f"(c[3])
        : "r"(a0), "r"(a1), "r"(a2), "r"(a3), "r"(b0), "r"(b1));
}

__device__ __forceinline__ void cp16(void* smem, const void* g) {
    uint32_t s = (uint32_t)__cvta_generic_to_shared(smem);
    asm volatile("cp.async.cg.shared.global [%0], [%1], 16;" :: "r"(s), "l"(g));
}

// ---------------- positional tables ----------------
__global__ void fill_invf(float* __restrict__ invf) {
    int f = threadIdx.x;
    if (f < 512) {
        double v = exp(-((double)(2 * f) / (double)D_MODEL) * log(10000.0));
        invf[f] = (float)v;
    }
}

__global__ void fill_pos(float* __restrict__ P, const float* __restrict__ invf) {
    int idx = blockIdx.x * blockDim.x + threadIdx.x;
    if (idx >= KK * D_MODEL) return;
    int m   = idx / D_MODEL;
    int col = idx - m * D_MODEL;
    float pos = (float)(KK - 1 - m);
    int f = (col < D_MODEL / 2) ? col : col - D_MODEL / 2;
    float ang = pos * __ldg(&invf[f]);
    P[idx] = (col < D_MODEL / 2) ? sinf(ang) : cosf(ang);
}

// ---------------- concat c = [mem, x] along seq ----------------
__global__ void concat_kernel(const float* __restrict__ x, const float* __restrict__ mem,
                              float* __restrict__ c) {
    int idx = blockIdx.x * blockDim.x + threadIdx.x;     // float4 units
    const int row_f4 = D_MODEL / 4;                      // 256
    if (idx >= ROWS_C * row_f4) return;
    int row = idx / row_f4;
    int col = idx - row * row_f4;
    int b = row / KK;
    int t = row - b * KK;
    const float4* src;
    if (t < Mm) src = (const float4*)mem + ((size_t)(b * Mm + t)) * row_f4 + col;
    else        src = (const float4*)x   + ((size_t)(b * Tt + (t - Mm))) * row_f4 + col;
    ((float4*)c)[idx] = *src;
}

// ---------------- tf32 tensor-core GEMM: 128x128 tile, 32-deep K stages ----------------
// EPI: 0 = +bias ; 1 = gelu(+bias) ; 2 = +bias +res
// Smem per stage: A[128][36] (pad 4), B[32][136] (pad 8) -> conflict-free mma frag reads.
#define TG_AS (128*36)
#define TG_BS (32*136)
#define TG_STG (TG_AS + TG_BS)
#define TG_SMEM (3 * TG_STG * 4)

template <int EPI>
__global__ void __launch_bounds__(256)
tgemm(const float* __restrict__ A, const float* __restrict__ Bm,
      const float* __restrict__ bias, const float* __restrict__ res,
      float* __restrict__ C, int Ndim, int Kdim) {
    extern __shared__ float smx[];
    const int tid = threadIdx.x, wid = tid >> 5, lane = tid & 31;
    const int bm = blockIdx.y * 128, bn = blockIdx.x * 128;
    const int wm = (wid >> 2) * 64, wn = (wid & 3) * 32;
    const int KT = Kdim / 32;

    float acc[4][4][4];
#pragma unroll
    for (int mi = 0; mi < 4; mi++)
#pragma unroll
        for (int nj = 0; nj < 4; nj++)
#pragma unroll
            for (int e = 0; e < 4; e++) acc[mi][nj][e] = 0.f;

    auto issue = [&](int kt) {
        int s = kt % 3;
        float* As = smx + s * TG_STG;
        float* Bs = As + TG_AS;
        int k0 = kt * 32;
#pragma unroll
        for (int p = 0; p < 4; p++) {
            int f4 = tid + p * 256;            // A: 128 rows x 8 float4
            int r = f4 >> 3, c4 = (f4 & 7) << 2;
            cp16(&As[r * 36 + c4], &A[(size_t)(bm + r) * Kdim + k0 + c4]);
        }
#pragma unroll
        for (int p = 0; p < 4; p++) {
            int f4 = tid + p * 256;            // B: 32 rows x 32 float4
            int r = f4 >> 5, c4 = (f4 & 31) << 2;
            cp16(&Bs[r * 136 + c4], &Bm[(size_t)(k0 + r) * Ndim + bn + c4]);
        }
        asm volatile("cp.async.commit_group;");
    };

    auto compute = [&](int s) {
        const float* As = smx + s * TG_STG;
        const float* Bs = As + TG_AS;
#pragma unroll
        for (int sub = 0; sub < 4; sub++) {
            int kk = sub * 8;
            uint32_t af[4][4], bf[4][2];
#pragma unroll
            for (int mi = 0; mi < 4; mi++) {
                int m0 = wm + mi * 16 + (lane >> 2);
                int kc = kk + (lane & 3);
                af[mi][0] = f2tf32(As[(m0)     * 36 + kc]);
                af[mi][1] = f2tf32(As[(m0 + 8) * 36 + kc]);
                af[mi][2] = f2tf32(As[(m0)     * 36 + kc + 4]);
                af[mi][3] = f2tf32(As[(m0 + 8) * 36 + kc + 4]);
            }
#pragma unroll
            for (int nj = 0; nj < 4; nj++) {
                int n0 = wn + nj * 8 + (lane >> 2);
                int kr = kk + (lane & 3);
                bf[nj][0] = f2tf32(Bs[(kr)     * 136 + n0]);
                bf[nj][1] = f2tf32(Bs[(kr + 4) * 136 + n0]);
            }
#pragma unroll
            for (int mi = 0; mi < 4; mi++)
#pragma unroll
                for (int nj = 0; nj < 4; nj++)
                    mma_tf32(acc[mi][nj], af[mi][0], af[mi][1], af[mi][2], af[mi][3],
                             bf[nj][0], bf[nj][1]);
        }
    };

    issue(0);
    issue(1);
    for (int kt = 0; kt < KT; kt++) {
        if (kt == KT - 1) asm volatile("cp.async.wait_group 0;");
        else              asm volatile("cp.async.wait_group 1;");
        __syncthreads();
        if (kt + 2 < KT) issue(kt + 2);
        compute(kt % 3);
    }

    // epilogue: c0,c1 at (row, col..col+1); c2,c3 at (row+8, col..col+1)
#pragma unroll
    for (int mi = 0; mi < 4; mi++) {
#pragma unroll
        for (int nj = 0; nj < 4; nj++) {
            int row = bm + wm + mi * 16 + (lane >> 2);
            int col = bn + wn + nj * 8 + (lane & 3) * 2;
#pragma unroll
            for (int half = 0; half < 2; half++) {
                int r = row + half * 8;
                float v0 = acc[mi][nj][half * 2 + 0] + bias[col];
                float v1 = acc[mi][nj][half * 2 + 1] + bias[col + 1];
                if (EPI == 1) { v0 = gelu_f(v0); v1 = gelu_f(v1); }
                if (EPI == 2) {
                    v0 += res[(size_t)r * Ndim + col];
                    v1 += res[(size_t)r * Ndim + col + 1];
                }
                float2 w = make_float2(v0, v1);
                *(float2*)&C[(size_t)r * Ndim + col] = w;
            }
        }
    }
}

// same kernel without bias (for r = P @ Wr)
__global__ void __launch_bounds__(256)
tgemm_nb(const float* __restrict__ A, const float* __restrict__ Bm,
         float* __restrict__ C, int Ndim, int Kdim) {
    extern __shared__ float smx[];
    const int tid = threadIdx.x, wid = tid >> 5, lane = tid & 31;
    const int bm = blockIdx.y * 128, bn = blockIdx.x * 128;
    const int wm = (wid >> 2) * 64, wn = (wid & 3) * 32;
    const int KT = Kdim / 32;

    float acc[4][4][4];
#pragma unroll
    for (int mi = 0; mi < 4; mi++)
#pragma unroll
        for (int nj = 0; nj < 4; nj++)
#pragma unroll
            for (int e = 0; e < 4; e++) acc[mi][nj][e] = 0.f;

    auto issue = [&](int kt) {
        int s = kt % 3;
        float* As = smx + s * TG_STG;
        float* Bs = As + TG_AS;
        int k0 = kt * 32;
#pragma unroll
        for (int p = 0; p < 4; p++) {
            int f4 = tid + p * 256;
            int r = f4 >> 3, c4 = (f4 & 7) << 2;
            cp16(&As[r * 36 + c4], &A[(size_t)(bm + r) * Kdim + k0 + c4]);
        }
#pragma unroll
        for (int p = 0; p < 4; p++) {
            int f4 = tid + p * 256;
            int r = f4 >> 5, c4 = (f4 & 31) << 2;
            cp16(&Bs[r * 136 + c4], &Bm[(size_t)(k0 + r) * Ndim + bn + c4]);
        }
        asm volatile("cp.async.commit_group;");
    };

    auto compute = [&](int s) {
        const float* As = smx + s * TG_STG;
        const float* Bs = As + TG_AS;
#pragma unroll
        for (int sub = 0; sub < 4; sub++) {
            int kk = sub * 8;
            uint32_t af[4][4], bf[4][2];
#pragma unroll
            for (int mi = 0; mi < 4; mi++) {
                int m0 = wm + mi * 16 + (lane >> 2);
                int kc = kk + (lane & 3);
                af[mi][0] = f2tf32(As[(m0)     * 36 + kc]);
                af[mi][1] = f2tf32(As[(m0 + 8) * 36 + kc]);
                af[mi][2] = f2tf32(As[(m0)     * 36 + kc + 4]);
                af[mi][3] = f2tf32(As[(m0 + 8) * 36 + kc + 4]);
            }
#pragma unroll
            for (int nj = 0; nj < 4; nj++) {
                int n0 = wn + nj * 8 + (lane >> 2);
                int kr = kk + (lane & 3);
                bf[nj][0] = f2tf32(Bs[(kr)     * 136 + n0]);
                bf[nj][1] = f2tf32(Bs[(kr + 4) * 136 + n0]);
            }
#pragma unroll
            for (int mi = 0; mi < 4; mi++)
#pragma unroll
                for (int nj = 0; nj < 4; nj++)
                    mma_tf32(acc[mi][nj], af[mi][0], af[mi][1], af[mi][2], af[mi][3],
                             bf[nj][0], bf[nj][1]);
        }
    };

    issue(0);
    issue(1);
    for (int kt = 0; kt < KT; kt++) {
        if (kt == KT - 1) asm volatile("cp.async.wait_group 0;");
        else              asm volatile("cp.async.wait_group 1;");
        __syncthreads();
        if (kt + 2 < KT) issue(kt + 2);
        compute(kt % 3);
    }

#pragma unroll
    for (int mi = 0; mi < 4; mi++) {
#pragma unroll
        for (int nj = 0; nj < 4; nj++) {
            int row = bm + wm + mi * 16 + (lane >> 2);
            int col = bn + wn + nj * 8 + (lane & 3) * 2;
#pragma unroll
            for (int half = 0; half < 2; half++) {
                int r = row + half * 8;
                float2 w = make_float2(acc[mi][nj][half * 2 + 0], acc[mi][nj][half * 2 + 1]);
                *(float2*)&C[(size_t)r * Ndim + col] = w;
            }
        }
    }
}

// ---------------- flash attention with Transformer-XL relative term ----------------
__global__ void __launch_bounds__(256)
flash_xl(const float* __restrict__ qg, const float* __restrict__ kg,
         const float* __restrict__ vg, const float* __restrict__ rg,
         const float* __restrict__ ug, const float* __restrict__ vpg,
         const int* __restrict__ iscp, float* __restrict__ outg) {
    extern __shared__ float sm[];
    float* Qs  = sm;                  // [64][65]
    float* Us  = Qs  + 64 * 65;       // [64]
    float* Vps = Us  + 64;            // [64]
    float* Kst = Vps + 64;            // [64 d][65] (transposed, padded)
    float* Rs  = Kst + 64 * 65;       // [128 m][65]
    float* Vs  = Rs  + 128 * 65;      // [64 j][64 d]
    float* Ps  = Vs  + 64 * 64;       // [64 r][65]

    const int tid = threadIdx.x;
    const int tx = tid & 7, ty = tid >> 3;
    const int i0 = blockIdx.x * 64, h = blockIdx.y, b = blockIdx.z;
    const int r0l = ty * 2, r1l = r0l + 1;
    const int causal = iscp[0];

    {
        const float* qbase = qg + ((size_t)(b * Tt + i0)) * D_MODEL + h * D_HEADc;
#pragma unroll
        for (int p = 0; p < 4; p++) {
            int idx = tid + p * 256;
            int rl = idx >> 4; int ca = (idx & 15) << 2;
            float4 v4 = *(const float4*)&qbase[(size_t)rl * D_MODEL + ca];
            Qs[rl * 65 + ca]     = v4.x; Qs[rl * 65 + ca + 1] = v4.y;
            Qs[rl * 65 + ca + 2] = v4.z; Qs[rl * 65 + ca + 3] = v4.w;
        }
        if (tid < 64) { Us[tid] = ug[h * D_HEADc + tid]; Vps[tid] = vpg[h * D_HEADc + tid]; }
    }

    float mi0 = -1e30f, mi1 = -1e30f, li0 = 0.f, li1 = 0.f;
    float o0[8], o1[8];
#pragma unroll
    for (int d = 0; d < 8; d++) { o0[d] = 0.f; o1[d] = 0.f; }

    const int njt = (Mm + i0) / 64 + 1;
    const int mbase0 = Tt - 64 - i0;

    for (int jt = 0; jt < njt; jt++) {
        const int j0 = jt * 64;
        __syncthreads();

        {
            const float* kbase = kg + ((size_t)(b * KK + j0)) * D_MODEL + h * D_HEADc;
            const float* vbase = vg + ((size_t)(b * KK + j0)) * D_MODEL + h * D_HEADc;
#pragma unroll
            for (int p = 0; p < 4; p++) {
                int idx = tid + p * 256;
                int j = idx >> 4; int ca = (idx & 15) << 2;
                float4 kv = *(const float4*)&kbase[(size_t)j * D_MODEL + ca];
                Kst[(ca + 0) * 65 + j] = kv.x; Kst[(ca + 1) * 65 + j] = kv.y;
                Kst[(ca + 2) * 65 + j] = kv.z; Kst[(ca + 3) * 65 + j] = kv.w;
                *(float4*)&Vs[j * 64 + ca] = *(const float4*)&vbase[(size_t)j * D_MODEL + ca];
            }
            const int mb = mbase0 + j0;
#pragma unroll
            for (int p = 0; p < 8; p++) {
                int idx = tid + p * 256;
                int mmz = idx >> 4; int ca = (idx & 15) << 2;
                int mg = mb + mmz; if (mg > KK - 1) mg = KK - 1;
                float4 rv = *(const float4*)&rg[(size_t)mg * D_MODEL + h * D_HEADc + ca];
                Rs[mmz * 65 + ca]     = rv.x; Rs[mmz * 65 + ca + 1] = rv.y;
                Rs[mmz * 65 + ca + 2] = rv.z; Rs[mmz * 65 + ca + 3] = rv.w;
            }
        }
        __syncthreads();

        float s0[8], s1[8];
#pragma unroll
        for (int jj = 0; jj < 8; jj++) { s0[jj] = 0.f; s1[jj] = 0.f; }
#pragma unroll 4
        for (int d = 0; d < 64; d++) {
            float q0 = Qs[r0l * 65 + d], q1 = Qs[r1l * 65 + d];
            float ud = Us[d], vd = Vps[d];
            float qu0 = q0 + ud, qu1 = q1 + ud;
            float qv0 = q0 + vd, qv1 = q1 + vd;
#pragma unroll
            for (int jj = 0; jj < 8; jj++) {
                int j = tx * 8 + jj;
                float kv = Kst[d * 65 + j];
                s0[jj] += qu0 * kv;
                s1[jj] += qu1 * kv;
                float rv0 = Rs[(j + 63 - r0l) * 65 + d];
                float rv1 = Rs[(j + 63 - r1l) * 65 + d];
                s0[jj] += qv0 * rv0;
                s1[jj] += qv1 * rv1;
            }
        }

        const float scale = 0.125f;
        const int ig0 = i0 + r0l, ig1 = i0 + r1l;
        float rm0 = -1e30f, rm1 = -1e30f;
#pragma unroll
        for (int jj = 0; jj < 8; jj++) {
            int jgl = j0 + tx * 8 + jj;
            float v0 = s0[jj] * scale, v1 = s1[jj] * scale;
            if (causal && jgl > ig0 + Mm) v0 = -1e30f;
            if (causal && jgl > ig1 + Mm) v1 = -1e30f;
            s0[jj] = v0; s1[jj] = v1;
            rm0 = fmaxf(rm0, v0); rm1 = fmaxf(rm1, v1);
        }
#pragma unroll
        for (int off = 1; off < 8; off <<= 1) {
            rm0 = fmaxf(rm0, __shfl_xor_sync(0xffffffffu, rm0, off));
            rm1 = fmaxf(rm1, __shfl_xor_sync(0xffffffffu, rm1, off));
        }
        float mn0 = fmaxf(mi0, rm0), mn1 = fmaxf(mi1, rm1);
        float corr0 = (mi0 < -0.9e30f) ? 0.f : __expf(mi0 - mn0);
        float corr1 = (mi1 < -0.9e30f) ? 0.f : __expf(mi1 - mn1);
        float sum0 = 0.f, sum1 = 0.f;
#pragma unroll
        for (int jj = 0; jj < 8; jj++) {
            float p0 = (s0[jj] < -0.9e30f) ? 0.f : __expf(s0[jj] - mn0);
            float p1 = (s1[jj] < -0.9e30f) ? 0.f : __expf(s1[jj] - mn1);
            s0[jj] = p0; s1[jj] = p1;
            sum0 += p0; sum1 += p1;
        }
#pragma unroll
        for (int off = 1; off < 8; off <<= 1) {
            sum0 += __shfl_xor_sync(0xffffffffu, sum0, off);
            sum1 += __shfl_xor_sync(0xffffffffu, sum1, off);
        }
        li0 = li0 * corr0 + sum0; li1 = li1 * corr1 + sum1;
        mi0 = mn0; mi1 = mn1;
#pragma unroll
        for (int dd = 0; dd < 8; dd++) { o0[dd] *= corr0; o1[dd] *= corr1; }

#pragma unroll
        for (int jj = 0; jj < 8; jj++) {
            Ps[r0l * 65 + tx * 8 + jj] = s0[jj];
            Ps[r1l * 65 + tx * 8 + jj] = s1[jj];
        }
        __syncthreads();
#pragma unroll 4
        for (int j = 0; j < 64; j++) {
            float p0 = Ps[r0l * 65 + j], p1 = Ps[r1l * 65 + j];
            float4 va = *(const float4*)&Vs[j * 64 + tx * 8];
            float4 vb = *(const float4*)&Vs[j * 64 + tx * 8 + 4];
            o0[0] += p0 * va.x; o0[1] += p0 * va.y; o0[2] += p0 * va.z; o0[3] += p0 * va.w;
            o0[4] += p0 * vb.x; o0[5] += p0 * vb.y; o0[6] += p0 * vb.z; o0[7] += p0 * vb.w;
            o1[0] += p1 * va.x; o1[1] += p1 * va.y; o1[2] += p1 * va.z; o1[3] += p1 * va.w;
            o1[4] += p1 * vb.x; o1[5] += p1 * vb.y; o1[6] += p1 * vb.z; o1[7] += p1 * vb.w;
        }
    }

    float inv0 = 1.f / li0, inv1 = 1.f / li1;
    float* ob0 = outg + ((size_t)(b * Tt + i0 + r0l)) * D_MODEL + h * D_HEADc + tx * 8;
    float* ob1 = outg + ((size_t)(b * Tt + i0 + r1l)) * D_MODEL + h * D_HEADc + tx * 8;
    float4 w;
    w = make_float4(o0[0]*inv0, o0[1]*inv0, o0[2]*inv0, o0[3]*inv0); *(float4*)ob0 = w;
    w = make_float4(o0[4]*inv0, o0[5]*inv0, o0[6]*inv0, o0[7]*inv0); *(float4*)(ob0+4) = w;
    w = make_float4(o1[0]*inv1, o1[1]*inv1, o1[2]*inv1, o1[3]*inv1); *(float4*)ob1 = w;
    w = make_float4(o1[4]*inv1, o1[5]*inv1, o1[6]*inv1, o1[7]*inv1); *(float4*)(ob1+4) = w;
}

// ---------------- LayerNorm over last dim (D=1024), one block per row ----------------
__global__ void __launch_bounds__(256)
layernorm_k(const float* __restrict__ in, const float* __restrict__ g,
            const float* __restrict__ be, float* __restrict__ out) {
    __shared__ float red[34];
    const int row = blockIdx.x;
    const int tid = threadIdx.x;
    float4 v = ((const float4*)(in + (size_t)row * D_MODEL))[tid];

    float s = v.x + v.y + v.z + v.w;
    int lane = tid & 31, wid = tid >> 5;
#pragma unroll
    for (int off = 16; off >= 1; off >>= 1) s += __shfl_xor_sync(0xffffffffu, s, off);
    if (lane == 0) red[wid] = s;
    __syncthreads();
    if (tid == 0) {
        float t = 0.f;
#pragma unroll
        for (int w2 = 0; w2 < 8; w2++) t += red[w2];
        red[32] = t;
    }
    __syncthreads();
    float mu = red[32] * (1.f / (float)D_MODEL);

    float dx0 = v.x - mu, dx1 = v.y - mu, dx2 = v.z - mu, dx3 = v.w - mu;
    float sq = dx0 * dx0 + dx1 * dx1 + dx2 * dx2 + dx3 * dx3;
#pragma unroll
    for (int off = 16; off >= 1; off >>= 1) sq += __shfl_xor_sync(0xffffffffu, sq, off);
    if (lane == 0) red[wid] = sq;
    __syncthreads();
    if (tid == 0) {
        float t = 0.f;
#pragma unroll
        for (int w2 = 0; w2 < 8; w2++) t += red[w2];
        red[33] = t;
    }
    __syncthreads();
    float rstd = rsqrtf(red[33] * (1.f / (float)D_MODEL) + 1e-5f);

    float4 gv = ((const float4*)g)[tid];
    float4 bv = ((const float4*)be)[tid];
    float4 o;
    o.x = dx0 * rstd * gv.x + bv.x;
    o.y = dx1 * rstd * gv.y + bv.y;
    o.z = dx2 * rstd * gv.z + bv.z;
    o.w = dx3 * rstd * gv.w + bv.w;
    ((float4*)(out + (size_t)row * D_MODEL))[tid] = o;
}

// ---------------- launch ----------------
extern "C" void kernel_launch(void* const* d_in, const int* in_sizes, int n_in,
                              void* d_out, int out_size) {
    const float* x    = (const float*)d_in[0];
    const float* mem  = (const float*)d_in[1];
    const float* Wq   = (const float*)d_in[2];
    const float* bq   = (const float*)d_in[3];
    const float* Wk   = (const float*)d_in[4];
    const float* bk   = (const float*)d_in[5];
    const float* Wv   = (const float*)d_in[6];
    const float* bv   = (const float*)d_in[7];
    const float* Wo   = (const float*)d_in[8];
    const float* bo   = (const float*)d_in[9];
    const float* Wr   = (const float*)d_in[10];
    const float* u    = (const float*)d_in[11];
    const float* vpar = (const float*)d_in[12];
    const float* g1   = (const float*)d_in[13];
    const float* be1  = (const float*)d_in[14];
    const float* g2   = (const float*)d_in[15];
    const float* be2  = (const float*)d_in[16];
    const float* W1   = (const float*)d_in[17];
    const float* b1   = (const float*)d_in[18];
    const float* W2   = (const float*)d_in[19];
    const float* b2   = (const float*)d_in[20];
    const int*   isc  = (const int*)d_in[21];
    float* out = (float*)d_out;

    float *P, *r, *q, *c, *k, *vv, *attn, *s, *h, *f1, *invf;
    cudaGetSymbolAddress((void**)&P,    g_P);
    cudaGetSymbolAddress((void**)&r,    g_r);
    cudaGetSymbolAddress((void**)&q,    g_q);
    cudaGetSymbolAddress((void**)&c,    g_c);
    cudaGetSymbolAddress((void**)&k,    g_k);
    cudaGetSymbolAddress((void**)&vv,   g_v);
    cudaGetSymbolAddress((void**)&attn, g_attn);
    cudaGetSymbolAddress((void**)&s,    g_s);
    cudaGetSymbolAddress((void**)&h,    g_h);
    cudaGetSymbolAddress((void**)&f1,   g_f1);
    cudaGetSymbolAddress((void**)&invf, g_invf);

    cudaFuncSetAttribute(tgemm<0>, cudaFuncAttributeMaxDynamicSharedMemorySize, TG_SMEM);
    cudaFuncSetAttribute(tgemm<1>, cudaFuncAttributeMaxDynamicSharedMemorySize, TG_SMEM);
    cudaFuncSetAttribute(tgemm<2>, cudaFuncAttributeMaxDynamicSharedMemorySize, TG_SMEM);
    cudaFuncSetAttribute(tgemm_nb, cudaFuncAttributeMaxDynamicSharedMemorySize, TG_SMEM);

    fill_invf<<<1, 512>>>(invf);
    fill_pos<<<(KK * D_MODEL + 255) / 256, 256>>>(P, invf);
    concat_kernel<<<(ROWS_C * (D_MODEL / 4) + 255) / 256, 256>>>(x, mem, c);

    // projections (tf32 tensor cores)
    tgemm<0><<<dim3(D_MODEL / 128, ROWS_X / 128), 256, TG_SMEM>>>(x, Wq, bq, nullptr, q, D_MODEL, D_MODEL);
    tgemm<0><<<dim3(D_MODEL / 128, ROWS_C / 128), 256, TG_SMEM>>>(c, Wk, bk, nullptr, k, D_MODEL, D_MODEL);
    tgemm<0><<<dim3(D_MODEL / 128, ROWS_C / 128), 256, TG_SMEM>>>(c, Wv, bv, nullptr, vv, D_MODEL, D_MODEL);
    tgemm_nb<<<dim3(D_MODEL / 128, KK / 128), 256, TG_SMEM>>>(P, Wr, r, D_MODEL, D_MODEL);

    // attention
    size_t smemB = (size_t)(64 * 65 + 64 + 64 + 64 * 65 + 128 * 65 + 64 * 64 + 64 * 65) * 4;
    cudaFuncSetAttribute(flash_xl, cudaFuncAttributeMaxDynamicSharedMemorySize, (int)smemB);
    flash_xl<<<dim3(Tt / 64, N_HEADc, Bb), 256, smemB>>>(q, k, vv, r, u, vpar, isc, attn);

    // o-proj + residual, LN1
    tgemm<2><<<dim3(D_MODEL / 128, ROWS_X / 128), 256, TG_SMEM>>>(attn, Wo, bo, x, s, D_MODEL, D_MODEL);
    layernorm_k<<<ROWS_X, 256>>>(s, g1, be1, h);

    // FFN
    tgemm<1><<<dim3(FFN_H / 128, ROWS_X / 128), 256, TG_SMEM>>>(h, W1, b1, nullptr, f1, FFN_H, D_MODEL);
    tgemm<2><<<dim3(D_MODEL / 128, ROWS_X / 128), 256, TG_SMEM>>>(f1, W2, b2, h, s, D_MODEL, FFN_H);
    layernorm_k<<<ROWS_X, 256>>>(s, g2, be2, out);
}

// round 5
// speedup vs baseline: 3.4498x; 2.6235x over previous
#include <cuda_runtime.h>
#include <math.h>
#include <stdint.h>

// ---------------- problem constants ----------------
#define D_MODEL 1024
#define N_HEADc 16
#define D_HEADc 64
#define FFN_H   4096
#define Bb      4
#define Tt      2048
#define Mm      2048
#define KK      4096            // M + T
#define ROWS_X  (Bb*Tt)         // 8192
#define ROWS_C  (Bb*KK)         // 16384

// ---------------- scratch (static device memory; no runtime alloc) ----------------
static __device__ float g_P   [(size_t)KK*D_MODEL];
static __device__ float g_r   [(size_t)KK*D_MODEL];
static __device__ float g_q   [(size_t)ROWS_X*D_MODEL];
static __device__ float g_c   [(size_t)ROWS_C*D_MODEL];
static __device__ float g_k   [(size_t)ROWS_C*D_MODEL];
static __device__ float g_v   [(size_t)ROWS_C*D_MODEL];
static __device__ float g_attn[(size_t)ROWS_X*D_MODEL];
static __device__ float g_s   [(size_t)ROWS_X*D_MODEL];
static __device__ float g_h   [(size_t)ROWS_X*D_MODEL];
static __device__ float g_f1  [(size_t)ROWS_X*FFN_H];
static __device__ float g_invf[512];

// ---------------- helpers ----------------
__device__ __forceinline__ float gelu_f(float x) {
    float x3 = x * x * x;
    float t  = tanhf(0.7978845608028654f * (x + 0.044715f * x3));
    return 0.5f * x * (1.0f + t);
}

__device__ __forceinline__ uint32_t f2tf32(float x) {
    uint32_t r;
    asm("cvt.rna.tf32.f32 %0, %1;" : "=r"(r) : "f"(x));
    return r;
}

__device__ __forceinline__ void mma_tf32(float c[4], uint32_t a0, uint32_t a1,
                                         uint32_t a2, uint32_t a3,
                                         uint32_t b0, uint32_t b1) {
    asm volatile(
        "mma.sync.aligned.m16n8k8.row.col.f32.tf32.tf32.f32 "
        "{%0,%1,%2,%3},{%4,%5,%6,%7},{%8,%9},{%0,%1,%2,%3};"
        : "+f"(c[0]), "+f"(c[1]), "+f"(c[2]), "+f"(c[3])
        : "r"(a0), "r"(a1), "r"(a2), "r"(a3), "r"(b0), "r"(b1));
}

__device__ __forceinline__ void cp16(void* smem, const void* g) {
    uint32_t s = (uint32_t)__cvta_generic_to_shared(smem);
    asm volatile("cp.async.cg.shared.global [%0], [%1], 16;" :: "r"(s), "l"(g));
}

// ---------------- positional tables ----------------
__global__ void fill_invf(float* __restrict__ invf) {
    int f = threadIdx.x;
    if (f < 512) {
        double v = exp(-((double)(2 * f) / (double)D_MODEL) * log(10000.0));
        invf[f] = (float)v;
    }
}

__global__ void fill_pos(float* __restrict__ P, const float* __restrict__ invf) {
    int idx = blockIdx.x * blockDim.x + threadIdx.x;
    if (idx >= KK * D_MODEL) return;
    int m   = idx / D_MODEL;
    int col = idx - m * D_MODEL;
    float pos = (float)(KK - 1 - m);
    int f = (col < D_MODEL / 2) ? col : col - D_MODEL / 2;
    float ang = pos * __ldg(&invf[f]);
    P[idx] = (col < D_MODEL / 2) ? sinf(ang) : cosf(ang);
}

// ---------------- concat c = [mem, x] along seq ----------------
__global__ void concat_kernel(const float* __restrict__ x, const float* __restrict__ mem,
                              float* __restrict__ c) {
    int idx = blockIdx.x * blockDim.x + threadIdx.x;     // float4 units
    const int row_f4 = D_MODEL / 4;                      // 256
    if (idx >= ROWS_C * row_f4) return;
    int row = idx / row_f4;
    int col = idx - row * row_f4;
    int b = row / KK;
    int t = row - b * KK;
    const float4* src;
    if (t < Mm) src = (const float4*)mem + ((size_t)(b * Mm + t)) * row_f4 + col;
    else        src = (const float4*)x   + ((size_t)(b * Tt + (t - Mm))) * row_f4 + col;
    ((float4*)c)[idx] = *src;
}

// ---------------- tf32 tensor-core GEMM: 128x128 tile, 32-deep K stages ----------------
#define TG_AS (128*36)
#define TG_BS (32*136)
#define TG_STG (TG_AS + TG_BS)
#define TG_SMEM (3 * TG_STG * 4)

template <int EPI>
__global__ void __launch_bounds__(256)
tgemm(const float* __restrict__ A, const float* __restrict__ Bm,
      const float* __restrict__ bias, const float* __restrict__ res,
      float* __restrict__ C, int Ndim, int Kdim) {
    extern __shared__ float smx[];
    const int tid = threadIdx.x, wid = tid >> 5, lane = tid & 31;
    const int bm = blockIdx.y * 128, bn = blockIdx.x * 128;
    const int wm = (wid >> 2) * 64, wn = (wid & 3) * 32;
    const int KT = Kdim / 32;

    float acc[4][4][4];
#pragma unroll
    for (int mi = 0; mi < 4; mi++)
#pragma unroll
        for (int nj = 0; nj < 4; nj++)
#pragma unroll
            for (int e = 0; e < 4; e++) acc[mi][nj][e] = 0.f;

    auto issue = [&](int kt) {
        int s = kt % 3;
        float* As = smx + s * TG_STG;
        float* Bs = As + TG_AS;
        int k0 = kt * 32;
#pragma unroll
        for (int p = 0; p < 4; p++) {
            int f4 = tid + p * 256;
            int r = f4 >> 3, c4 = (f4 & 7) << 2;
            cp16(&As[r * 36 + c4], &A[(size_t)(bm + r) * Kdim + k0 + c4]);
        }
#pragma unroll
        for (int p = 0; p < 4; p++) {
            int f4 = tid + p * 256;
            int r = f4 >> 5, c4 = (f4 & 31) << 2;
            cp16(&Bs[r * 136 + c4], &Bm[(size_t)(k0 + r) * Ndim + bn + c4]);
        }
        asm volatile("cp.async.commit_group;");
    };

    auto compute = [&](int s) {
        const float* As = smx + s * TG_STG;
        const float* Bs = As + TG_AS;
#pragma unroll
        for (int sub = 0; sub < 4; sub++) {
            int kk = sub * 8;
            uint32_t af[4][4], bf[4][2];
#pragma unroll
            for (int mi = 0; mi < 4; mi++) {
                int m0 = wm + mi * 16 + (lane >> 2);
                int kc = kk + (lane & 3);
                af[mi][0] = f2tf32(As[(m0)     * 36 + kc]);
                af[mi][1] = f2tf32(As[(m0 + 8) * 36 + kc]);
                af[mi][2] = f2tf32(As[(m0)     * 36 + kc + 4]);
                af[mi][3] = f2tf32(As[(m0 + 8) * 36 + kc + 4]);
            }
#pragma unroll
            for (int nj = 0; nj < 4; nj++) {
                int n0 = wn + nj * 8 + (lane >> 2);
                int kr = kk + (lane & 3);
                bf[nj][0] = f2tf32(Bs[(kr)     * 136 + n0]);
                bf[nj][1] = f2tf32(Bs[(kr + 4) * 136 + n0]);
            }
#pragma unroll
            for (int mi = 0; mi < 4; mi++)
#pragma unroll
                for (int nj = 0; nj < 4; nj++)
                    mma_tf32(acc[mi][nj], af[mi][0], af[mi][1], af[mi][2], af[mi][3],
                             bf[nj][0], bf[nj][1]);
        }
    };

    issue(0);
    issue(1);
    for (int kt = 0; kt < KT; kt++) {
        if (kt == KT - 1) asm volatile("cp.async.wait_group 0;");
        else              asm volatile("cp.async.wait_group 1;");
        __syncthreads();
        if (kt + 2 < KT) issue(kt + 2);
        compute(kt % 3);
    }

#pragma unroll
    for (int mi = 0; mi < 4; mi++) {
#pragma unroll
        for (int nj = 0; nj < 4; nj++) {
            int row = bm + wm + mi * 16 + (lane >> 2);
            int col = bn + wn + nj * 8 + (lane & 3) * 2;
#pragma unroll
            for (int half = 0; half < 2; half++) {
                int r = row + half * 8;
                float v0 = acc[mi][nj][half * 2 + 0] + bias[col];
                float v1 = acc[mi][nj][half * 2 + 1] + bias[col + 1];
                if (EPI == 1) { v0 = gelu_f(v0); v1 = gelu_f(v1); }
                if (EPI == 2) {
                    v0 += res[(size_t)r * Ndim + col];
                    v1 += res[(size_t)r * Ndim + col + 1];
                }
                float2 w = make_float2(v0, v1);
                *(float2*)&C[(size_t)r * Ndim + col] = w;
            }
        }
    }
}

__global__ void __launch_bounds__(256)
tgemm_nb(const float* __restrict__ A, const float* __restrict__ Bm,
         float* __restrict__ C, int Ndim, int Kdim) {
    extern __shared__ float smx[];
    const int tid = threadIdx.x, wid = tid >> 5, lane = tid & 31;
    const int bm = blockIdx.y * 128, bn = blockIdx.x * 128;
    const int wm = (wid >> 2) * 64, wn = (wid & 3) * 32;
    const int KT = Kdim / 32;

    float acc[4][4][4];
#pragma unroll
    for (int mi = 0; mi < 4; mi++)
#pragma unroll
        for (int nj = 0; nj < 4; nj++)
#pragma unroll
            for (int e = 0; e < 4; e++) acc[mi][nj][e] = 0.f;

    auto issue = [&](int kt) {
        int s = kt % 3;
        float* As = smx + s * TG_STG;
        float* Bs = As + TG_AS;
        int k0 = kt * 32;
#pragma unroll
        for (int p = 0; p < 4; p++) {
            int f4 = tid + p * 256;
            int r = f4 >> 3, c4 = (f4 & 7) << 2;
            cp16(&As[r * 36 + c4], &A[(size_t)(bm + r) * Kdim + k0 + c4]);
        }
#pragma unroll
        for (int p = 0; p < 4; p++) {
            int f4 = tid + p * 256;
            int r = f4 >> 5, c4 = (f4 & 31) << 2;
            cp16(&Bs[r * 136 + c4], &Bm[(size_t)(k0 + r) * Ndim + bn + c4]);
        }
        asm volatile("cp.async.commit_group;");
    };

    auto compute = [&](int s) {
        const float* As = smx + s * TG_STG;
        const float* Bs = As + TG_AS;
#pragma unroll
        for (int sub = 0; sub < 4; sub++) {
            int kk = sub * 8;
            uint32_t af[4][4], bf[4][2];
#pragma unroll
            for (int mi = 0; mi < 4; mi++) {
                int m0 = wm + mi * 16 + (lane >> 2);
                int kc = kk + (lane & 3);
                af[mi][0] = f2tf32(As[(m0)     * 36 + kc]);
                af[mi][1] = f2tf32(As[(m0 + 8) * 36 + kc]);
                af[mi][2] = f2tf32(As[(m0)     * 36 + kc + 4]);
                af[mi][3] = f2tf32(As[(m0 + 8) * 36 + kc + 4]);
            }
#pragma unroll
            for (int nj = 0; nj < 4; nj++) {
                int n0 = wn + nj * 8 + (lane >> 2);
                int kr = kk + (lane & 3);
                bf[nj][0] = f2tf32(Bs[(kr)     * 136 + n0]);
                bf[nj][1] = f2tf32(Bs[(kr + 4) * 136 + n0]);
            }
#pragma unroll
            for (int mi = 0; mi < 4; mi++)
#pragma unroll
                for (int nj = 0; nj < 4; nj++)
                    mma_tf32(acc[mi][nj], af[mi][0], af[mi][1], af[mi][2], af[mi][3],
                             bf[nj][0], bf[nj][1]);
        }
    };

    issue(0);
    issue(1);
    for (int kt = 0; kt < KT; kt++) {
        if (kt == KT - 1) asm volatile("cp.async.wait_group 0;");
        else              asm volatile("cp.async.wait_group 1;");
        __syncthreads();
        if (kt + 2 < KT) issue(kt + 2);
        compute(kt % 3);
    }

#pragma unroll
    for (int mi = 0; mi < 4; mi++) {
#pragma unroll
        for (int nj = 0; nj < 4; nj++) {
            int row = bm + wm + mi * 16 + (lane >> 2);
            int col = bn + wn + nj * 8 + (lane & 3) * 2;
#pragma unroll
            for (int half = 0; half < 2; half++) {
                int r = row + half * 8;
                float2 w = make_float2(acc[mi][nj][half * 2 + 0], acc[mi][nj][half * 2 + 1]);
                *(float2*)&C[(size_t)r * Ndim + col] = w;
            }
        }
    }
}

// ---------------- tensor-core flash attention with XL relative term ----------------
// Block: 128 q-rows x 64-key tiles; 8 warps, warp w owns rows [16w,16w+16).
// BD[i,j] = (q_i+v) . R[Tt-1-i+jg]  (valid where jg <= i+M, i.e. all unmasked entries).
// G[i,m] = (q_i+v) . R[wb+m] computed by mma into a 3-slot x 64-col smem ring;
// BD gathered as G[i, jl+127-i_local]. G/P/O are warp-row-private => only K/V/R
// tile loads need block syncs.
// Smem (floats): Kt[64][72] Rt[64][72] Vs[64][72] Gs[128][200] Ps[128][72]
#define FA_KT 0
#define FA_RT (FA_KT + 64*72)
#define FA_VS (FA_RT + 64*72)
#define FA_GS (FA_VS + 64*72)
#define FA_PS (FA_GS + 128*200)
#define FA_SMEM ((FA_PS + 128*72) * 4)

__global__ void __launch_bounds__(256, 1)
flash_xl_tc(const float* __restrict__ qg, const float* __restrict__ kg,
            const float* __restrict__ vg, const float* __restrict__ rg,
            const float* __restrict__ ug, const float* __restrict__ vpg,
            const int* __restrict__ iscp, float* __restrict__ outg) {
    extern __shared__ float sm[];
    float* Kt  = sm + FA_KT;
    float* Rt  = sm + FA_RT;
    float* Vsm = sm + FA_VS;
    float* Gs  = sm + FA_GS;
    float* Ps  = sm + FA_PS;

    const int tid = threadIdx.x, lane = tid & 31, w = tid >> 5;
    const int i0 = blockIdx.x * 128, h = blockIdx.y, b = blockIdx.z;
    const int causal = iscp[0];
    const int mrow = w * 16;
    const int r0 = mrow + (lane >> 2);        // this thread's row pair: r0, r0+8
    const int kc = lane & 3;
    const int base0 = Tt - 128 - i0;          // R window base at j0=0

    // ---- load Q [128][64] into Ps, build A-fragments for Q+u and Q+v ----
    {
        const float* qbase = qg + ((size_t)(b * Tt + i0)) * D_MODEL + h * D_HEADc;
#pragma unroll
        for (int p = 0; p < 8; p++) {
            int idx = tid + p * 256;
            int rl = idx >> 4, c4 = (idx & 15) << 2;
            *(float4*)&Ps[rl * 72 + c4] = *(const float4*)&qbase[(size_t)rl * D_MODEL + c4];
        }
    }
    __syncthreads();

    uint32_t aQu[8][4], aQv[8][4];
#pragma unroll
    for (int kk = 0; kk < 8; kk++) {
        int d0 = kk * 8 + kc, d1 = d0 + 4;
        float u0 = __ldg(&ug[h * D_HEADc + d0]),  u1 = __ldg(&ug[h * D_HEADc + d1]);
        float v0 = __ldg(&vpg[h * D_HEADc + d0]), v1 = __ldg(&vpg[h * D_HEADc + d1]);
        float q00 = Ps[r0 * 72 + d0],       q10 = Ps[(r0 + 8) * 72 + d0];
        float q01 = Ps[r0 * 72 + d1],       q11 = Ps[(r0 + 8) * 72 + d1];
        aQu[kk][0] = f2tf32(q00 + u0); aQu[kk][1] = f2tf32(q10 + u0);
        aQu[kk][2] = f2tf32(q01 + u1); aQu[kk][3] = f2tf32(q11 + u1);
        aQv[kk][0] = f2tf32(q00 + v0); aQv[kk][1] = f2tf32(q10 + v0);
        aQv[kk][2] = f2tf32(q01 + v1); aQv[kk][3] = f2tf32(q11 + v1);
    }
    __syncthreads();   // Ps free for P staging

    // ---- prefill G ring slots 0,1 (window halves [base0, base0+128)) ----
#pragma unroll
    for (int hh = 0; hh < 2; hh++) {
        int rb = base0 + hh * 64;
#pragma unroll
        for (int p = 0; p < 4; p++) {
            int idx = tid + p * 256;
            int mmv = idx >> 4, c4 = (idx & 15) << 2;
            int rrow = rb + mmv; if (rrow > KK - 1) rrow = KK - 1; if (rrow < 0) rrow = 0;
            float4 rv = *(const float4*)&rg[(size_t)rrow * D_MODEL + h * D_HEADc + c4];
            Rt[(c4 + 0) * 72 + mmv] = rv.x; Rt[(c4 + 1) * 72 + mmv] = rv.y;
            Rt[(c4 + 2) * 72 + mmv] = rv.z; Rt[(c4 + 3) * 72 + mmv] = rv.w;
        }
        __syncthreads();
#pragma unroll
        for (int nf = 0; nf < 8; nf++) {
            float gc[4] = {0.f, 0.f, 0.f, 0.f};
            int n0 = nf * 8 + (lane >> 2);
#pragma unroll
            for (int kk = 0; kk < 8; kk++) {
                int kr = kk * 8 + kc;
                uint32_t b0 = f2tf32(Rt[kr * 72 + n0]);
                uint32_t b1 = f2tf32(Rt[(kr + 4) * 72 + n0]);
                mma_tf32(gc, aQv[kk][0], aQv[kk][1], aQv[kk][2], aQv[kk][3], b0, b1);
            }
            int col = hh * 64 + nf * 8 + kc * 2;
            Gs[r0 * 200 + col] = gc[0];       Gs[r0 * 200 + col + 1] = gc[1];
            Gs[(r0 + 8) * 200 + col] = gc[2]; Gs[(r0 + 8) * 200 + col + 1] = gc[3];
        }
        __syncthreads();
    }

    // ---- main loop over key tiles ----
    float mi0 = -1e30f, mi1 = -1e30f, li0 = 0.f, li1 = 0.f;
    float oc[8][4];
#pragma unroll
    for (int nf = 0; nf < 8; nf++)
#pragma unroll
        for (int e = 0; e < 4; e++) oc[nf][e] = 0.f;

    const int njt = causal ? (i0 / 64 + 34) : (KK / 64);
    const float scale = 0.125f;

    for (int jt = 0; jt < njt; jt++) {
        const int j0 = jt * 64;
        __syncthreads();   // prior-iter readers of Kt/Rt/Vs done

        {   // K (transposed), V, and new R half (window rows base0+j0+128 ..)
            const float* kb = kg + ((size_t)(b * KK + j0)) * D_MODEL + h * D_HEADc;
            const float* vb = vg + ((size_t)(b * KK + j0)) * D_MODEL + h * D_HEADc;
#pragma unroll
            for (int p = 0; p < 4; p++) {
                int idx = tid + p * 256;
                int j = idx >> 4, c4 = (idx & 15) << 2;
                float4 kv = *(const float4*)&kb[(size_t)j * D_MODEL + c4];
                Kt[(c4 + 0) * 72 + j] = kv.x; Kt[(c4 + 1) * 72 + j] = kv.y;
                Kt[(c4 + 2) * 72 + j] = kv.z; Kt[(c4 + 3) * 72 + j] = kv.w;
                *(float4*)&Vsm[j * 72 + c4] = *(const float4*)&vb[(size_t)j * D_MODEL + c4];
            }
            int rb = base0 + j0 + 128;
#pragma unroll
            for (int p = 0; p < 4; p++) {
                int idx = tid + p * 256;
                int mmv = idx >> 4, c4 = (idx & 15) << 2;
                int rrow = rb + mmv; if (rrow > KK - 1) rrow = KK - 1;
                float4 rv = *(const float4*)&rg[(size_t)rrow * D_MODEL + h * D_HEADc + c4];
                Rt[(c4 + 0) * 72 + mmv] = rv.x; Rt[(c4 + 1) * 72 + mmv] = rv.y;
                Rt[(c4 + 2) * 72 + mmv] = rv.z; Rt[(c4 + 3) * 72 + mmv] = rv.w;
            }
        }
        __syncthreads();

        // G for new window half -> ring slot (jt+2)%3  (warp-private rows)
        {
            int slot = (jt + 2) % 3;
#pragma unroll
            for (int nf = 0; nf < 8; nf++) {
                float gc[4] = {0.f, 0.f, 0.f, 0.f};
                int n0 = nf * 8 + (lane >> 2);
#pragma unroll
                for (int kk = 0; kk < 8; kk++) {
                    int kr = kk * 8 + kc;
                    uint32_t b0 = f2tf32(Rt[kr * 72 + n0]);
                    uint32_t b1 = f2tf32(Rt[(kr + 4) * 72 + n0]);
                    mma_tf32(gc, aQv[kk][0], aQv[kk][1], aQv[kk][2], aQv[kk][3], b0, b1);
                }
                int col = slot * 64 + nf * 8 + kc * 2;
                Gs[r0 * 200 + col] = gc[0];       Gs[r0 * 200 + col + 1] = gc[1];
                Gs[(r0 + 8) * 200 + col] = gc[2]; Gs[(r0 + 8) * 200 + col + 1] = gc[3];
            }
        }
        __syncwarp();

        // S = AC via mma
        float sc[8][4];
#pragma unroll
        for (int nf = 0; nf < 8; nf++) {
            sc[nf][0] = sc[nf][1] = sc[nf][2] = sc[nf][3] = 0.f;
            int n0 = nf * 8 + (lane >> 2);
#pragma unroll
            for (int kk = 0; kk < 8; kk++) {
                int kr = kk * 8 + kc;
                uint32_t b0 = f2tf32(Kt[kr * 72 + n0]);
                uint32_t b1 = f2tf32(Kt[(kr + 4) * 72 + n0]);
                mma_tf32(sc[nf], aQu[kk][0], aQu[kk][1], aQu[kk][2], aQu[kk][3], b0, b1);
            }
        }

        // + BD gather, scale, causal mask
#pragma unroll
        for (int nf = 0; nf < 8; nf++) {
#pragma unroll
            for (int e = 0; e < 4; e++) {
                int rl = r0 + ((e >= 2) ? 8 : 0);
                int jl = nf * 8 + kc * 2 + (e & 1);
                int m_lin = jl + 127 - rl;
                int slotg = (jt + (m_lin >> 6)) % 3;
                float val = (sc[nf][e] + Gs[rl * 200 + slotg * 64 + (m_lin & 63)]) * scale;
                if (causal && (j0 + jl) > (i0 + rl + Mm)) val = -1e30f;
                sc[nf][e] = val;
            }
        }

        // online softmax (rows fully within warp: lanes differing in lane&3)
        float rm0 = -1e30f, rm1 = -1e30f;
#pragma unroll
        for (int nf = 0; nf < 8; nf++) {
            rm0 = fmaxf(rm0, fmaxf(sc[nf][0], sc[nf][1]));
            rm1 = fmaxf(rm1, fmaxf(sc[nf][2], sc[nf][3]));
        }
        rm0 = fmaxf(rm0, __shfl_xor_sync(0xffffffffu, rm0, 1));
        rm0 = fmaxf(rm0, __shfl_xor_sync(0xffffffffu, rm0, 2));
        rm1 = fmaxf(rm1, __shfl_xor_sync(0xffffffffu, rm1, 1));
        rm1 = fmaxf(rm1, __shfl_xor_sync(0xffffffffu, rm1, 2));
        float mn0 = fmaxf(mi0, rm0), mn1 = fmaxf(mi1, rm1);
        float corr0 = __expf(mi0 - mn0), corr1 = __expf(mi1 - mn1);
        float sum0 = 0.f, sum1 = 0.f;
#pragma unroll
        for (int nf = 0; nf < 8; nf++) {
            float p0 = __expf(sc[nf][0] - mn0);
            float p1 = __expf(sc[nf][1] - mn0);
            float p2 = __expf(sc[nf][2] - mn1);
            float p3 = __expf(sc[nf][3] - mn1);
            sc[nf][0] = p0; sc[nf][1] = p1; sc[nf][2] = p2; sc[nf][3] = p3;
            sum0 += p0 + p1; sum1 += p2 + p3;
        }
        sum0 += __shfl_xor_sync(0xffffffffu, sum0, 1);
        sum0 += __shfl_xor_sync(0xffffffffu, sum0, 2);
        sum1 += __shfl_xor_sync(0xffffffffu, sum1, 1);
        sum1 += __shfl_xor_sync(0xffffffffu, sum1, 2);
        li0 = li0 * corr0 + sum0; li1 = li1 * corr1 + sum1;
        mi0 = mn0; mi1 = mn1;
#pragma unroll
        for (int nf = 0; nf < 8; nf++) {
            oc[nf][0] *= corr0; oc[nf][1] *= corr0;
            oc[nf][2] *= corr1; oc[nf][3] *= corr1;
        }

        // stage P (warp-private rows) then PV mma
#pragma unroll
        for (int nf = 0; nf < 8; nf++) {
            int col = nf * 8 + kc * 2;
            *(float2*)&Ps[r0 * 72 + col]       = make_float2(sc[nf][0], sc[nf][1]);
            *(float2*)&Ps[(r0 + 8) * 72 + col] = make_float2(sc[nf][2], sc[nf][3]);
        }
        __syncwarp();
        uint32_t pa[8][4];
#pragma unroll
        for (int kk = 0; kk < 8; kk++) {
            int d0 = kk * 8 + kc, d1 = d0 + 4;
            pa[kk][0] = f2tf32(Ps[r0 * 72 + d0]);
            pa[kk][1] = f2tf32(Ps[(r0 + 8) * 72 + d0]);
            pa[kk][2] = f2tf32(Ps[r0 * 72 + d1]);
            pa[kk][3] = f2tf32(Ps[(r0 + 8) * 72 + d1]);
        }
#pragma unroll
        for (int nf = 0; nf < 8; nf++) {
            int n0 = nf * 8 + (lane >> 2);
#pragma unroll
            for (int kk = 0; kk < 8; kk++) {
                int kr = kk * 8 + kc;
                uint32_t b0 = f2tf32(Vsm[kr * 72 + n0]);
                uint32_t b1 = f2tf32(Vsm[(kr + 4) * 72 + n0]);
                mma_tf32(oc[nf], pa[kk][0], pa[kk][1], pa[kk][2], pa[kk][3], b0, b1);
            }
        }
    }

    // ---- epilogue: O / l ----
    float inv0 = 1.f / li0, inv1 = 1.f / li1;
    float* ob0 = outg + ((size_t)(b * Tt + i0 + r0)) * D_MODEL + h * D_HEADc;
    float* ob1 = outg + ((size_t)(b * Tt + i0 + r0 + 8)) * D_MODEL + h * D_HEADc;
#pragma unroll
    for (int nf = 0; nf < 8; nf++) {
        int col = nf * 8 + kc * 2;
        *(float2*)&ob0[col] = make_float2(oc[nf][0] * inv0, oc[nf][1] * inv0);
        *(float2*)&ob1[col] = make_float2(oc[nf][2] * inv1, oc[nf][3] * inv1);
    }
}

// ---------------- LayerNorm over last dim (D=1024), one block per row ----------------
__global__ void __launch_bounds__(256)
layernorm_k(const float* __restrict__ in, const float* __restrict__ g,
            const float* __restrict__ be, float* __restrict__ out) {
    __shared__ float red[34];
    const int row = blockIdx.x;
    const int tid = threadIdx.x;
    float4 v = ((const float4*)(in + (size_t)row * D_MODEL))[tid];

    float s = v.x + v.y + v.z + v.w;
    int lane = tid & 31, wid = tid >> 5;
#pragma unroll
    for (int off = 16; off >= 1; off >>= 1) s += __shfl_xor_sync(0xffffffffu, s, off);
    if (lane == 0) red[wid] = s;
    __syncthreads();
    if (tid == 0) {
        float t = 0.f;
#pragma unroll
        for (int w2 = 0; w2 < 8; w2++) t += red[w2];
        red[32] = t;
    }
    __syncthreads();
    float mu = red[32] * (1.f / (float)D_MODEL);

    float dx0 = v.x - mu, dx1 = v.y - mu, dx2 = v.z - mu, dx3 = v.w - mu;
    float sq = dx0 * dx0 + dx1 * dx1 + dx2 * dx2 + dx3 * dx3;
#pragma unroll
    for (int off = 16; off >= 1; off >>= 1) sq += __shfl_xor_sync(0xffffffffu, sq, off);
    if (lane == 0) red[wid] = sq;
    __syncthreads();
    if (tid == 0) {
        float t = 0.f;
#pragma unroll
        for (int w2 = 0; w2 < 8; w2++) t += red[w2];
        red[33] = t;
    }
    __syncthreads();
    float rstd = rsqrtf(red[33] * (1.f / (float)D_MODEL) + 1e-5f);

    float4 gv = ((const float4*)g)[tid];
    float4 bv = ((const float4*)be)[tid];
    float4 o;
    o.x = dx0 * rstd * gv.x + bv.x;
    o.y = dx1 * rstd * gv.y + bv.y;
    o.z = dx2 * rstd * gv.z + bv.z;
    o.w = dx3 * rstd * gv.w + bv.w;
    ((float4*)(out + (size_t)row * D_MODEL))[tid] = o;
}

// ---------------- launch ----------------
extern "C" void kernel_launch(void* const* d_in, const int* in_sizes, int n_in,
                              void* d_out, int out_size) {
    const float* x    = (const float*)d_in[0];
    const float* mem  = (const float*)d_in[1];
    const float* Wq   = (const float*)d_in[2];
    const float* bq   = (const float*)d_in[3];
    const float* Wk   = (const float*)d_in[4];
    const float* bk   = (const float*)d_in[5];
    const float* Wv   = (const float*)d_in[6];
    const float* bv   = (const float*)d_in[7];
    const float* Wo   = (const float*)d_in[8];
    const float* bo   = (const float*)d_in[9];
    const float* Wr   = (const float*)d_in[10];
    const float* u    = (const float*)d_in[11];
    const float* vpar = (const float*)d_in[12];
    const float* g1   = (const float*)d_in[13];
    const float* be1  = (const float*)d_in[14];
    const float* g2   = (const float*)d_in[15];
    const float* be2  = (const float*)d_in[16];
    const float* W1   = (const float*)d_in[17];
    const float* b1   = (const float*)d_in[18];
    const float* W2   = (const float*)d_in[19];
    const float* b2   = (const float*)d_in[20];
    const int*   isc  = (const int*)d_in[21];
    float* out = (float*)d_out;

    float *P, *r, *q, *c, *k, *vv, *attn, *s, *h, *f1, *invf;
    cudaGetSymbolAddress((void**)&P,    g_P);
    cudaGetSymbolAddress((void**)&r,    g_r);
    cudaGetSymbolAddress((void**)&q,    g_q);
    cudaGetSymbolAddress((void**)&c,    g_c);
    cudaGetSymbolAddress((void**)&k,    g_k);
    cudaGetSymbolAddress((void**)&vv,   g_v);
    cudaGetSymbolAddress((void**)&attn, g_attn);
    cudaGetSymbolAddress((void**)&s,    g_s);
    cudaGetSymbolAddress((void**)&h,    g_h);
    cudaGetSymbolAddress((void**)&f1,   g_f1);
    cudaGetSymbolAddress((void**)&invf, g_invf);

    cudaFuncSetAttribute(tgemm<0>, cudaFuncAttributeMaxDynamicSharedMemorySize, TG_SMEM);
    cudaFuncSetAttribute(tgemm<1>, cudaFuncAttributeMaxDynamicSharedMemorySize, TG_SMEM);
    cudaFuncSetAttribute(tgemm<2>, cudaFuncAttributeMaxDynamicSharedMemorySize, TG_SMEM);
    cudaFuncSetAttribute(tgemm_nb, cudaFuncAttributeMaxDynamicSharedMemorySize, TG_SMEM);
    cudaFuncSetAttribute(flash_xl_tc, cudaFuncAttributeMaxDynamicSharedMemorySize, FA_SMEM);

    fill_invf<<<1, 512>>>(invf);
    fill_pos<<<(KK * D_MODEL + 255) / 256, 256>>>(P, invf);
    concat_kernel<<<(ROWS_C * (D_MODEL / 4) + 255) / 256, 256>>>(x, mem, c);

    // projections (tf32 tensor cores)
    tgemm<0><<<dim3(D_MODEL / 128, ROWS_X / 128), 256, TG_SMEM>>>(x, Wq, bq, nullptr, q, D_MODEL, D_MODEL);
    tgemm<0><<<dim3(D_MODEL / 128, ROWS_C / 128), 256, TG_SMEM>>>(c, Wk, bk, nullptr, k, D_MODEL, D_MODEL);
    tgemm<0><<<dim3(D_MODEL / 128, ROWS_C / 128), 256, TG_SMEM>>>(c, Wv, bv, nullptr, vv, D_MODEL, D_MODEL);
    tgemm_nb<<<dim3(D_MODEL / 128, KK / 128), 256, TG_SMEM>>>(P, Wr, r, D_MODEL, D_MODEL);

    // attention (tensor-core flash)
    flash_xl_tc<<<dim3(Tt / 128, N_HEADc, Bb), 256, FA_SMEM>>>(q, k, vv, r, u, vpar, isc, attn);

    // o-proj + residual, LN1
    tgemm<2><<<dim3(D_MODEL / 128, ROWS_X / 128), 256, TG_SMEM>>>(attn, Wo, bo, x, s, D_MODEL, D_MODEL);
    layernorm_k<<<ROWS_X, 256>>>(s, g1, be1, h);

    // FFN
    tgemm<1><<<dim3(FFN_H / 128, ROWS_X / 128), 256, TG_SMEM>>>(h, W1, b1, nullptr, f1, FFN_H, D_MODEL);
    tgemm<2><<<dim3(D_MODEL / 128, ROWS_X / 128), 256, TG_SMEM>>>(f1, W2, b2, h, s, D_MODEL, FFN_H);
    layernorm_k<<<ROWS_X, 256>>>(s, g2, be2, out);
}

// round 7
// speedup vs baseline: 3.7532x; 1.0880x over previous
#include <cuda_runtime.h>
#include <math.h>
#include <stdint.h>

// ---------------- problem constants ----------------
#define D_MODEL 1024
#define N_HEADc 16
#define D_HEADc 64
#define FFN_H   4096
#define Bb      4
#define Tt      2048
#define Mm      2048
#define KK      4096            // M + T
#define ROWS_X  (Bb*Tt)         // 8192
#define ROWS_C  (Bb*KK)         // 16384

// ---------------- scratch (static device memory; no runtime alloc) ----------------
static __device__ float g_P   [(size_t)KK*D_MODEL];
static __device__ float g_r   [(size_t)KK*D_MODEL];
static __device__ float g_q   [(size_t)ROWS_X*D_MODEL];
static __device__ float g_c   [(size_t)ROWS_C*D_MODEL];
static __device__ float g_k   [(size_t)ROWS_C*D_MODEL];
static __device__ float g_v   [(size_t)ROWS_C*D_MODEL];
static __device__ float g_vt  [(size_t)Bb*N_HEADc*D_HEADc*KK];   // V transposed: [(b,h,d)][key]
static __device__ float g_attn[(size_t)ROWS_X*D_MODEL];
static __device__ float g_s   [(size_t)ROWS_X*D_MODEL];
static __device__ float g_h   [(size_t)ROWS_X*D_MODEL];
static __device__ float g_f1  [(size_t)ROWS_X*FFN_H];
static __device__ float g_invf[512];

// ---------------- helpers ----------------
__device__ __forceinline__ float gelu_f(float x) {
    float x3 = x * x * x;
    float t  = tanhf(0.7978845608028654f * (x + 0.044715f * x3));
    return 0.5f * x * (1.0f + t);
}

__device__ __forceinline__ uint32_t f2tf32(float x) {
    uint32_t r;
    asm("cvt.rna.tf32.f32 %0, %1;" : "=r"(r) : "f"(x));
    return r;
}
// round-to-nearest tf32, returned as float bit pattern (mma reads upper bits)
__device__ __forceinline__ float tf32r(float x) {
    return __uint_as_float(f2tf32(x));
}

__device__ __forceinline__ void mma_tf32(float c[4], uint32_t a0, uint32_t a1,
                                         uint32_t a2, uint32_t a3,
                                         uint32_t b0, uint32_t b1) {
    asm volatile(
        "mma.sync.aligned.m16n8k8.row.col.f32.tf32.tf32.f32 "
        "{%0,%1,%2,%3},{%4,%5,%6,%7},{%8,%9},{%0,%1,%2,%3};"
        : "+f"(c[0]), "+f"(c[1]), "+f"(c[2]), "+f"(c[3])
        : "r"(a0), "r"(a1), "r"(a2), "r"(a3), "r"(b0), "r"(b1));
}

__device__ __forceinline__ void cp16(void* smem, const void* g) {
    uint32_t s = (uint32_t)__cvta_generic_to_shared(smem);
    asm volatile("cp.async.cg.shared.global [%0], [%1], 16;" :: "r"(s), "l"(g));
}

// ---------------- positional tables ----------------
__global__ void fill_invf(float* __restrict__ invf) {
    int f = threadIdx.x;
    if (f < 512) {
        double v = exp(-((double)(2 * f) / (double)D_MODEL) * log(10000.0));
        invf[f] = (float)v;
    }
}

__global__ void fill_pos(float* __restrict__ P, const float* __restrict__ invf) {
    int idx = blockIdx.x * blockDim.x + threadIdx.x;
    if (idx >= KK * D_MODEL) return;
    int m   = idx / D_MODEL;
    int col = idx - m * D_MODEL;
    float pos = (float)(KK - 1 - m);
    int f = (col < D_MODEL / 2) ? col : col - D_MODEL / 2;
    float ang = pos * __ldg(&invf[f]);
    P[idx] = (col < D_MODEL / 2) ? sinf(ang) : cosf(ang);
}

// ---------------- concat c = [mem, x] along seq ----------------
__global__ void concat_kernel(const float* __restrict__ x, const float* __restrict__ mem,
                              float* __restrict__ c) {
    int idx = blockIdx.x * blockDim.x + threadIdx.x;     // float4 units
    const int row_f4 = D_MODEL / 4;                      // 256
    if (idx >= ROWS_C * row_f4) return;
    int row = idx / row_f4;
    int col = idx - row * row_f4;
    int b = row / KK;
    int t = row - b * KK;
    const float4* src;
    if (t < Mm) src = (const float4*)mem + ((size_t)(b * Mm + t)) * row_f4 + col;
    else        src = (const float4*)x   + ((size_t)(b * Tt + (t - Mm))) * row_f4 + col;
    ((float4*)c)[idx] = *src;
}

// ---------------- V transpose: g_v [b*K+t][h*64+d] -> g_vt [(b,h,d)][t] ----------------
__global__ void __launch_bounds__(256)
transpose_v(const float* __restrict__ v, float* __restrict__ vt) {
    __shared__ float ts[64][65];
    const int tid = threadIdx.x;
    const int t0 = blockIdx.x * 64, h = blockIdx.y, b = blockIdx.z;
#pragma unroll
    for (int p = 0; p < 4; p++) {
        int idx = tid + p * 256;
        int tr = idx >> 4, c4 = (idx & 15) << 2;
        float4 vv = *(const float4*)&v[(size_t)(b * KK + t0 + tr) * D_MODEL + h * D_HEADc + c4];
        ts[c4 + 0][tr] = vv.x; ts[c4 + 1][tr] = vv.y;
        ts[c4 + 2][tr] = vv.z; ts[c4 + 3][tr] = vv.w;
    }
    __syncthreads();
#pragma unroll
    for (int p = 0; p < 4; p++) {
        int idx = tid + p * 256;
        int d = idx >> 4, c4 = (idx & 15) << 2;
        float4 w4 = make_float4(ts[d][c4], ts[d][c4 + 1], ts[d][c4 + 2], ts[d][c4 + 3]);
        *(float4*)&vt[((size_t)((b * N_HEADc + h) * D_HEADc + d)) * KK + t0 + c4] = w4;
    }
}

// ---------------- tf32 tensor-core GEMM: 128x128 tile, 32-deep K stages ----------------
// After each stage lands, an in-place vectorized rna-round pass converts the tile to
// tf32 bit patterns once; the mma fragment loads then skip per-element cvt.
#define TG_AS (128*36)
#define TG_BS (32*136)
#define TG_STG (TG_AS + TG_BS)
#define TG_SMEM (3 * TG_STG * 4)

template <int EPI>
__global__ void __launch_bounds__(256)
tgemm(const float* __restrict__ A, const float* __restrict__ Bm,
      const float* __restrict__ bias, const float* __restrict__ res,
      float* __restrict__ C, int Ndim, int Kdim) {
    extern __shared__ float smx[];
    const int tid = threadIdx.x, wid = tid >> 5, lane = tid & 31;
    const int bm = blockIdx.y * 128, bn = blockIdx.x * 128;
    const int wm = (wid >> 2) * 64, wn = (wid & 3) * 32;
    const int KT = Kdim / 32;

    float acc[4][4][4];
#pragma unroll
    for (int mi = 0; mi < 4; mi++)
#pragma unroll
        for (int nj = 0; nj < 4; nj++)
#pragma unroll
            for (int e = 0; e < 4; e++) acc[mi][nj][e] = 0.f;

    auto issue = [&](int kt) {
        int s = kt % 3;
        float* As = smx + s * TG_STG;
        float* Bs = As + TG_AS;
        int k0 = kt * 32;
#pragma unroll
        for (int p = 0; p < 4; p++) {
            int f4 = tid + p * 256;
            int r = f4 >> 3, c4 = (f4 & 7) << 2;
            cp16(&As[r * 36 + c4], &A[(size_t)(bm + r) * Kdim + k0 + c4]);
        }
#pragma unroll
        for (int p = 0; p < 4; p++) {
            int f4 = tid + p * 256;
            int r = f4 >> 5, c4 = (f4 & 31) << 2;
            cp16(&Bs[r * 136 + c4], &Bm[(size_t)(k0 + r) * Ndim + bn + c4]);
        }
        asm volatile("cp.async.commit_group;");
    };

    auto cvtpass = [&](int s) {
        float* St = smx + s * TG_STG;
#pragma unroll
        for (int p = 0; p < 9; p++) {
            int f4 = tid + p * 256;
            if (f4 < TG_STG / 4) {
                float4 vz = *(float4*)&St[f4 * 4];
                vz.x = tf32r(vz.x); vz.y = tf32r(vz.y);
                vz.z = tf32r(vz.z); vz.w = tf32r(vz.w);
                *(float4*)&St[f4 * 4] = vz;
            }
        }
    };

    auto compute = [&](int s) {
        const float* As = smx + s * TG_STG;
        const float* Bs = As + TG_AS;
#pragma unroll
        for (int sub = 0; sub < 4; sub++) {
            int kk = sub * 8;
            uint32_t af[4][4], bf[4][2];
#pragma unroll
            for (int mi = 0; mi < 4; mi++) {
                int m0 = wm + mi * 16 + (lane >> 2);
                int kc = kk + (lane & 3);
                af[mi][0] = __float_as_uint(As[(m0)     * 36 + kc]);
                af[mi][1] = __float_as_uint(As[(m0 + 8) * 36 + kc]);
                af[mi][2] = __float_as_uint(As[(m0)     * 36 + kc + 4]);
                af[mi][3] = __float_as_uint(As[(m0 + 8) * 36 + kc + 4]);
            }
#pragma unroll
            for (int nj = 0; nj < 4; nj++) {
                int n0 = wn + nj * 8 + (lane >> 2);
                int kr = kk + (lane & 3);
                bf[nj][0] = __float_as_uint(Bs[(kr)     * 136 + n0]);
                bf[nj][1] = __float_as_uint(Bs[(kr + 4) * 136 + n0]);
            }
#pragma unroll
            for (int mi = 0; mi < 4; mi++)
#pragma unroll
                for (int nj = 0; nj < 4; nj++)
                    mma_tf32(acc[mi][nj], af[mi][0], af[mi][1], af[mi][2], af[mi][3],
                             bf[nj][0], bf[nj][1]);
        }
    };

    issue(0);
    issue(1);
    for (int kt = 0; kt < KT; kt++) {
        if (kt == KT - 1) asm volatile("cp.async.wait_group 0;");
        else              asm volatile("cp.async.wait_group 1;");
        __syncthreads();
        if (kt + 2 < KT) issue(kt + 2);
        cvtpass(kt % 3);
        __syncthreads();
        compute(kt % 3);
    }

#pragma unroll
    for (int mi = 0; mi < 4; mi++) {
#pragma unroll
        for (int nj = 0; nj < 4; nj++) {
            int row = bm + wm + mi * 16 + (lane >> 2);
            int col = bn + wn + nj * 8 + (lane & 3) * 2;
#pragma unroll
            for (int half = 0; half < 2; half++) {
                int r = row + half * 8;
                float v0 = acc[mi][nj][half * 2 + 0];
                float v1 = acc[mi][nj][half * 2 + 1];
                if (EPI != 3) { v0 += bias[col]; v1 += bias[col + 1]; }
                if (EPI == 1) { v0 = gelu_f(v0); v1 = gelu_f(v1); }
                if (EPI == 2) {
                    v0 += res[(size_t)r * Ndim + col];
                    v1 += res[(size_t)r * Ndim + col + 1];
                }
                float2 w = make_float2(v0, v1);
                *(float2*)&C[(size_t)r * Ndim + col] = w;
            }
        }
    }
}

// ---------------- tensor-core flash attention with XL relative term ----------------
// B-operands (K, R, V) pre-rounded to tf32 and stored fragment-packed:
//   row pitch 36 float2; slot (kk*4+kc) of row n holds the (k, k+4) pair one mma
//   lane needs -> conflict-free LDS.64, zero in-loop cvt.
// V is loaded from the transposed copy g_vt so its pairs (key axis) pack the same way.
// G ring: 4 slots x 64 cols (power-of-2 gather), pitch 264 for conflict-free stores.
#define FP_KP 0
#define FP_RP (FP_KP + 64*72)
#define FP_VP (FP_RP + 64*72)
#define FP_GS (FP_VP + 64*72)          // 128 x 264
#define FP_PS (FP_GS + 128*264)        // 128 x 72
#define FP_SMEM ((FP_PS + 128*72) * 4) // 227,328 B

__global__ void __launch_bounds__(256, 1)
flash_xl_tc(const float* __restrict__ qg, const float* __restrict__ kg,
            const float* __restrict__ vtg, const float* __restrict__ rg,
            const float* __restrict__ ug, const float* __restrict__ vpg,
            const int* __restrict__ iscp, float* __restrict__ outg) {
    extern __shared__ float sm[];
    float* KP = sm + FP_KP;
    float* RP = sm + FP_RP;
    float* VP = sm + FP_VP;
    float* Gs = sm + FP_GS;
    float* Ps = sm + FP_PS;

    const int tid = threadIdx.x, lane = tid & 31, w = tid >> 5;
    const int i0 = blockIdx.x * 128, h = blockIdx.y, b = blockIdx.z;
    const int causal = iscp[0];
    const int r0 = w * 16 + (lane >> 2);
    const int kc = lane & 3;
    const int base0 = Tt - 128 - i0;

    // ---- load Q into Ps, build A-fragments for Q+u and Q+v (rna-rounded) ----
    {
        const float* qbase = qg + ((size_t)(b * Tt + i0)) * D_MODEL + h * D_HEADc;
#pragma unroll
        for (int p = 0; p < 8; p++) {
            int idx = tid + p * 256;
            int rl = idx >> 4, c4 = (idx & 15) << 2;
            *(float4*)&Ps[rl * 72 + c4] = *(const float4*)&qbase[(size_t)rl * D_MODEL + c4];
        }
    }
    __syncthreads();

    uint32_t aQu[8][4], aQv[8][4];
#pragma unroll
    for (int kk = 0; kk < 8; kk++) {
        int d0 = kk * 8 + kc, d1 = d0 + 4;
        float u0 = __ldg(&ug[h * D_HEADc + d0]),  u1 = __ldg(&ug[h * D_HEADc + d1]);
        float v0 = __ldg(&vpg[h * D_HEADc + d0]), v1 = __ldg(&vpg[h * D_HEADc + d1]);
        float q00 = Ps[r0 * 72 + d0],       q10 = Ps[(r0 + 8) * 72 + d0];
        float q01 = Ps[r0 * 72 + d1],       q11 = Ps[(r0 + 8) * 72 + d1];
        aQu[kk][0] = f2tf32(q00 + u0); aQu[kk][1] = f2tf32(q10 + u0);
        aQu[kk][2] = f2tf32(q01 + u1); aQu[kk][3] = f2tf32(q11 + u1);
        aQv[kk][0] = f2tf32(q00 + v0); aQv[kk][1] = f2tf32(q10 + v0);
        aQv[kk][2] = f2tf32(q01 + v1); aQv[kk][3] = f2tf32(q11 + v1);
    }
    __syncthreads();   // Ps free for P staging

    // ---- prefill G ring positions [0,128) ----
#pragma unroll
    for (int hh = 0; hh < 2; hh++) {
        int rb = base0 + hh * 64;
#pragma unroll
        for (int p = 0; p < 4; p++) {
            int idx = tid + p * 256;
            int mr = idx >> 4, c4 = (idx & 15) << 2;
            int gr = rb + mr; if (gr > KK - 1) gr = KK - 1; if (gr < 0) gr = 0;
            float4 rv = *(const float4*)&rg[(size_t)gr * D_MODEL + h * D_HEADc + c4];
            int fb = mr * 72 + (c4 >> 3) * 8 + ((c4 >> 2) & 1);
            RP[fb + 0] = tf32r(rv.x); RP[fb + 2] = tf32r(rv.y);
            RP[fb + 4] = tf32r(rv.z); RP[fb + 6] = tf32r(rv.w);
        }
        __syncthreads();
#pragma unroll
        for (int nf = 0; nf < 8; nf++) {
            float gc[4] = {0.f, 0.f, 0.f, 0.f};
            int n0 = nf * 8 + (lane >> 2);
#pragma unroll
            for (int kk = 0; kk < 8; kk++) {
                float2 rv = *(const float2*)&RP[n0 * 72 + kk * 8 + kc * 2];
                mma_tf32(gc, aQv[kk][0], aQv[kk][1], aQv[kk][2], aQv[kk][3],
                         __float_as_uint(rv.x), __float_as_uint(rv.y));
            }
            int col = hh * 64 + nf * 8 + kc * 2;
            *(float2*)&Gs[r0 * 264 + col]       = make_float2(gc[0], gc[1]);
            *(float2*)&Gs[(r0 + 8) * 264 + col] = make_float2(gc[2], gc[3]);
        }
        __syncthreads();
    }

    // ---- main loop ----
    float mi0 = -1e30f, mi1 = -1e30f, li0 = 0.f, li1 = 0.f;
    float oc[8][4];
#pragma unroll
    for (int nf = 0; nf < 8; nf++)
#pragma unroll
        for (int e = 0; e < 4; e++) oc[nf][e] = 0.f;

    const int njt = causal ? (i0 / 64 + 34) : (KK / 64);
    const float scale = 0.125f;
    const size_t vrowbase = (size_t)((b * N_HEADc + h) * D_HEADc) * KK;

    for (int jt = 0; jt < njt; jt++) {
        const int j0 = jt * 64;
        __syncthreads();   // prior-iter fragment readers of KP/RP/VP done

        {   // K packed, V packed (from transposed V), new R half packed
            const float* kb = kg + ((size_t)(b * KK + j0)) * D_MODEL + h * D_HEADc;
#pragma unroll
            for (int p = 0; p < 4; p++) {
                int idx = tid + p * 256;
                int j = idx >> 4, c4 = (idx & 15) << 2;
                float4 kv = *(const float4*)&kb[(size_t)j * D_MODEL + c4];
                int fb = j * 72 + (c4 >> 3) * 8 + ((c4 >> 2) & 1);
                KP[fb + 0] = tf32r(kv.x); KP[fb + 2] = tf32r(kv.y);
                KP[fb + 4] = tf32r(kv.z); KP[fb + 6] = tf32r(kv.w);
            }
#pragma unroll
            for (int p = 0; p < 4; p++) {
                int idx = tid + p * 256;
                int d = idx >> 4, c4 = (idx & 15) << 2;
                float4 vv4 = *(const float4*)&vtg[vrowbase + (size_t)d * KK + j0 + c4];
                int fb = d * 72 + (c4 >> 3) * 8 + ((c4 >> 2) & 1);
                VP[fb + 0] = tf32r(vv4.x); VP[fb + 2] = tf32r(vv4.y);
                VP[fb + 4] = tf32r(vv4.z); VP[fb + 6] = tf32r(vv4.w);
            }
            int rb = base0 + j0 + 128;
#pragma unroll
            for (int p = 0; p < 4; p++) {
                int idx = tid + p * 256;
                int mr = idx >> 4, c4 = (idx & 15) << 2;
                int gr = rb + mr; if (gr > KK - 1) gr = KK - 1;
                float4 rv = *(const float4*)&rg[(size_t)gr * D_MODEL + h * D_HEADc + c4];
                int fb = mr * 72 + (c4 >> 3) * 8 + ((c4 >> 2) & 1);
                RP[fb + 0] = tf32r(rv.x); RP[fb + 2] = tf32r(rv.y);
                RP[fb + 4] = tf32r(rv.z); RP[fb + 6] = tf32r(rv.w);
            }
        }
        __syncthreads();

        // G for new window half -> ring position ((jt+2)&3)*64  (warp-private rows)
        {
            int gbase = ((jt + 2) & 3) * 64;
#pragma unroll
            for (int nf = 0; nf < 8; nf++) {
                float gc[4] = {0.f, 0.f, 0.f, 0.f};
                int n0 = nf * 8 + (lane >> 2);
#pragma unroll
                for (int kk = 0; kk < 8; kk++) {
                    float2 rv = *(const float2*)&RP[n0 * 72 + kk * 8 + kc * 2];
                    mma_tf32(gc, aQv[kk][0], aQv[kk][1], aQv[kk][2], aQv[kk][3],
                             __float_as_uint(rv.x), __float_as_uint(rv.y));
                }
                int col = gbase + nf * 8 + kc * 2;
                *(float2*)&Gs[r0 * 264 + col]       = make_float2(gc[0], gc[1]);
                *(float2*)&Gs[(r0 + 8) * 264 + col] = make_float2(gc[2], gc[3]);
            }
        }
        __syncwarp();

        // S = AC via mma
        float sc[8][4];
#pragma unroll
        for (int nf = 0; nf < 8; nf++) {
            sc[nf][0] = sc[nf][1] = sc[nf][2] = sc[nf][3] = 0.f;
            int n0 = nf * 8 + (lane >> 2);
#pragma unroll
            for (int kk = 0; kk < 8; kk++) {
                float2 kv = *(const float2*)&KP[n0 * 72 + kk * 8 + kc * 2];
                mma_tf32(sc[nf], aQu[kk][0], aQu[kk][1], aQu[kk][2], aQu[kk][3],
                         __float_as_uint(kv.x), __float_as_uint(kv.y));
            }
        }

        // + BD gather from ring, scale, causal mask
        const int jtb = (jt * 64) & 255;
#pragma unroll
        for (int nf = 0; nf < 8; nf++) {
#pragma unroll
            for (int e = 0; e < 4; e++) {
                int rl = r0 + ((e >= 2) ? 8 : 0);
                int jl = nf * 8 + kc * 2 + (e & 1);
                int ridx = (jtb + jl + 127 - rl) & 255;
                float val = (sc[nf][e] + Gs[rl * 264 + ridx]) * scale;
                if (causal && (j0 + jl) > (i0 + rl + Mm)) val = -1e30f;
                sc[nf][e] = val;
            }
        }

        // online softmax (rows within warp; reduce across lane&3)
        float rm0 = -1e30f, rm1 = -1e30f;
#pragma unroll
        for (int nf = 0; nf < 8; nf++) {
            rm0 = fmaxf(rm0, fmaxf(sc[nf][0], sc[nf][1]));
            rm1 = fmaxf(rm1, fmaxf(sc[nf][2], sc[nf][3]));
        }
        rm0 = fmaxf(rm0, __shfl_xor_sync(0xffffffffu, rm0, 1));
        rm0 = fmaxf(rm0, __shfl_xor_sync(0xffffffffu, rm0, 2));
        rm1 = fmaxf(rm1, __shfl_xor_sync(0xffffffffu, rm1, 1));
        rm1 = fmaxf(rm1, __shfl_xor_sync(0xffffffffu, rm1, 2));
        float mn0 = fmaxf(mi0, rm0), mn1 = fmaxf(mi1, rm1);
        float corr0 = __expf(mi0 - mn0), corr1 = __expf(mi1 - mn1);
        float sum0 = 0.f, sum1 = 0.f;
#pragma unroll
        for (int nf = 0; nf < 8; nf++) {
            float p0 = __expf(sc[nf][0] - mn0);
            float p1 = __expf(sc[nf][1] - mn0);
            float p2 = __expf(sc[nf][2] - mn1);
            float p3 = __expf(sc[nf][3] - mn1);
            sc[nf][0] = p0; sc[nf][1] = p1; sc[nf][2] = p2; sc[nf][3] = p3;
            sum0 += p0 + p1; sum1 += p2 + p3;
        }
        sum0 += __shfl_xor_sync(0xffffffffu, sum0, 1);
        sum0 += __shfl_xor_sync(0xffffffffu, sum0, 2);
        sum1 += __shfl_xor_sync(0xffffffffu, sum1, 1);
        sum1 += __shfl_xor_sync(0xffffffffu, sum1, 2);
        li0 = li0 * corr0 + sum0; li1 = li1 * corr1 + sum1;
        mi0 = mn0; mi1 = mn1;
#pragma unroll
        for (int nf = 0; nf < 8; nf++) {
            oc[nf][0] *= corr0; oc[nf][1] *= corr0;
            oc[nf][2] *= corr1; oc[nf][3] *= corr1;
        }

        // stage P (warp-private rows) then PV mma
#pragma unroll
        for (int nf = 0; nf < 8; nf++) {
            int col = nf * 8 + kc * 2;
            *(float2*)&Ps[r0 * 72 + col]       = make_float2(sc[nf][0], sc[nf][1]);
            *(float2*)&Ps[(r0 + 8) * 72 + col] = make_float2(sc[nf][2], sc[nf][3]);
        }
        __syncwarp();
        uint32_t pa[8][4];
#pragma unroll
        for (int kk = 0; kk < 8; kk++) {
            int d0 = kk * 8 + kc, d1 = d0 + 4;
            pa[kk][0] = f2tf32(Ps[r0 * 72 + d0]);
            pa[kk][1] = f2tf32(Ps[(r0 + 8) * 72 + d0]);
            pa[kk][2] = f2tf32(Ps[r0 * 72 + d1]);
            pa[kk][3] = f2tf32(Ps[(r0 + 8) * 72 + d1]);
        }
#pragma unroll
        for (int nf = 0; nf < 8; nf++) {
            int n0 = nf * 8 + (lane >> 2);
#pragma unroll
            for (int kk = 0; kk < 8; kk++) {
                float2 vv = *(const float2*)&VP[n0 * 72 + kk * 8 + kc * 2];
                mma_tf32(oc[nf], pa[kk][0], pa[kk][1], pa[kk][2], pa[kk][3],
                         __float_as_uint(vv.x), __float_as_uint(vv.y));
            }
        }
    }

    // ---- epilogue: O / l ----
    float inv0 = 1.f / li0, inv1 = 1.f / li1;
    float* ob0 = outg + ((size_t)(b * Tt + i0 + r0)) * D_MODEL + h * D_HEADc;
    float* ob1 = outg + ((size_t)(b * Tt + i0 + r0 + 8)) * D_MODEL + h * D_HEADc;
#pragma unroll
    for (int nf = 0; nf < 8; nf++) {
        int col = nf * 8 + kc * 2;
        *(float2*)&ob0[col] = make_float2(oc[nf][0] * inv0, oc[nf][1] * inv0);
        *(float2*)&ob1[col] = make_float2(oc[nf][2] * inv1, oc[nf][3] * inv1);
    }
}

// ---------------- LayerNorm over last dim (D=1024), one block per row ----------------
__global__ void __launch_bounds__(256)
layernorm_k(const float* __restrict__ in, const float* __restrict__ g,
            const float* __restrict__ be, float* __restrict__ out) {
    __shared__ float red[34];
    const int row = blockIdx.x;
    const int tid = threadIdx.x;
    float4 v = ((const float4*)(in + (size_t)row * D_MODEL))[tid];

    float s = v.x + v.y + v.z + v.w;
    int lane = tid & 31, wid = tid >> 5;
#pragma unroll
    for (int off = 16; off >= 1; off >>= 1) s += __shfl_xor_sync(0xffffffffu, s, off);
    if (lane == 0) red[wid] = s;
    __syncthreads();
    if (tid == 0) {
        float t = 0.f;
#pragma unroll
        for (int w2 = 0; w2 < 8; w2++) t += red[w2];
        red[32] = t;
    }
    __syncthreads();
    float mu = red[32] * (1.f / (float)D_MODEL);

    float dx0 = v.x - mu, dx1 = v.y - mu, dx2 = v.z - mu, dx3 = v.w - mu;
    float sq = dx0 * dx0 + dx1 * dx1 + dx2 * dx2 + dx3 * dx3;
#pragma unroll
    for (int off = 16; off >= 1; off >>= 1) sq += __shfl_xor_sync(0xffffffffu, sq, off);
    if (lane == 0) red[wid] = sq;
    __syncthreads();
    if (tid == 0) {
        float t = 0.f;
#pragma unroll
        for (int w2 = 0; w2 < 8; w2++) t += red[w2];
        red[33] = t;
    }
    __syncthreads();
    float rstd = rsqrtf(red[33] * (1.f / (float)D_MODEL) + 1e-5f);

    float4 gv = ((const float4*)g)[tid];
    float4 bv = ((const float4*)be)[tid];
    float4 o;
    o.x = dx0 * rstd * gv.x + bv.x;
    o.y = dx1 * rstd * gv.y + bv.y;
    o.z = dx2 * rstd * gv.z + bv.z;
    o.w = dx3 * rstd * gv.w + bv.w;
    ((float4*)(out + (size_t)row * D_MODEL))[tid] = o;
}

// ---------------- launch ----------------
extern "C" void kernel_launch(void* const* d_in, const int* in_sizes, int n_in,
                              void* d_out, int out_size) {
    const float* x    = (const float*)d_in[0];
    const float* mem  = (const float*)d_in[1];
    const float* Wq   = (const float*)d_in[2];
    const float* bq   = (const float*)d_in[3];
    const float* Wk   = (const float*)d_in[4];
    const float* bk   = (const float*)d_in[5];
    const float* Wv   = (const float*)d_in[6];
    const float* bv   = (const float*)d_in[7];
    const float* Wo   = (const float*)d_in[8];
    const float* bo   = (const float*)d_in[9];
    const float* Wr   = (const float*)d_in[10];
    const float* u    = (const float*)d_in[11];
    const float* vpar = (const float*)d_in[12];
    const float* g1   = (const float*)d_in[13];
    const float* be1  = (const float*)d_in[14];
    const float* g2   = (const float*)d_in[15];
    const float* be2  = (const float*)d_in[16];
    const float* W1   = (const float*)d_in[17];
    const float* b1   = (const float*)d_in[18];
    const float* W2   = (const float*)d_in[19];
    const float* b2   = (const float*)d_in[20];
    const int*   isc  = (const int*)d_in[21];
    float* out = (float*)d_out;

    float *P, *r, *q, *c, *k, *vv, *vt, *attn, *s, *h, *f1, *invf;
    cudaGetSymbolAddress((void**)&P,    g_P);
    cudaGetSymbolAddress((void**)&r,    g_r);
    cudaGetSymbolAddress((void**)&q,    g_q);
    cudaGetSymbolAddress((void**)&c,    g_c);
    cudaGetSymbolAddress((void**)&k,    g_k);
    cudaGetSymbolAddress((void**)&vv,   g_v);
    cudaGetSymbolAddress((void**)&vt,   g_vt);
    cudaGetSymbolAddress((void**)&attn, g_attn);
    cudaGetSymbolAddress((void**)&s,    g_s);
    cudaGetSymbolAddress((void**)&h,    g_h);
    cudaGetSymbolAddress((void**)&f1,   g_f1);
    cudaGetSymbolAddress((void**)&invf, g_invf);

    cudaFuncSetAttribute(tgemm<0>, cudaFuncAttributeMaxDynamicSharedMemorySize, TG_SMEM);
    cudaFuncSetAttribute(tgemm<1>, cudaFuncAttributeMaxDynamicSharedMemorySize, TG_SMEM);
    cudaFuncSetAttribute(tgemm<2>, cudaFuncAttributeMaxDynamicSharedMemorySize, TG_SMEM);
    cudaFuncSetAttribute(tgemm<3>, cudaFuncAttributeMaxDynamicSharedMemorySize, TG_SMEM);
    cudaFuncSetAttribute(flash_xl_tc, cudaFuncAttributeMaxDynamicSharedMemorySize, FP_SMEM);

    fill_invf<<<1, 512>>>(invf);
    fill_pos<<<(KK * D_MODEL + 255) / 256, 256>>>(P, invf);
    concat_kernel<<<(ROWS_C * (D_MODEL / 4) + 255) / 256, 256>>>(x, mem, c);

    // projections (tf32 tensor cores)
    tgemm<0><<<dim3(D_MODEL / 128, ROWS_X / 128), 256, TG_SMEM>>>(x, Wq, bq, nullptr, q, D_MODEL, D_MODEL);
    tgemm<0><<<dim3(D_MODEL / 128, ROWS_C / 128), 256, TG_SMEM>>>(c, Wk, bk, nullptr, k, D_MODEL, D_MODEL);
    tgemm<0><<<dim3(D_MODEL / 128, ROWS_C / 128), 256, TG_SMEM>>>(c, Wv, bv, nullptr, vv, D_MODEL, D_MODEL);
    tgemm<3><<<dim3(D_MODEL / 128, KK / 128), 256, TG_SMEM>>>(P, Wr, nullptr, nullptr, r, D_MODEL, D_MODEL);
    transpose_v<<<dim3(KK / 64, N_HEADc, Bb), 256>>>(vv, vt);

    // attention (tensor-core flash, fragment-packed operands)
    flash_xl_tc<<<dim3(Tt / 128, N_HEADc, Bb), 256, FP_SMEM>>>(q, k, vt, r, u, vpar, isc, attn);

    // o-proj + residual, LN1
    tgemm<2><<<dim3(D_MODEL / 128, ROWS_X / 128), 256, TG_SMEM>>>(attn, Wo, bo, x, s, D_MODEL, D_MODEL);
    layernorm_k<<<ROWS_X, 256>>>(s, g1, be1, h);

    // FFN
    tgemm<1><<<dim3(FFN_H / 128, ROWS_X / 128), 256, TG_SMEM>>>(h, W1, b1, nullptr, f1, FFN_H, D_MODEL);
    tgemm<2><<<dim3(D_MODEL / 128, ROWS_X / 128), 256, TG_SMEM>>>(f1, W2, b2, h, s, D_MODEL, FFN_H);
    layernorm_k<<<ROWS_X, 256>>>(s, g2, be2, out);
}

// round 8
// speedup vs baseline: 4.5651x; 1.2163x over previous
#include <cuda_runtime.h>
#include <math.h>
#include <stdint.h>

// ---------------- problem constants ----------------
#define D_MODEL 1024
#define N_HEADc 16
#define D_HEADc 64
#define FFN_H   4096
#define Bb      4
#define Tt      2048
#define Mm      2048
#define KK      4096            // M + T
#define ROWS_X  (Bb*Tt)         // 8192
#define ROWS_C  (Bb*KK)         // 16384

// ---------------- scratch (static device memory; no runtime alloc) ----------------
static __device__ float g_P   [(size_t)KK*D_MODEL];
static __device__ float g_r   [(size_t)KK*D_MODEL];
static __device__ float g_q   [(size_t)ROWS_X*D_MODEL];
static __device__ float g_c   [(size_t)ROWS_C*D_MODEL];
static __device__ float g_k   [(size_t)ROWS_C*D_MODEL];
static __device__ float g_v   [(size_t)ROWS_C*D_MODEL];
static __device__ float g_vt  [(size_t)Bb*N_HEADc*D_HEADc*KK];   // V transposed: [(b,h,d)][key]
static __device__ float g_attn[(size_t)ROWS_X*D_MODEL];
static __device__ float g_s   [(size_t)ROWS_X*D_MODEL];
static __device__ float g_h   [(size_t)ROWS_X*D_MODEL];
static __device__ float g_f1  [(size_t)ROWS_X*FFN_H];
static __device__ float g_invf[512];

// ---------------- helpers ----------------
__device__ __forceinline__ float gelu_f(float x) {
    float x3 = x * x * x;
    float t  = tanhf(0.7978845608028654f * (x + 0.044715f * x3));
    return 0.5f * x * (1.0f + t);
}

__device__ __forceinline__ uint32_t f2tf32(float x) {
    uint32_t r;
    asm("cvt.rna.tf32.f32 %0, %1;" : "=r"(r) : "f"(x));
    return r;
}
// round-to-nearest tf32, returned as float bit pattern (mma reads upper bits)
__device__ __forceinline__ float tf32r(float x) {
    return __uint_as_float(f2tf32(x));
}

__device__ __forceinline__ void mma_tf32(float c[4], uint32_t a0, uint32_t a1,
                                         uint32_t a2, uint32_t a3,
                                         uint32_t b0, uint32_t b1) {
    asm volatile(
        "mma.sync.aligned.m16n8k8.row.col.f32.tf32.tf32.f32 "
        "{%0,%1,%2,%3},{%4,%5,%6,%7},{%8,%9},{%0,%1,%2,%3};"
        : "+f"(c[0]), "+f"(c[1]), "+f"(c[2]), "+f"(c[3])
        : "r"(a0), "r"(a1), "r"(a2), "r"(a3), "r"(b0), "r"(b1));
}

__device__ __forceinline__ void cp16(void* smem, const void* g) {
    uint32_t s = (uint32_t)__cvta_generic_to_shared(smem);
    asm volatile("cp.async.cg.shared.global [%0], [%1], 16;" :: "r"(s), "l"(g));
}

// ---------------- positional tables ----------------
__global__ void fill_invf(float* __restrict__ invf) {
    int f = threadIdx.x;
    if (f < 512) {
        double v = exp(-((double)(2 * f) / (double)D_MODEL) * log(10000.0));
        invf[f] = (float)v;
    }
}

__global__ void fill_pos(float* __restrict__ P, const float* __restrict__ invf) {
    int idx = blockIdx.x * blockDim.x + threadIdx.x;
    if (idx >= KK * D_MODEL) return;
    int m   = idx / D_MODEL;
    int col = idx - m * D_MODEL;
    float pos = (float)(KK - 1 - m);
    int f = (col < D_MODEL / 2) ? col : col - D_MODEL / 2;
    float ang = pos * __ldg(&invf[f]);
    P[idx] = (col < D_MODEL / 2) ? sinf(ang) : cosf(ang);
}

// ---------------- concat c = [mem, x] along seq ----------------
__global__ void concat_kernel(const float* __restrict__ x, const float* __restrict__ mem,
                              float* __restrict__ c) {
    int idx = blockIdx.x * blockDim.x + threadIdx.x;     // float4 units
    const int row_f4 = D_MODEL / 4;                      // 256
    if (idx >= ROWS_C * row_f4) return;
    int row = idx / row_f4;
    int col = idx - row * row_f4;
    int b = row / KK;
    int t = row - b * KK;
    const float4* src;
    if (t < Mm) src = (const float4*)mem + ((size_t)(b * Mm + t)) * row_f4 + col;
    else        src = (const float4*)x   + ((size_t)(b * Tt + (t - Mm))) * row_f4 + col;
    ((float4*)c)[idx] = *src;
}

// ---------------- V transpose: g_v [b*K+t][h*64+d] -> g_vt [(b,h,d)][t] ----------------
__global__ void __launch_bounds__(256)
transpose_v(const float* __restrict__ v, float* __restrict__ vt) {
    __shared__ float ts[64][65];
    const int tid = threadIdx.x;
    const int t0 = blockIdx.x * 64, h = blockIdx.y, b = blockIdx.z;
#pragma unroll
    for (int p = 0; p < 4; p++) {
        int idx = tid + p * 256;
        int tr = idx >> 4, c4 = (idx & 15) << 2;
        float4 vv = *(const float4*)&v[(size_t)(b * KK + t0 + tr) * D_MODEL + h * D_HEADc + c4];
        ts[c4 + 0][tr] = vv.x; ts[c4 + 1][tr] = vv.y;
        ts[c4 + 2][tr] = vv.z; ts[c4 + 3][tr] = vv.w;
    }
    __syncthreads();
#pragma unroll
    for (int p = 0; p < 4; p++) {
        int idx = tid + p * 256;
        int d = idx >> 4, c4 = (idx & 15) << 2;
        float4 w4 = make_float4(ts[d][c4], ts[d][c4 + 1], ts[d][c4 + 2], ts[d][c4 + 3]);
        *(float4*)&vt[((size_t)((b * N_HEADc + h) * D_HEADc + d)) * KK + t0 + c4] = w4;
    }
}

// ---------------- tf32 tensor-core GEMM: 128x128 tile, 32-deep K stages ----------------
// R5 design: inline cvt at fragment load (FFMA-pipe, overlaps LDS).
// __launch_bounds__(256, 2) pins regs <= 128 so 2 CTAs/SM always fit.
// EPI: 0 = +bias ; 1 = gelu(+bias) ; 2 = +bias +res ; 3 = plain
#define TG_AS (128*36)
#define TG_BS (32*136)
#define TG_STG (TG_AS + TG_BS)
#define TG_SMEM (3 * TG_STG * 4)

template <int EPI>
__global__ void __launch_bounds__(256, 2)
tgemm(const float* __restrict__ A, const float* __restrict__ Bm,
      const float* __restrict__ bias, const float* __restrict__ res,
      float* __restrict__ C, int Ndim, int Kdim) {
    extern __shared__ float smx[];
    const int tid = threadIdx.x, wid = tid >> 5, lane = tid & 31;
    const int bm = blockIdx.y * 128, bn = blockIdx.x * 128;
    const int wm = (wid >> 2) * 64, wn = (wid & 3) * 32;
    const int KT = Kdim / 32;

    float acc[4][4][4];
#pragma unroll
    for (int mi = 0; mi < 4; mi++)
#pragma unroll
        for (int nj = 0; nj < 4; nj++)
#pragma unroll
            for (int e = 0; e < 4; e++) acc[mi][nj][e] = 0.f;

    auto issue = [&](int kt) {
        int s = kt % 3;
        float* As = smx + s * TG_STG;
        float* Bs = As + TG_AS;
        int k0 = kt * 32;
#pragma unroll
        for (int p = 0; p < 4; p++) {
            int f4 = tid + p * 256;            // A: 128 rows x 8 float4
            int r = f4 >> 3, c4 = (f4 & 7) << 2;
            cp16(&As[r * 36 + c4], &A[(size_t)(bm + r) * Kdim + k0 + c4]);
        }
#pragma unroll
        for (int p = 0; p < 4; p++) {
            int f4 = tid + p * 256;            // B: 32 rows x 32 float4
            int r = f4 >> 5, c4 = (f4 & 31) << 2;
            cp16(&Bs[r * 136 + c4], &Bm[(size_t)(k0 + r) * Ndim + bn + c4]);
        }
        asm volatile("cp.async.commit_group;");
    };

    auto compute = [&](int s) {
        const float* As = smx + s * TG_STG;
        const float* Bs = As + TG_AS;
#pragma unroll
        for (int sub = 0; sub < 4; sub++) {
            int kk = sub * 8;
            uint32_t af[4][4], bf[4][2];
#pragma unroll
            for (int mi = 0; mi < 4; mi++) {
                int m0 = wm + mi * 16 + (lane >> 2);
                int kc = kk + (lane & 3);
                af[mi][0] = f2tf32(As[(m0)     * 36 + kc]);
                af[mi][1] = f2tf32(As[(m0 + 8) * 36 + kc]);
                af[mi][2] = f2tf32(As[(m0)     * 36 + kc + 4]);
                af[mi][3] = f2tf32(As[(m0 + 8) * 36 + kc + 4]);
            }
#pragma unroll
            for (int nj = 0; nj < 4; nj++) {
                int n0 = wn + nj * 8 + (lane >> 2);
                int kr = kk + (lane & 3);
                bf[nj][0] = f2tf32(Bs[(kr)     * 136 + n0]);
                bf[nj][1] = f2tf32(Bs[(kr + 4) * 136 + n0]);
            }
#pragma unroll
            for (int mi = 0; mi < 4; mi++)
#pragma unroll
                for (int nj = 0; nj < 4; nj++)
                    mma_tf32(acc[mi][nj], af[mi][0], af[mi][1], af[mi][2], af[mi][3],
                             bf[nj][0], bf[nj][1]);
        }
    };

    issue(0);
    issue(1);
    for (int kt = 0; kt < KT; kt++) {
        if (kt == KT - 1) asm volatile("cp.async.wait_group 0;");
        else              asm volatile("cp.async.wait_group 1;");
        __syncthreads();
        if (kt + 2 < KT) issue(kt + 2);
        compute(kt % 3);
        __syncthreads();
    }

#pragma unroll
    for (int mi = 0; mi < 4; mi++) {
#pragma unroll
        for (int nj = 0; nj < 4; nj++) {
            int row = bm + wm + mi * 16 + (lane >> 2);
            int col = bn + wn + nj * 8 + (lane & 3) * 2;
#pragma unroll
            for (int half = 0; half < 2; half++) {
                int r = row + half * 8;
                float v0 = acc[mi][nj][half * 2 + 0];
                float v1 = acc[mi][nj][half * 2 + 1];
                if (EPI != 3) { v0 += bias[col]; v1 += bias[col + 1]; }
                if (EPI == 1) { v0 = gelu_f(v0); v1 = gelu_f(v1); }
                if (EPI == 2) {
                    v0 += res[(size_t)r * Ndim + col];
                    v1 += res[(size_t)r * Ndim + col + 1];
                }
                float2 w = make_float2(v0, v1);
                *(float2*)&C[(size_t)r * Ndim + col] = w;
            }
        }
    }
}

// ---------------- tensor-core flash attention with XL relative term ----------------
// B-operands (K, R, V) pre-rounded to tf32 and stored fragment-packed:
//   row pitch 36 float2; slot (kk*4+kc) of row n holds the (k, k+4) pair one mma
//   lane needs -> conflict-free LDS.64, zero in-loop cvt.
// V is loaded from the transposed copy g_vt so its pairs (key axis) pack the same way.
// G ring: 4 slots x 64 cols (power-of-2 gather), pitch 264 for conflict-free stores.
#define FP_KP 0
#define FP_RP (FP_KP + 64*72)
#define FP_VP (FP_RP + 64*72)
#define FP_GS (FP_VP + 64*72)          // 128 x 264
#define FP_PS (FP_GS + 128*264)        // 128 x 72
#define FP_SMEM ((FP_PS + 128*72) * 4) // 227,328 B

__global__ void __launch_bounds__(256, 1)
flash_xl_tc(const float* __restrict__ qg, const float* __restrict__ kg,
            const float* __restrict__ vtg, const float* __restrict__ rg,
            const float* __restrict__ ug, const float* __restrict__ vpg,
            const int* __restrict__ iscp, float* __restrict__ outg) {
    extern __shared__ float sm[];
    float* KP = sm + FP_KP;
    float* RP = sm + FP_RP;
    float* VP = sm + FP_VP;
    float* Gs = sm + FP_GS;
    float* Ps = sm + FP_PS;

    const int tid = threadIdx.x, lane = tid & 31, w = tid >> 5;
    const int i0 = blockIdx.x * 128, h = blockIdx.y, b = blockIdx.z;
    const int causal = iscp[0];
    const int r0 = w * 16 + (lane >> 2);
    const int kc = lane & 3;
    const int base0 = Tt - 128 - i0;

    // ---- load Q into Ps, build A-fragments for Q+u and Q+v (rna-rounded) ----
    {
        const float* qbase = qg + ((size_t)(b * Tt + i0)) * D_MODEL + h * D_HEADc;
#pragma unroll
        for (int p = 0; p < 8; p++) {
            int idx = tid + p * 256;
            int rl = idx >> 4, c4 = (idx & 15) << 2;
            *(float4*)&Ps[rl * 72 + c4] = *(const float4*)&qbase[(size_t)rl * D_MODEL + c4];
        }
    }
    __syncthreads();

    uint32_t aQu[8][4], aQv[8][4];
#pragma unroll
    for (int kk = 0; kk < 8; kk++) {
        int d0 = kk * 8 + kc, d1 = d0 + 4;
        float u0 = __ldg(&ug[h * D_HEADc + d0]),  u1 = __ldg(&ug[h * D_HEADc + d1]);
        float v0 = __ldg(&vpg[h * D_HEADc + d0]), v1 = __ldg(&vpg[h * D_HEADc + d1]);
        float q00 = Ps[r0 * 72 + d0],       q10 = Ps[(r0 + 8) * 72 + d0];
        float q01 = Ps[r0 * 72 + d1],       q11 = Ps[(r0 + 8) * 72 + d1];
        aQu[kk][0] = f2tf32(q00 + u0); aQu[kk][1] = f2tf32(q10 + u0);
        aQu[kk][2] = f2tf32(q01 + u1); aQu[kk][3] = f2tf32(q11 + u1);
        aQv[kk][0] = f2tf32(q00 + v0); aQv[kk][1] = f2tf32(q10 + v0);
        aQv[kk][2] = f2tf32(q01 + v1); aQv[kk][3] = f2tf32(q11 + v1);
    }
    __syncthreads();   // Ps free for P staging

    // ---- prefill G ring positions [0,128) ----
#pragma unroll
    for (int hh = 0; hh < 2; hh++) {
        int rb = base0 + hh * 64;
#pragma unroll
        for (int p = 0; p < 4; p++) {
            int idx = tid + p * 256;
            int mr = idx >> 4, c4 = (idx & 15) << 2;
            int gr = rb + mr; if (gr > KK - 1) gr = KK - 1; if (gr < 0) gr = 0;
            float4 rv = *(const float4*)&rg[(size_t)gr * D_MODEL + h * D_HEADc + c4];
            int fb = mr * 72 + (c4 >> 3) * 8 + ((c4 >> 2) & 1);
            RP[fb + 0] = tf32r(rv.x); RP[fb + 2] = tf32r(rv.y);
            RP[fb + 4] = tf32r(rv.z); RP[fb + 6] = tf32r(rv.w);
        }
        __syncthreads();
#pragma unroll
        for (int nf = 0; nf < 8; nf++) {
            float gc[4] = {0.f, 0.f, 0.f, 0.f};
            int n0 = nf * 8 + (lane >> 2);
#pragma unroll
            for (int kk = 0; kk < 8; kk++) {
                float2 rv = *(const float2*)&RP[n0 * 72 + kk * 8 + kc * 2];
                mma_tf32(gc, aQv[kk][0], aQv[kk][1], aQv[kk][2], aQv[kk][3],
                         __float_as_uint(rv.x), __float_as_uint(rv.y));
            }
            int col = hh * 64 + nf * 8 + kc * 2;
            *(float2*)&Gs[r0 * 264 + col]       = make_float2(gc[0], gc[1]);
            *(float2*)&Gs[(r0 + 8) * 264 + col] = make_float2(gc[2], gc[3]);
        }
        __syncthreads();
    }

    // ---- main loop ----
    float mi0 = -1e30f, mi1 = -1e30f, li0 = 0.f, li1 = 0.f;
    float oc[8][4];
#pragma unroll
    for (int nf = 0; nf < 8; nf++)
#pragma unroll
        for (int e = 0; e < 4; e++) oc[nf][e] = 0.f;

    const int njt = causal ? (i0 / 64 + 34) : (KK / 64);
    const float scale = 0.125f;
    const size_t vrowbase = (size_t)((b * N_HEADc + h) * D_HEADc) * KK;

    for (int jt = 0; jt < njt; jt++) {
        const int j0 = jt * 64;
        __syncthreads();   // prior-iter fragment readers of KP/RP/VP done

        {   // K packed, V packed (from transposed V), new R half packed
            const float* kb = kg + ((size_t)(b * KK + j0)) * D_MODEL + h * D_HEADc;
#pragma unroll
            for (int p = 0; p < 4; p++) {
                int idx = tid + p * 256;
                int j = idx >> 4, c4 = (idx & 15) << 2;
                float4 kv = *(const float4*)&kb[(size_t)j * D_MODEL + c4];
                int fb = j * 72 + (c4 >> 3) * 8 + ((c4 >> 2) & 1);
                KP[fb + 0] = tf32r(kv.x); KP[fb + 2] = tf32r(kv.y);
                KP[fb + 4] = tf32r(kv.z); KP[fb + 6] = tf32r(kv.w);
            }
#pragma unroll
            for (int p = 0; p < 4; p++) {
                int idx = tid + p * 256;
                int d = idx >> 4, c4 = (idx & 15) << 2;
                float4 vv4 = *(const float4*)&vtg[vrowbase + (size_t)d * KK + j0 + c4];
                int fb = d * 72 + (c4 >> 3) * 8 + ((c4 >> 2) & 1);
                VP[fb + 0] = tf32r(vv4.x); VP[fb + 2] = tf32r(vv4.y);
                VP[fb + 4] = tf32r(vv4.z); VP[fb + 6] = tf32r(vv4.w);
            }
            int rb = base0 + j0 + 128;
#pragma unroll
            for (int p = 0; p < 4; p++) {
                int idx = tid + p * 256;
                int mr = idx >> 4, c4 = (idx & 15) << 2;
                int gr = rb + mr; if (gr > KK - 1) gr = KK - 1;
                float4 rv = *(const float4*)&rg[(size_t)gr * D_MODEL + h * D_HEADc + c4];
                int fb = mr * 72 + (c4 >> 3) * 8 + ((c4 >> 2) & 1);
                RP[fb + 0] = tf32r(rv.x); RP[fb + 2] = tf32r(rv.y);
                RP[fb + 4] = tf32r(rv.z); RP[fb + 6] = tf32r(rv.w);
            }
        }
        __syncthreads();

        // G for new window half -> ring position ((jt+2)&3)*64  (warp-private rows)
        {
            int gbase = ((jt + 2) & 3) * 64;
#pragma unroll
            for (int nf = 0; nf < 8; nf++) {
                float gc[4] = {0.f, 0.f, 0.f, 0.f};
                int n0 = nf * 8 + (lane >> 2);
#pragma unroll
                for (int kk = 0; kk < 8; kk++) {
                    float2 rv = *(const float2*)&RP[n0 * 72 + kk * 8 + kc * 2];
                    mma_tf32(gc, aQv[kk][0], aQv[kk][1], aQv[kk][2], aQv[kk][3],
                             __float_as_uint(rv.x), __float_as_uint(rv.y));
                }
                int col = gbase + nf * 8 + kc * 2;
                *(float2*)&Gs[r0 * 264 + col]       = make_float2(gc[0], gc[1]);
                *(float2*)&Gs[(r0 + 8) * 264 + col] = make_float2(gc[2], gc[3]);
            }
        }
        __syncwarp();

        // S = AC via mma
        float sc[8][4];
#pragma unroll
        for (int nf = 0; nf < 8; nf++) {
            sc[nf][0] = sc[nf][1] = sc[nf][2] = sc[nf][3] = 0.f;
            int n0 = nf * 8 + (lane >> 2);
#pragma unroll
            for (int kk = 0; kk < 8; kk++) {
                float2 kv = *(const float2*)&KP[n0 * 72 + kk * 8 + kc * 2];
                mma_tf32(sc[nf], aQu[kk][0], aQu[kk][1], aQu[kk][2], aQu[kk][3],
                         __float_as_uint(kv.x), __float_as_uint(kv.y));
            }
        }

        // + BD gather from ring, scale, causal mask
        const int jtb = (jt * 64) & 255;
#pragma unroll
        for (int nf = 0; nf < 8; nf++) {
#pragma unroll
            for (int e = 0; e < 4; e++) {
                int rl = r0 + ((e >= 2) ? 8 : 0);
                int jl = nf * 8 + kc * 2 + (e & 1);
                int ridx = (jtb + jl + 127 - rl) & 255;
                float val = (sc[nf][e] + Gs[rl * 264 + ridx]) * scale;
                if (causal && (j0 + jl) > (i0 + rl + Mm)) val = -1e30f;
                sc[nf][e] = val;
            }
        }

        // online softmax (rows within warp; reduce across lane&3)
        float rm0 = -1e30f, rm1 = -1e30f;
#pragma unroll
        for (int nf = 0; nf < 8; nf++) {
            rm0 = fmaxf(rm0, fmaxf(sc[nf][0], sc[nf][1]));
            rm1 = fmaxf(rm1, fmaxf(sc[nf][2], sc[nf][3]));
        }
        rm0 = fmaxf(rm0, __shfl_xor_sync(0xffffffffu, rm0, 1));
        rm0 = fmaxf(rm0, __shfl_xor_sync(0xffffffffu, rm0, 2));
        rm1 = fmaxf(rm1, __shfl_xor_sync(0xffffffffu, rm1, 1));
        rm1 = fmaxf(rm1, __shfl_xor_sync(0xffffffffu, rm1, 2));
        float mn0 = fmaxf(mi0, rm0), mn1 = fmaxf(mi1, rm1);
        float corr0 = __expf(mi0 - mn0), corr1 = __expf(mi1 - mn1);
        float sum0 = 0.f, sum1 = 0.f;
#pragma unroll
        for (int nf = 0; nf < 8; nf++) {
            float p0 = __expf(sc[nf][0] - mn0);
            float p1 = __expf(sc[nf][1] - mn0);
            float p2 = __expf(sc[nf][2] - mn1);
            float p3 = __expf(sc[nf][3] - mn1);
            sc[nf][0] = p0; sc[nf][1] = p1; sc[nf][2] = p2; sc[nf][3] = p3;
            sum0 += p0 + p1; sum1 += p2 + p3;
        }
        sum0 += __shfl_xor_sync(0xffffffffu, sum0, 1);
        sum0 += __shfl_xor_sync(0xffffffffu, sum0, 2);
        sum1 += __shfl_xor_sync(0xffffffffu, sum1, 1);
        sum1 += __shfl_xor_sync(0xffffffffu, sum1, 2);
        li0 = li0 * corr0 + sum0; li1 = li1 * corr1 + sum1;
        mi0 = mn0; mi1 = mn1;
#pragma unroll
        for (int nf = 0; nf < 8; nf++) {
            oc[nf][0] *= corr0; oc[nf][1] *= corr0;
            oc[nf][2] *= corr1; oc[nf][3] *= corr1;
        }

        // stage P (warp-private rows) then PV mma
#pragma unroll
        for (int nf = 0; nf < 8; nf++) {
            int col = nf * 8 + kc * 2;
            *(float2*)&Ps[r0 * 72 + col]       = make_float2(sc[nf][0], sc[nf][1]);
            *(float2*)&Ps[(r0 + 8) * 72 + col] = make_float2(sc[nf][2], sc[nf][3]);
        }
        __syncwarp();
        uint32_t pa[8][4];
#pragma unroll
        for (int kk = 0; kk < 8; kk++) {
            int d0 = kk * 8 + kc, d1 = d0 + 4;
            pa[kk][0] = f2tf32(Ps[r0 * 72 + d0]);
            pa[kk][1] = f2tf32(Ps[(r0 + 8) * 72 + d0]);
            pa[kk][2] = f2tf32(Ps[r0 * 72 + d1]);
            pa[kk][3] = f2tf32(Ps[(r0 + 8) * 72 + d1]);
        }
#pragma unroll
        for (int nf = 0; nf < 8; nf++) {
            int n0 = nf * 8 + (lane >> 2);
#pragma unroll
            for (int kk = 0; kk < 8; kk++) {
                float2 vv = *(const float2*)&VP[n0 * 72 + kk * 8 + kc * 2];
                mma_tf32(oc[nf], pa[kk][0], pa[kk][1], pa[kk][2], pa[kk][3],
                         __float_as_uint(vv.x), __float_as_uint(vv.y));
            }
        }
    }

    // ---- epilogue: O / l ----
    float inv0 = 1.f / li0, inv1 = 1.f / li1;
    float* ob0 = outg + ((size_t)(b * Tt + i0 + r0)) * D_MODEL + h * D_HEADc;
    float* ob1 = outg + ((size_t)(b * Tt + i0 + r0 + 8)) * D_MODEL + h * D_HEADc;
#pragma unroll
    for (int nf = 0; nf < 8; nf++) {
        int col = nf * 8 + kc * 2;
        *(float2*)&ob0[col] = make_float2(oc[nf][0] * inv0, oc[nf][1] * inv0);
        *(float2*)&ob1[col] = make_float2(oc[nf][2] * inv1, oc[nf][3] * inv1);
    }
}

// ---------------- LayerNorm over last dim (D=1024), one block per row ----------------
__global__ void __launch_bounds__(256)
layernorm_k(const float* __restrict__ in, const float* __restrict__ g,
            const float* __restrict__ be, float* __restrict__ out) {
    __shared__ float red[34];
    const int row = blockIdx.x;
    const int tid = threadIdx.x;
    float4 v = ((const float4*)(in + (size_t)row * D_MODEL))[tid];

    float s = v.x + v.y + v.z + v.w;
    int lane = tid & 31, wid = tid >> 5;
#pragma unroll
    for (int off = 16; off >= 1; off >>= 1) s += __shfl_xor_sync(0xffffffffu, s, off);
    if (lane == 0) red[wid] = s;
    __syncthreads();
    if (tid == 0) {
        float t = 0.f;
#pragma unroll
        for (int w2 = 0; w2 < 8; w2++) t += red[w2];
        red[32] = t;
    }
    __syncthreads();
    float mu = red[32] * (1.f / (float)D_MODEL);

    float dx0 = v.x - mu, dx1 = v.y - mu, dx2 = v.z - mu, dx3 = v.w - mu;
    float sq = dx0 * dx0 + dx1 * dx1 + dx2 * dx2 + dx3 * dx3;
#pragma unroll
    for (int off = 16; off >= 1; off >>= 1) sq += __shfl_xor_sync(0xffffffffu, sq, off);
    if (lane == 0) red[wid] = sq;
    __syncthreads();
    if (tid == 0) {
        float t = 0.f;
#pragma unroll
        for (int w2 = 0; w2 < 8; w2++) t += red[w2];
        red[33] = t;
    }
    __syncthreads();
    float rstd = rsqrtf(red[33] * (1.f / (float)D_MODEL) + 1e-5f);

    float4 gv = ((const float4*)g)[tid];
    float4 bv = ((const float4*)be)[tid];
    float4 o;
    o.x = dx0 * rstd * gv.x + bv.x;
    o.y = dx1 * rstd * gv.y + bv.y;
    o.z = dx2 * rstd * gv.z + bv.z;
    o.w = dx3 * rstd * gv.w + bv.w;
    ((float4*)(out + (size_t)row * D_MODEL))[tid] = o;
}

// ---------------- launch ----------------
extern "C" void kernel_launch(void* const* d_in, const int* in_sizes, int n_in,
                              void* d_out, int out_size) {
    const float* x    = (const float*)d_in[0];
    const float* mem  = (const float*)d_in[1];
    const float* Wq   = (const float*)d_in[2];
    const float* bq   = (const float*)d_in[3];
    const float* Wk   = (const float*)d_in[4];
    const float* bk   = (const float*)d_in[5];
    const float* Wv   = (const float*)d_in[6];
    const float* bv   = (const float*)d_in[7];
    const float* Wo   = (const float*)d_in[8];
    const float* bo   = (const float*)d_in[9];
    const float* Wr   = (const float*)d_in[10];
    const float* u    = (const float*)d_in[11];
    const float* vpar = (const float*)d_in[12];
    const float* g1   = (const float*)d_in[13];
    const float* be1  = (const float*)d_in[14];
    const float* g2   = (const float*)d_in[15];
    const float* be2  = (const float*)d_in[16];
    const float* W1   = (const float*)d_in[17];
    const float* b1   = (const float*)d_in[18];
    const float* W2   = (const float*)d_in[19];
    const float* b2   = (const float*)d_in[20];
    const int*   isc  = (const int*)d_in[21];
    float* out = (float*)d_out;

    float *P, *r, *q, *c, *k, *vv, *vt, *attn, *s, *h, *f1, *invf;
    cudaGetSymbolAddress((void**)&P,    g_P);
    cudaGetSymbolAddress((void**)&r,    g_r);
    cudaGetSymbolAddress((void**)&q,    g_q);
    cudaGetSymbolAddress((void**)&c,    g_c);
    cudaGetSymbolAddress((void**)&k,    g_k);
    cudaGetSymbolAddress((void**)&vv,   g_v);
    cudaGetSymbolAddress((void**)&vt,   g_vt);
    cudaGetSymbolAddress((void**)&attn, g_attn);
    cudaGetSymbolAddress((void**)&s,    g_s);
    cudaGetSymbolAddress((void**)&h,    g_h);
    cudaGetSymbolAddress((void**)&f1,   g_f1);
    cudaGetSymbolAddress((void**)&invf, g_invf);

    cudaFuncSetAttribute(tgemm<0>, cudaFuncAttributeMaxDynamicSharedMemorySize, TG_SMEM);
    cudaFuncSetAttribute(tgemm<1>, cudaFuncAttributeMaxDynamicSharedMemorySize, TG_SMEM);
    cudaFuncSetAttribute(tgemm<2>, cudaFuncAttributeMaxDynamicSharedMemorySize, TG_SMEM);
    cudaFuncSetAttribute(tgemm<3>, cudaFuncAttributeMaxDynamicSharedMemorySize, TG_SMEM);
    cudaFuncSetAttribute(flash_xl_tc, cudaFuncAttributeMaxDynamicSharedMemorySize, FP_SMEM);

    fill_invf<<<1, 512>>>(invf);
    fill_pos<<<(KK * D_MODEL + 255) / 256, 256>>>(P, invf);
    concat_kernel<<<(ROWS_C * (D_MODEL / 4) + 255) / 256, 256>>>(x, mem, c);

    // projections (tf32 tensor cores)
    tgemm<0><<<dim3(D_MODEL / 128, ROWS_X / 128), 256, TG_SMEM>>>(x, Wq, bq, nullptr, q, D_MODEL, D_MODEL);
    tgemm<0><<<dim3(D_MODEL / 128, ROWS_C / 128), 256, TG_SMEM>>>(c, Wk, bk, nullptr, k, D_MODEL, D_MODEL);
    tgemm<0><<<dim3(D_MODEL / 128, ROWS_C / 128), 256, TG_SMEM>>>(c, Wv, bv, nullptr, vv, D_MODEL, D_MODEL);
    tgemm<3><<<dim3(D_MODEL / 128, KK / 128), 256, TG_SMEM>>>(P, Wr, nullptr, nullptr, r, D_MODEL, D_MODEL);
    transpose_v<<<dim3(KK / 64, N_HEADc, Bb), 256>>>(vv, vt);

    // attention (tensor-core flash, fragment-packed operands)
    flash_xl_tc<<<dim3(Tt / 128, N_HEADc, Bb), 256, FP_SMEM>>>(q, k, vt, r, u, vpar, isc, attn);

    // o-proj + residual, LN1
    tgemm<2><<<dim3(D_MODEL / 128, ROWS_X / 128), 256, TG_SMEM>>>(attn, Wo, bo, x, s, D_MODEL, D_MODEL);
    layernorm_k<<<ROWS_X, 256>>>(s, g1, be1, h);

    // FFN
    tgemm<1><<<dim3(FFN_H / 128, ROWS_X / 128), 256, TG_SMEM>>>(h, W1, b1, nullptr, f1, FFN_H, D_MODEL);
    tgemm<2><<<dim3(D_MODEL / 128, ROWS_X / 128), 256, TG_SMEM>>>(f1, W2, b2, h, s, D_MODEL, FFN_H);
    layernorm_k<<<ROWS_X, 256>>>(s, g2, be2, out);
}

// round 11
// speedup vs baseline: 5.0093x; 1.0973x over previous
#include <cuda_runtime.h>
#include <math.h>
#include <stdint.h>

// ---------------- problem constants ----------------
#define D_MODEL 1024
#define N_HEADc 16
#define D_HEADc 64
#define FFN_H   4096
#define Bb      4
#define Tt      2048
#define Mm      2048
#define KK      4096            // M + T
#define ROWS_X  (Bb*Tt)         // 8192
#define ROWS_C  (Bb*KK)         // 16384

// ---------------- scratch (static device memory; no runtime alloc) ----------------
static __device__ float g_P   [(size_t)KK*D_MODEL];        // packed-A layout
static __device__ float g_r   [(size_t)KK*D_MODEL];
static __device__ float g_q   [(size_t)ROWS_X*D_MODEL];
static __device__ float g_c   [(size_t)ROWS_C*D_MODEL];
static __device__ float g_k   [(size_t)ROWS_C*D_MODEL];
static __device__ float g_v   [(size_t)ROWS_C*D_MODEL];
static __device__ float g_vt  [(size_t)Bb*N_HEADc*D_HEADc*KK];
static __device__ float g_attn[(size_t)ROWS_X*D_MODEL];
static __device__ float g_s   [(size_t)ROWS_X*D_MODEL];
static __device__ float g_h   [(size_t)ROWS_X*D_MODEL];
static __device__ float g_f1  [(size_t)ROWS_X*FFN_H];
static __device__ float g_invf[512];
// packed-A activation copies
static __device__ float g_xp  [(size_t)ROWS_X*D_MODEL];
static __device__ float g_cp  [(size_t)ROWS_C*D_MODEL];
static __device__ float g_ap  [(size_t)ROWS_X*D_MODEL];
static __device__ float g_hp  [(size_t)ROWS_X*D_MODEL];
static __device__ float g_f1p [(size_t)ROWS_X*FFN_H];
// packed weights
static __device__ float g_wqp[(size_t)D_MODEL*D_MODEL];
static __device__ float g_wkp[(size_t)D_MODEL*D_MODEL];
static __device__ float g_wvp[(size_t)D_MODEL*D_MODEL];
static __device__ float g_wrp[(size_t)D_MODEL*D_MODEL];
static __device__ float g_wop[(size_t)D_MODEL*D_MODEL];
static __device__ float g_w1p[(size_t)D_MODEL*FFN_H];
static __device__ float g_w2p[(size_t)FFN_H*D_MODEL];

// ---------------- helpers ----------------
__device__ __forceinline__ float gelu_f(float x) {
    float x3 = x * x * x;
    float t  = tanhf(0.7978845608028654f * (x + 0.044715f * x3));
    return 0.5f * x * (1.0f + t);
}

__device__ __forceinline__ uint32_t f2tf32(float x) {
    uint32_t r;
    asm("cvt.rna.tf32.f32 %0, %1;" : "=r"(r) : "f"(x));
    return r;
}
__device__ __forceinline__ float tf32r(float x) {
    return __uint_as_float(f2tf32(x));
}

__device__ __forceinline__ void mma_tf32(float c[4], uint32_t a0, uint32_t a1,
                                         uint32_t a2, uint32_t a3,
                                         uint32_t b0, uint32_t b1) {
    asm volatile(
        "mma.sync.aligned.m16n8k8.row.col.f32.tf32.tf32.f32 "
        "{%0,%1,%2,%3},{%4,%5,%6,%7},{%8,%9},{%0,%1,%2,%3};"
        : "+f"(c[0]), "+f"(c[1]), "+f"(c[2]), "+f"(c[3])
        : "r"(a0), "r"(a1), "r"(a2), "r"(a3), "r"(b0), "r"(b1));
}

__device__ __forceinline__ void cp16(void* smem, const void* g) {
    uint32_t s = (uint32_t)__cvta_generic_to_shared(smem);
    asm volatile("cp.async.cg.shared.global [%0], [%1], 16;" :: "r"(s), "l"(g));
}

// ---------------- operand pack kernels ----------------
// packed-A: per (mg,kg) cell, 32 lanes x float4 {A[m0][kc], A[m0+8][kc], A[m0][kc+4], A[m0+8][kc+4]}
// with m0 = mg*16 + lane/4, kc = kg*8 + lane%4. Pre-rounded to tf32.
__global__ void __launch_bounds__(256)
pack_a(const float* __restrict__ A, float* __restrict__ Ap, int Mdim, int Kdim) {
    int t = blockIdx.x * blockDim.x + threadIdx.x;
    int kgdim = Kdim >> 3;
    int total = (Mdim >> 4) * kgdim * 32;
    if (t >= total) return;
    int lane = t & 31, cell = t >> 5;
    int mg = cell / kgdim, kg = cell - mg * kgdim;
    int m0 = mg * 16 + (lane >> 2);
    int k0 = kg * 8 + (lane & 3);
    float4 v;
    v.x = tf32r(A[(size_t)m0 * Kdim + k0]);
    v.y = tf32r(A[(size_t)(m0 + 8) * Kdim + k0]);
    v.z = tf32r(A[(size_t)m0 * Kdim + k0 + 4]);
    v.w = tf32r(A[(size_t)(m0 + 8) * Kdim + k0 + 4]);
    *(float4*)&Ap[(size_t)t * 4] = v;
}

// packed-B: per (kg,n) cell, 4 float2 pairs {W[kg*8+kc][n], W[kg*8+kc+4][n]}, kc=0..3. tf32 pre-rounded.
__global__ void __launch_bounds__(256)
pack_w(const float* __restrict__ W, float* __restrict__ Wp, int Ndim, int Kdim) {
    int t = blockIdx.x * blockDim.x + threadIdx.x;
    int total = (Kdim >> 3) * Ndim;
    if (t >= total) return;
    int kg = t / Ndim, n = t - kg * Ndim;
    float p0a = tf32r(W[(size_t)(kg * 8 + 0) * Ndim + n]);
    float p0b = tf32r(W[(size_t)(kg * 8 + 4) * Ndim + n]);
    float p1a = tf32r(W[(size_t)(kg * 8 + 1) * Ndim + n]);
    float p1b = tf32r(W[(size_t)(kg * 8 + 5) * Ndim + n]);
    float p2a = tf32r(W[(size_t)(kg * 8 + 2) * Ndim + n]);
    float p2b = tf32r(W[(size_t)(kg * 8 + 6) * Ndim + n]);
    float p3a = tf32r(W[(size_t)(kg * 8 + 3) * Ndim + n]);
    float p3b = tf32r(W[(size_t)(kg * 8 + 7) * Ndim + n]);
    float* dst = Wp + (size_t)t * 8;
    *(float4*)dst       = make_float4(p0a, p0b, p1a, p1b);
    *(float4*)(dst + 4) = make_float4(p2a, p2b, p3a, p3b);
}

// ---------------- positional tables ----------------
__global__ void fill_invf(float* __restrict__ invf) {
    int f = threadIdx.x;
    if (f < 512) {
        double v = exp(-((double)(2 * f) / (double)D_MODEL) * log(10000.0));
        invf[f] = (float)v;
    }
}

// writes P directly in packed-A layout (tf32-rounded)
__global__ void fill_pos_packed(float* __restrict__ P, const float* __restrict__ invf) {
    int idx = blockIdx.x * blockDim.x + threadIdx.x;
    if (idx >= KK * D_MODEL) return;
    int elem = idx & 3, lane = (idx >> 2) & 31, cell = idx >> 7;
    int kg = cell & 127;          // D_MODEL/8 = 128
    int mg = cell >> 7;
    int m   = mg * 16 + (lane >> 2) + ((elem & 1) << 3);
    int col = kg * 8 + (lane & 3) + ((elem >> 1) << 2);
    float pos = (float)(KK - 1 - m);
    int f = (col < D_MODEL / 2) ? col : col - D_MODEL / 2;
    float ang = pos * __ldg(&invf[f]);
    P[idx] = tf32r((col < D_MODEL / 2) ? sinf(ang) : cosf(ang));
}

// ---------------- concat c = [mem, x] along seq ----------------
__global__ void concat_kernel(const float* __restrict__ x, const float* __restrict__ mem,
                              float* __restrict__ c) {
    int idx = blockIdx.x * blockDim.x + threadIdx.x;     // float4 units
    const int row_f4 = D_MODEL / 4;                      // 256
    if (idx >= ROWS_C * row_f4) return;
    int row = idx / row_f4;
    int col = idx - row * row_f4;
    int b = row / KK;
    int t = row - b * KK;
    const float4* src;
    if (t < Mm) src = (const float4*)mem + ((size_t)(b * Mm + t)) * row_f4 + col;
    else        src = (const float4*)x   + ((size_t)(b * Tt + (t - Mm))) * row_f4 + col;
    ((float4*)c)[idx] = *src;
}

// ---------------- V transpose: g_v [b*K+t][h*64+d] -> g_vt [(b,h,d)][t] ----------------
__global__ void __launch_bounds__(256)
transpose_v(const float* __restrict__ v, float* __restrict__ vt) {
    __shared__ float ts[64][65];
    const int tid = threadIdx.x;
    const int t0 = blockIdx.x * 64, h = blockIdx.y, b = blockIdx.z;
#pragma unroll
    for (int p = 0; p < 4; p++) {
        int idx = tid + p * 256;
        int tr = idx >> 4, c4 = (idx & 15) << 2;
        float4 vv = *(const float4*)&v[(size_t)(b * KK + t0 + tr) * D_MODEL + h * D_HEADc + c4];
        ts[c4 + 0][tr] = vv.x; ts[c4 + 1][tr] = vv.y;
        ts[c4 + 2][tr] = vv.z; ts[c4 + 3][tr] = vv.w;
    }
    __syncthreads();
#pragma unroll
    for (int p = 0; p < 4; p++) {
        int idx = tid + p * 256;
        int d = idx >> 4, c4 = (idx & 15) << 2;
        float4 w4 = make_float4(ts[d][c4], ts[d][c4 + 1], ts[d][c4 + 2], ts[d][c4 + 3]);
        *(float4*)&vt[((size_t)((b * N_HEADc + h) * D_HEADc + d)) * KK + t0 + c4] = w4;
    }
}

// ---------------- packed-operand tf32 GEMM: 128x128 tile, 32-deep K stages ----------------
// A and B both pre-packed in mma-fragment order, pre-rounded tf32:
//   A-frag = 1 LDS.128, B-frag = 1 LDS.64, zero in-loop cvt.
// EPI: 0 = +bias ; 1 = gelu(+bias) ; 2 = +bias +res ; 3 = plain
#define TG2_AS 4096                    // floats per A stage (16KB)
#define TG2_BS 4096                    // floats per B stage (16KB)
#define TG2_STG (TG2_AS + TG2_BS)
#define TG2_SMEM (3 * TG2_STG * 4)     // 98,304 B

template <int EPI>
__global__ void __launch_bounds__(256, 2)
tgemm(const float* __restrict__ Ap, const float* __restrict__ Wp,
      const float* __restrict__ bias, const float* __restrict__ res,
      float* __restrict__ C, int Ndim, int Kdim) {
    extern __shared__ float smx[];
    const int tid = threadIdx.x, wid = tid >> 5, lane = tid & 31;
    const int bm = blockIdx.y * 128, bn = blockIdx.x * 128;
    const int wmg = (wid >> 2) * 4, wn = (wid & 3) * 32;
    const int KT = Kdim / 32;
    const int kgdim = Kdim >> 3;
    const int mg0 = bm >> 4;

    float acc[4][4][4];
#pragma unroll
    for (int mi = 0; mi < 4; mi++)
#pragma unroll
        for (int nj = 0; nj < 4; nj++)
#pragma unroll
            for (int e = 0; e < 4; e++) acc[mi][nj][e] = 0.f;

    auto issue = [&](int kt) {
        int s = kt % 3;
        float* As = smx + s * TG2_STG;
        float* Bs = As + TG2_AS;
        int kg0 = kt * 4;
        // A: 32 cells (8 mgl x 4 kgl) x 32 lanes x 16B
#pragma unroll
        for (int p = 0; p < 4; p++) {
            int c = tid + p * 256;
            size_t fidx = ((size_t)((mg0 + (c >> 7)) * kgdim + kg0 + ((c >> 5) & 3)) * 32
                           + (c & 31)) * 4;
            cp16(&As[c * 4], &Ap[fidx]);
        }
        // B: 4 kgl x 128 n cells x 32B (2 chunks each)
#pragma unroll
        for (int p = 0; p < 4; p++) {
            int c = tid + p * 256;
            int kgl = c >> 8, rest = c & 255;
            size_t fidx = ((size_t)((kg0 + kgl) * Ndim + bn + (rest >> 1))) * 8 + (rest & 1) * 4;
            cp16(&Bs[c * 4], &Wp[fidx]);
        }
        asm volatile("cp.async.commit_group;");
    };

    auto compute = [&](int s) {
        const float* As = smx + s * TG2_STG;
        const float* Bs = As + TG2_AS;
#pragma unroll
        for (int sub = 0; sub < 4; sub++) {
            uint4 af[4];
            float2 bfv[4];
#pragma unroll
            for (int mi = 0; mi < 4; mi++)
                af[mi] = *(const uint4*)&As[(((wmg + mi) * 4 + sub) * 32 + lane) * 4];
#pragma unroll
            for (int nj = 0; nj < 4; nj++)
                bfv[nj] = *(const float2*)&Bs[((size_t)(sub * 128 + wn + nj * 8 + (lane >> 2))) * 8
                                              + (lane & 3) * 2];
#pragma unroll
            for (int mi = 0; mi < 4; mi++)
#pragma unroll
                for (int nj = 0; nj < 4; nj++)
                    mma_tf32(acc[mi][nj], af[mi].x, af[mi].y, af[mi].z, af[mi].w,
                             __float_as_uint(bfv[nj].x), __float_as_uint(bfv[nj].y));
        }
    };

    issue(0);
    issue(1);
    for (int kt = 0; kt < KT; kt++) {
        if (kt == KT - 1) asm volatile("cp.async.wait_group 0;");
        else              asm volatile("cp.async.wait_group 1;");
        __syncthreads();
        if (kt + 2 < KT) issue(kt + 2);
        compute(kt % 3);
        __syncthreads();
    }

#pragma unroll
    for (int mi = 0; mi < 4; mi++) {
#pragma unroll
        for (int nj = 0; nj < 4; nj++) {
            int row = bm + (wmg + mi) * 16 + (lane >> 2);
            int col = bn + wn + nj * 8 + (lane & 3) * 2;
#pragma unroll
            for (int half = 0; half < 2; half++) {
                int r = row + half * 8;
                float v0 = acc[mi][nj][half * 2 + 0];
                float v1 = acc[mi][nj][half * 2 + 1];
                if (EPI != 3) { v0 += bias[col]; v1 += bias[col + 1]; }
                if (EPI == 1) { v0 = gelu_f(v0); v1 = gelu_f(v1); }
                if (EPI == 2) {
                    v0 += res[(size_t)r * Ndim + col];
                    v1 += res[(size_t)r * Ndim + col + 1];
                }
                float2 w = make_float2(v0, v1);
                *(float2*)&C[(size_t)r * Ndim + col] = w;
            }
        }
    }
}

// ---------------- tensor-core flash attention with XL relative term ----------------
#define FP_KP 0
#define FP_RP (FP_KP + 64*72)
#define FP_VP (FP_RP + 64*72)
#define FP_GS (FP_VP + 64*72)          // 128 x 264
#define FP_PS (FP_GS + 128*264)        // 128 x 72
#define FP_SMEM ((FP_PS + 128*72) * 4) // 227,328 B

__global__ void __launch_bounds__(256, 1)
flash_xl_tc(const float* __restrict__ qg, const float* __restrict__ kg,
            const float* __restrict__ vtg, const float* __restrict__ rg,
            const float* __restrict__ ug, const float* __restrict__ vpg,
            const int* __restrict__ iscp, float* __restrict__ outg) {
    extern __shared__ float sm[];
    float* KP = sm + FP_KP;
    float* RP = sm + FP_RP;
    float* VP = sm + FP_VP;
    float* Gs = sm + FP_GS;
    float* Ps = sm + FP_PS;

    const int tid = threadIdx.x, lane = tid & 31, w = tid >> 5;
    const int i0 = blockIdx.x * 128, h = blockIdx.y, b = blockIdx.z;
    const int causal = iscp[0];
    const int r0 = w * 16 + (lane >> 2);
    const int kc = lane & 3;
    const int base0 = Tt - 128 - i0;

    {
        const float* qbase = qg + ((size_t)(b * Tt + i0)) * D_MODEL + h * D_HEADc;
#pragma unroll
        for (int p = 0; p < 8; p++) {
            int idx = tid + p * 256;
            int rl = idx >> 4, c4 = (idx & 15) << 2;
            *(float4*)&Ps[rl * 72 + c4] = *(const float4*)&qbase[(size_t)rl * D_MODEL + c4];
        }
    }
    __syncthreads();

    uint32_t aQu[8][4], aQv[8][4];
#pragma unroll
    for (int kk = 0; kk < 8; kk++) {
        int d0 = kk * 8 + kc, d1 = d0 + 4;
        float u0 = __ldg(&ug[h * D_HEADc + d0]),  u1 = __ldg(&ug[h * D_HEADc + d1]);
        float v0 = __ldg(&vpg[h * D_HEADc + d0]), v1 = __ldg(&vpg[h * D_HEADc + d1]);
        float q00 = Ps[r0 * 72 + d0],       q10 = Ps[(r0 + 8) * 72 + d0];
        float q01 = Ps[r0 * 72 + d1],       q11 = Ps[(r0 + 8) * 72 + d1];
        aQu[kk][0] = f2tf32(q00 + u0); aQu[kk][1] = f2tf32(q10 + u0);
        aQu[kk][2] = f2tf32(q01 + u1); aQu[kk][3] = f2tf32(q11 + u1);
        aQv[kk][0] = f2tf32(q00 + v0); aQv[kk][1] = f2tf32(q10 + v0);
        aQv[kk][2] = f2tf32(q01 + v1); aQv[kk][3] = f2tf32(q11 + v1);
    }
    __syncthreads();

#pragma unroll
    for (int hh = 0; hh < 2; hh++) {
        int rb = base0 + hh * 64;
#pragma unroll
        for (int p = 0; p < 4; p++) {
            int idx = tid + p * 256;
            int mr = idx >> 4, c4 = (idx & 15) << 2;
            int gr = rb + mr; if (gr > KK - 1) gr = KK - 1; if (gr < 0) gr = 0;
            float4 rv = *(const float4*)&rg[(size_t)gr * D_MODEL + h * D_HEADc + c4];
            int fb = mr * 72 + (c4 >> 3) * 8 + ((c4 >> 2) & 1);
            RP[fb + 0] = tf32r(rv.x); RP[fb + 2] = tf32r(rv.y);
            RP[fb + 4] = tf32r(rv.z); RP[fb + 6] = tf32r(rv.w);
        }
        __syncthreads();
#pragma unroll
        for (int nf = 0; nf < 8; nf++) {
            float gc[4] = {0.f, 0.f, 0.f, 0.f};
            int n0 = nf * 8 + (lane >> 2);
#pragma unroll
            for (int kk = 0; kk < 8; kk++) {
                float2 rv = *(const float2*)&RP[n0 * 72 + kk * 8 + kc * 2];
                mma_tf32(gc, aQv[kk][0], aQv[kk][1], aQv[kk][2], aQv[kk][3],
                         __float_as_uint(rv.x), __float_as_uint(rv.y));
            }
            int col = hh * 64 + nf * 8 + kc * 2;
            *(float2*)&Gs[r0 * 264 + col]       = make_float2(gc[0], gc[1]);
            *(float2*)&Gs[(r0 + 8) * 264 + col] = make_float2(gc[2], gc[3]);
        }
        __syncthreads();
    }

    float mi0 = -1e30f, mi1 = -1e30f, li0 = 0.f, li1 = 0.f;
    float oc[8][4];
#pragma unroll
    for (int nf = 0; nf < 8; nf++)
#pragma unroll
        for (int e = 0; e < 4; e++) oc[nf][e] = 0.f;

    const int njt = causal ? (i0 / 64 + 34) : (KK / 64);
    const float scale = 0.125f;
    const size_t vrowbase = (size_t)((b * N_HEADc + h) * D_HEADc) * KK;

    for (int jt = 0; jt < njt; jt++) {
        const int j0 = jt * 64;
        __syncthreads();

        {
            const float* kb = kg + ((size_t)(b * KK + j0)) * D_MODEL + h * D_HEADc;
#pragma unroll
            for (int p = 0; p < 4; p++) {
                int idx = tid + p * 256;
                int j = idx >> 4, c4 = (idx & 15) << 2;
                float4 kv = *(const float4*)&kb[(size_t)j * D_MODEL + c4];
                int fb = j * 72 + (c4 >> 3) * 8 + ((c4 >> 2) & 1);
                KP[fb + 0] = tf32r(kv.x); KP[fb + 2] = tf32r(kv.y);
                KP[fb + 4] = tf32r(kv.z); KP[fb + 6] = tf32r(kv.w);
            }
#pragma unroll
            for (int p = 0; p < 4; p++) {
                int idx = tid + p * 256;
                int d = idx >> 4, c4 = (idx & 15) << 2;
                float4 vv4 = *(const float4*)&vtg[vrowbase + (size_t)d * KK + j0 + c4];
                int fb = d * 72 + (c4 >> 3) * 8 + ((c4 >> 2) & 1);
                VP[fb + 0] = tf32r(vv4.x); VP[fb + 2] = tf32r(vv4.y);
                VP[fb + 4] = tf32r(vv4.z); VP[fb + 6] = tf32r(vv4.w);
            }
            int rb = base0 + j0 + 128;
#pragma unroll
            for (int p = 0; p < 4; p++) {
                int idx = tid + p * 256;
                int mr = idx >> 4, c4 = (idx & 15) << 2;
                int gr = rb + mr; if (gr > KK - 1) gr = KK - 1;
                float4 rv = *(const float4*)&rg[(size_t)gr * D_MODEL + h * D_HEADc + c4];
                int fb = mr * 72 + (c4 >> 3) * 8 + ((c4 >> 2) & 1);
                RP[fb + 0] = tf32r(rv.x); RP[fb + 2] = tf32r(rv.y);
                RP[fb + 4] = tf32r(rv.z); RP[fb + 6] = tf32r(rv.w);
            }
        }
        __syncthreads();

        {
            int gbase = ((jt + 2) & 3) * 64;
#pragma unroll
            for (int nf = 0; nf < 8; nf++) {
                float gc[4] = {0.f, 0.f, 0.f, 0.f};
                int n0 = nf * 8 + (lane >> 2);
#pragma unroll
                for (int kk = 0; kk < 8; kk++) {
                    float2 rv = *(const float2*)&RP[n0 * 72 + kk * 8 + kc * 2];
                    mma_tf32(gc, aQv[kk][0], aQv[kk][1], aQv[kk][2], aQv[kk][3],
                             __float_as_uint(rv.x), __float_as_uint(rv.y));
                }
                int col = gbase + nf * 8 + kc * 2;
                *(float2*)&Gs[r0 * 264 + col]       = make_float2(gc[0], gc[1]);
                *(float2*)&Gs[(r0 + 8) * 264 + col] = make_float2(gc[2], gc[3]);
            }
        }
        __syncwarp();

        float sc[8][4];
#pragma unroll
        for (int nf = 0; nf < 8; nf++) {
            sc[nf][0] = sc[nf][1] = sc[nf][2] = sc[nf][3] = 0.f;
            int n0 = nf * 8 + (lane >> 2);
#pragma unroll
            for (int kk = 0; kk < 8; kk++) {
                float2 kv = *(const float2*)&KP[n0 * 72 + kk * 8 + kc * 2];
                mma_tf32(sc[nf], aQu[kk][0], aQu[kk][1], aQu[kk][2], aQu[kk][3],
                         __float_as_uint(kv.x), __float_as_uint(kv.y));
            }
        }

        const int jtb = (jt * 64) & 255;
#pragma unroll
        for (int nf = 0; nf < 8; nf++) {
#pragma unroll
            for (int e = 0; e < 4; e++) {
                int rl = r0 + ((e >= 2) ? 8 : 0);
                int jl = nf * 8 + kc * 2 + (e & 1);
                int ridx = (jtb + jl + 127 - rl) & 255;
                float val = (sc[nf][e] + Gs[rl * 264 + ridx]) * scale;
                if (causal && (j0 + jl) > (i0 + rl + Mm)) val = -1e30f;
                sc[nf][e] = val;
            }
        }

        float rm0 = -1e30f, rm1 = -1e30f;
#pragma unroll
        for (int nf = 0; nf < 8; nf++) {
            rm0 = fmaxf(rm0, fmaxf(sc[nf][0], sc[nf][1]));
            rm1 = fmaxf(rm1, fmaxf(sc[nf][2], sc[nf][3]));
        }
        rm0 = fmaxf(rm0, __shfl_xor_sync(0xffffffffu, rm0, 1));
        rm0 = fmaxf(rm0, __shfl_xor_sync(0xffffffffu, rm0, 2));
        rm1 = fmaxf(rm1, __shfl_xor_sync(0xffffffffu, rm1, 1));
        rm1 = fmaxf(rm1, __shfl_xor_sync(0xffffffffu, rm1, 2));
        float mn0 = fmaxf(mi0, rm0), mn1 = fmaxf(mi1, rm1);
        float corr0 = __expf(mi0 - mn0), corr1 = __expf(mi1 - mn1);
        float sum0 = 0.f, sum1 = 0.f;
#pragma unroll
        for (int nf = 0; nf < 8; nf++) {
            float p0 = __expf(sc[nf][0] - mn0);
            float p1 = __expf(sc[nf][1] - mn0);
            float p2 = __expf(sc[nf][2] - mn1);
            float p3 = __expf(sc[nf][3] - mn1);
            sc[nf][0] = p0; sc[nf][1] = p1; sc[nf][2] = p2; sc[nf][3] = p3;
            sum0 += p0 + p1; sum1 += p2 + p3;
        }
        sum0 += __shfl_xor_sync(0xffffffffu, sum0, 1);
        sum0 += __shfl_xor_sync(0xffffffffu, sum0, 2);
        sum1 += __shfl_xor_sync(0xffffffffu, sum1, 1);
        sum1 += __shfl_xor_sync(0xffffffffu, sum1, 2);
        li0 = li0 * corr0 + sum0; li1 = li1 * corr1 + sum1;
        mi0 = mn0; mi1 = mn1;
#pragma unroll
        for (int nf = 0; nf < 8; nf++) {
            oc[nf][0] *= corr0; oc[nf][1] *= corr0;
            oc[nf][2] *= corr1; oc[nf][3] *= corr1;
        }

#pragma unroll
        for (int nf = 0; nf < 8; nf++) {
            int col = nf * 8 + kc * 2;
            *(float2*)&Ps[r0 * 72 + col]       = make_float2(sc[nf][0], sc[nf][1]);
            *(float2*)&Ps[(r0 + 8) * 72 + col] = make_float2(sc[nf][2], sc[nf][3]);
        }
        __syncwarp();
        uint32_t pa[8][4];
#pragma unroll
        for (int kk = 0; kk < 8; kk++) {
            int d0 = kk * 8 + kc, d1 = d0 + 4;
            pa[kk][0] = f2tf32(Ps[r0 * 72 + d0]);
            pa[kk][1] = f2tf32(Ps[(r0 + 8) * 72 + d0]);
            pa[kk][2] = f2tf32(Ps[r0 * 72 + d1]);
            pa[kk][3] = f2tf32(Ps[(r0 + 8) * 72 + d1]);
        }
#pragma unroll
        for (int nf = 0; nf < 8; nf++) {
            int n0 = nf * 8 + (lane >> 2);
#pragma unroll
            for (int kk = 0; kk < 8; kk++) {
                float2 vv = *(const float2*)&VP[n0 * 72 + kk * 8 + kc * 2];
                mma_tf32(oc[nf], pa[kk][0], pa[kk][1], pa[kk][2], pa[kk][3],
                         __float_as_uint(vv.x), __float_as_uint(vv.y));
            }
        }
    }

    float inv0 = 1.f / li0, inv1 = 1.f / li1;
    float* ob0 = outg + ((size_t)(b * Tt + i0 + r0)) * D_MODEL + h * D_HEADc;
    float* ob1 = outg + ((size_t)(b * Tt + i0 + r0 + 8)) * D_MODEL + h * D_HEADc;
#pragma unroll
    for (int nf = 0; nf < 8; nf++) {
        int col = nf * 8 + kc * 2;
        *(float2*)&ob0[col] = make_float2(oc[nf][0] * inv0, oc[nf][1] * inv0);
        *(float2*)&ob1[col] = make_float2(oc[nf][2] * inv1, oc[nf][3] * inv1);
    }
}

// ---------------- LayerNorm over last dim (D=1024), one block per row ----------------
__global__ void __launch_bounds__(256)
layernorm_k(const float* __restrict__ in, const float* __restrict__ g,
            const float* __restrict__ be, float* __restrict__ out) {
    __shared__ float red[34];
    const int row = blockIdx.x;
    const int tid = threadIdx.x;
    float4 v = ((const float4*)(in + (size_t)row * D_MODEL))[tid];

    float s = v.x + v.y + v.z + v.w;
    int lane = tid & 31, wid = tid >> 5;
#pragma unroll
    for (int off = 16; off >= 1; off >>= 1) s += __shfl_xor_sync(0xffffffffu, s, off);
    if (lane == 0) red[wid] = s;
    __syncthreads();
    if (tid == 0) {
        float t = 0.f;
#pragma unroll
        for (int w2 = 0; w2 < 8; w2++) t += red[w2];
        red[32] = t;
    }
    __syncthreads();
    float mu = red[32] * (1.f / (float)D_MODEL);

    float dx0 = v.x - mu, dx1 = v.y - mu, dx2 = v.z - mu, dx3 = v.w - mu;
    float sq = dx0 * dx0 + dx1 * dx1 + dx2 * dx2 + dx3 * dx3;
#pragma unroll
    for (int off = 16; off >= 1; off >>= 1) sq += __shfl_xor_sync(0xffffffffu, sq, off);
    if (lane == 0) red[wid] = sq;
    __syncthreads();
    if (tid == 0) {
        float t = 0.f;
#pragma unroll
        for (int w2 = 0; w2 < 8; w2++) t += red[w2];
        red[33] = t;
    }
    __syncthreads();
    float rstd = rsqrtf(red[33] * (1.f / (float)D_MODEL) + 1e-5f);

    float4 gv = ((const float4*)g)[tid];
    float4 bv = ((const float4*)be)[tid];
    float4 o;
    o.x = dx0 * rstd * gv.x + bv.x;
    o.y = dx1 * rstd * gv.y + bv.y;
    o.z = dx2 * rstd * gv.z + bv.z;
    o.w = dx3 * rstd * gv.w + bv.w;
    ((float4*)(out + (size_t)row * D_MODEL))[tid] = o;
}

// ---------------- launch ----------------
extern "C" void kernel_launch(void* const* d_in, const int* in_sizes, int n_in,
                              void* d_out, int out_size) {
    const float* x    = (const float*)d_in[0];
    const float* mem  = (const float*)d_in[1];
    const float* Wq   = (const float*)d_in[2];
    const float* bq   = (const float*)d_in[3];
    const float* Wk   = (const float*)d_in[4];
    const float* bk   = (const float*)d_in[5];
    const float* Wv   = (const float*)d_in[6];
    const float* bv   = (const float*)d_in[7];
    const float* Wo   = (const float*)d_in[8];
    const float* bo   = (const float*)d_in[9];
    const float* Wr   = (const float*)d_in[10];
    const float* u    = (const float*)d_in[11];
    const float* vpar = (const float*)d_in[12];
    const float* g1   = (const float*)d_in[13];
    const float* be1  = (const float*)d_in[14];
    const float* g2   = (const float*)d_in[15];
    const float* be2  = (const float*)d_in[16];
    const float* W1   = (const float*)d_in[17];
    const float* b1   = (const float*)d_in[18];
    const float* W2   = (const float*)d_in[19];
    const float* b2   = (const float*)d_in[20];
    const int*   isc  = (const int*)d_in[21];
    float* out = (float*)d_out;

    float *P, *r, *q, *c, *k, *vv, *vt, *attn, *s, *h, *f1, *invf;
    float *xp, *cp, *ap, *hp, *f1p;
    float *wqp, *wkp, *wvp, *wrp, *wop, *w1p, *w2p;
    cudaGetSymbolAddress((void**)&P,    g_P);
    cudaGetSymbolAddress((void**)&r,    g_r);
    cudaGetSymbolAddress((void**)&q,    g_q);
    cudaGetSymbolAddress((void**)&c,    g_c);
    cudaGetSymbolAddress((void**)&k,    g_k);
    cudaGetSymbolAddress((void**)&vv,   g_v);
    cudaGetSymbolAddress((void**)&vt,   g_vt);
    cudaGetSymbolAddress((void**)&attn, g_attn);
    cudaGetSymbolAddress((void**)&s,    g_s);
    cudaGetSymbolAddress((void**)&h,    g_h);
    cudaGetSymbolAddress((void**)&f1,   g_f1);
    cudaGetSymbolAddress((void**)&invf, g_invf);
    cudaGetSymbolAddress((void**)&xp,   g_xp);
    cudaGetSymbolAddress((void**)&cp,   g_cp);
    cudaGetSymbolAddress((void**)&ap,   g_ap);
    cudaGetSymbolAddress((void**)&hp,   g_hp);
    cudaGetSymbolAddress((void**)&f1p,  g_f1p);
    cudaGetSymbolAddress((void**)&wqp,  g_wqp);
    cudaGetSymbolAddress((void**)&wkp,  g_wkp);
    cudaGetSymbolAddress((void**)&wvp,  g_wvp);
    cudaGetSymbolAddress((void**)&wrp,  g_wrp);
    cudaGetSymbolAddress((void**)&wop,  g_wop);
    cudaGetSymbolAddress((void**)&w1p,  g_w1p);
    cudaGetSymbolAddress((void**)&w2p,  g_w2p);

    cudaFuncSetAttribute(tgemm<0>, cudaFuncAttributeMaxDynamicSharedMemorySize, TG2_SMEM);
    cudaFuncSetAttribute(tgemm<1>, cudaFuncAttributeMaxDynamicSharedMemorySize, TG2_SMEM);
    cudaFuncSetAttribute(tgemm<2>, cudaFuncAttributeMaxDynamicSharedMemorySize, TG2_SMEM);
    cudaFuncSetAttribute(tgemm<3>, cudaFuncAttributeMaxDynamicSharedMemorySize, TG2_SMEM);
    cudaFuncSetAttribute(flash_xl_tc, cudaFuncAttributeMaxDynamicSharedMemorySize, FP_SMEM);

    const int TPB = 256;
    // tables + concat
    fill_invf<<<1, 512>>>(invf);
    fill_pos_packed<<<(KK * D_MODEL + TPB - 1) / TPB, TPB>>>(P, invf);
    concat_kernel<<<(ROWS_C * (D_MODEL / 4) + TPB - 1) / TPB, TPB>>>(x, mem, c);

    // pack weights (every launch; ~52MB total, cheap)
    pack_w<<<((D_MODEL / 8) * D_MODEL + TPB - 1) / TPB, TPB>>>(Wq, wqp, D_MODEL, D_MODEL);
    pack_w<<<((D_MODEL / 8) * D_MODEL + TPB - 1) / TPB, TPB>>>(Wk, wkp, D_MODEL, D_MODEL);
    pack_w<<<((D_MODEL / 8) * D_MODEL + TPB - 1) / TPB, TPB>>>(Wv, wvp, D_MODEL, D_MODEL);
    pack_w<<<((D_MODEL / 8) * D_MODEL + TPB - 1) / TPB, TPB>>>(Wr, wrp, D_MODEL, D_MODEL);
    pack_w<<<((D_MODEL / 8) * D_MODEL + TPB - 1) / TPB, TPB>>>(Wo, wop, D_MODEL, D_MODEL);
    pack_w<<<((D_MODEL / 8) * FFN_H + TPB - 1) / TPB, TPB>>>(W1, w1p, FFN_H, D_MODEL);
    pack_w<<<((FFN_H / 8) * D_MODEL + TPB - 1) / TPB, TPB>>>(W2, w2p, D_MODEL, FFN_H);

    // pack activations for projections
    pack_a<<<((ROWS_X / 16) * (D_MODEL / 8) * 32 + TPB - 1) / TPB, TPB>>>(x, xp, ROWS_X, D_MODEL);
    pack_a<<<((ROWS_C / 16) * (D_MODEL / 8) * 32 + TPB - 1) / TPB, TPB>>>(c, cp, ROWS_C, D_MODEL);

    // projections (packed-operand tf32 tensor cores)
    tgemm<0><<<dim3(D_MODEL / 128, ROWS_X / 128), 256, TG2_SMEM>>>(xp, wqp, bq, nullptr, q, D_MODEL, D_MODEL);
    tgemm<0><<<dim3(D_MODEL / 128, ROWS_C / 128), 256, TG2_SMEM>>>(cp, wkp, bk, nullptr, k, D_MODEL, D_MODEL);
    tgemm<0><<<dim3(D_MODEL / 128, ROWS_C / 128), 256, TG2_SMEM>>>(cp, wvp, bv, nullptr, vv, D_MODEL, D_MODEL);
    tgemm<3><<<dim3(D_MODEL / 128, KK / 128), 256, TG2_SMEM>>>(P, wrp, nullptr, nullptr, r, D_MODEL, D_MODEL);
    transpose_v<<<dim3(KK / 64, N_HEADc, Bb), 256>>>(vv, vt);

    // attention (tensor-core flash, fragment-packed smem operands)
    flash_xl_tc<<<dim3(Tt / 128, N_HEADc, Bb), 256, FP_SMEM>>>(q, k, vt, r, u, vpar, isc, attn);

    // o-proj + residual, LN1
    pack_a<<<((ROWS_X / 16) * (D_MODEL / 8) * 32 + TPB - 1) / TPB, TPB>>>(attn, ap, ROWS_X, D_MODEL);
    tgemm<2><<<dim3(D_MODEL / 128, ROWS_X / 128), 256, TG2_SMEM>>>(ap, wop, bo, x, s, D_MODEL, D_MODEL);
    layernorm_k<<<ROWS_X, 256>>>(s, g1, be1, h);

    // FFN
    pack_a<<<((ROWS_X / 16) * (D_MODEL / 8) * 32 + TPB - 1) / TPB, TPB>>>(h, hp, ROWS_X, D_MODEL);
    tgemm<1><<<dim3(FFN_H / 128, ROWS_X / 128), 256, TG2_SMEM>>>(hp, w1p, b1, nullptr, f1, FFN_H, D_MODEL);
    pack_a<<<((ROWS_X / 16) * (FFN_H / 8) * 32 + TPB - 1) / TPB, TPB>>>(f1, f1p, ROWS_X, FFN_H);
    tgemm<2><<<dim3(D_MODEL / 128, ROWS_X / 128), 256, TG2_SMEM>>>(f1p, w2p, b2, h, s, D_MODEL, FFN_H);
    layernorm_k<<<ROWS_X, 256>>>(s, g2, be2, out);
}

// round 12
// speedup vs baseline: 5.4117x; 1.0803x over previous
#include <cuda_runtime.h>
#include <math.h>
#include <stdint.h>

// ---------------- problem constants ----------------
#define D_MODEL 1024
#define N_HEADc 16
#define D_HEADc 64
#define FFN_H   4096
#define Bb      4
#define Tt      2048
#define Mm      2048
#define KK      4096            // M + T
#define ROWS_X  (Bb*Tt)         // 8192
#define ROWS_C  (Bb*KK)         // 16384

// ---------------- scratch (static device memory; no runtime alloc) ----------------
static __device__ float g_P   [(size_t)KK*D_MODEL];        // packed-A layout
static __device__ float g_r   [(size_t)KK*D_MODEL];
static __device__ float g_q   [(size_t)ROWS_X*D_MODEL];
static __device__ float g_c   [(size_t)ROWS_C*D_MODEL];
static __device__ float g_k   [(size_t)ROWS_C*D_MODEL];
static __device__ float g_v   [(size_t)ROWS_C*D_MODEL];
static __device__ float g_attn[(size_t)ROWS_X*D_MODEL];
static __device__ float g_s   [(size_t)ROWS_X*D_MODEL];
static __device__ float g_h   [(size_t)ROWS_X*D_MODEL];
static __device__ float g_f1  [(size_t)ROWS_X*FFN_H];
static __device__ float g_invf[512];
// packed-A activation copies
static __device__ float g_xp  [(size_t)ROWS_X*D_MODEL];
static __device__ float g_cp  [(size_t)ROWS_C*D_MODEL];
static __device__ float g_ap  [(size_t)ROWS_X*D_MODEL];
static __device__ float g_hp  [(size_t)ROWS_X*D_MODEL];
static __device__ float g_f1p [(size_t)ROWS_X*FFN_H];
// packed weights
static __device__ float g_wqp[(size_t)D_MODEL*D_MODEL];
static __device__ float g_wkp[(size_t)D_MODEL*D_MODEL];
static __device__ float g_wvp[(size_t)D_MODEL*D_MODEL];
static __device__ float g_wrp[(size_t)D_MODEL*D_MODEL];
static __device__ float g_wop[(size_t)D_MODEL*D_MODEL];
static __device__ float g_w1p[(size_t)D_MODEL*FFN_H];
static __device__ float g_w2p[(size_t)FFN_H*D_MODEL];
// fragment-packed flash operands (tf32 pre-rounded)
static __device__ float g_kp [(size_t)Bb*N_HEADc*KK*D_HEADc];   // [(b,h)][j][64]  pairs along d
static __device__ float g_vp [(size_t)Bb*N_HEADc*KK*D_HEADc];   // [(b,h)][jt][d][64] pairs along key
static __device__ float g_rp [(size_t)N_HEADc*KK*D_HEADc];      // [h][row][64]   pairs along d

// ---------------- helpers ----------------
__device__ __forceinline__ float gelu_f(float x) {
    float x3 = x * x * x;
    float t  = tanhf(0.7978845608028654f * (x + 0.044715f * x3));
    return 0.5f * x * (1.0f + t);
}

__device__ __forceinline__ uint32_t f2tf32(float x) {
    uint32_t r;
    asm("cvt.rna.tf32.f32 %0, %1;" : "=r"(r) : "f"(x));
    return r;
}
__device__ __forceinline__ float tf32r(float x) {
    return __uint_as_float(f2tf32(x));
}

__device__ __forceinline__ void mma_tf32(float c[4], uint32_t a0, uint32_t a1,
                                         uint32_t a2, uint32_t a3,
                                         uint32_t b0, uint32_t b1) {
    asm volatile(
        "mma.sync.aligned.m16n8k8.row.col.f32.tf32.tf32.f32 "
        "{%0,%1,%2,%3},{%4,%5,%6,%7},{%8,%9},{%0,%1,%2,%3};"
        : "+f"(c[0]), "+f"(c[1]), "+f"(c[2]), "+f"(c[3])
        : "r"(a0), "r"(a1), "r"(a2), "r"(a3), "r"(b0), "r"(b1));
}

__device__ __forceinline__ void cp16(void* smem, const void* g) {
    uint32_t s = (uint32_t)__cvta_generic_to_shared(smem);
    asm volatile("cp.async.cg.shared.global [%0], [%1], 16;" :: "r"(s), "l"(g));
}

// ---------------- operand pack kernels (GEMM) ----------------
__global__ void __launch_bounds__(256)
pack_a(const float* __restrict__ A, float* __restrict__ Ap, int Mdim, int Kdim) {
    int t = blockIdx.x * blockDim.x + threadIdx.x;
    int kgdim = Kdim >> 3;
    int total = (Mdim >> 4) * kgdim * 32;
    if (t >= total) return;
    int lane = t & 31, cell = t >> 5;
    int mg = cell / kgdim, kg = cell - mg * kgdim;
    int m0 = mg * 16 + (lane >> 2);
    int k0 = kg * 8 + (lane & 3);
    float4 v;
    v.x = tf32r(A[(size_t)m0 * Kdim + k0]);
    v.y = tf32r(A[(size_t)(m0 + 8) * Kdim + k0]);
    v.z = tf32r(A[(size_t)m0 * Kdim + k0 + 4]);
    v.w = tf32r(A[(size_t)(m0 + 8) * Kdim + k0 + 4]);
    *(float4*)&Ap[(size_t)t * 4] = v;
}

__global__ void __launch_bounds__(256)
pack_w(const float* __restrict__ W, float* __restrict__ Wp, int Ndim, int Kdim) {
    int t = blockIdx.x * blockDim.x + threadIdx.x;
    int total = (Kdim >> 3) * Ndim;
    if (t >= total) return;
    int kg = t / Ndim, n = t - kg * Ndim;
    float p0a = tf32r(W[(size_t)(kg * 8 + 0) * Ndim + n]);
    float p0b = tf32r(W[(size_t)(kg * 8 + 4) * Ndim + n]);
    float p1a = tf32r(W[(size_t)(kg * 8 + 1) * Ndim + n]);
    float p1b = tf32r(W[(size_t)(kg * 8 + 5) * Ndim + n]);
    float p2a = tf32r(W[(size_t)(kg * 8 + 2) * Ndim + n]);
    float p2b = tf32r(W[(size_t)(kg * 8 + 6) * Ndim + n]);
    float p3a = tf32r(W[(size_t)(kg * 8 + 3) * Ndim + n]);
    float p3b = tf32r(W[(size_t)(kg * 8 + 7) * Ndim + n]);
    float* dst = Wp + (size_t)t * 8;
    *(float4*)dst       = make_float4(p0a, p0b, p1a, p1b);
    *(float4*)(dst + 4) = make_float4(p2a, p2b, p3a, p3b);
}

// ---------------- flash operand pack kernels ----------------
// K: per (b,h,row j, kg cell): 8 floats = pairs {K[.][kg*8+kc], K[.][kg*8+kc+4]}, tf32
__global__ void __launch_bounds__(256)
pack_kp(const float* __restrict__ K, float* __restrict__ Kp) {
    int t = blockIdx.x * blockDim.x + threadIdx.x;   // 64*4096*8
    int kg = t & 7, j = (t >> 3) & (KK - 1), bh = t >> 15;
    int b = bh >> 4, h = bh & 15;
    const float* src = K + ((size_t)(b * KK + j)) * D_MODEL + h * D_HEADc + kg * 8;
    float* dst = Kp + ((size_t)bh * KK + j) * 64 + kg * 8;
    *(float4*)dst       = make_float4(tf32r(src[0]), tf32r(src[4]), tf32r(src[1]), tf32r(src[5]));
    *(float4*)(dst + 4) = make_float4(tf32r(src[2]), tf32r(src[6]), tf32r(src[3]), tf32r(src[7]));
}

// R: per (h,row,kg): same pairing along d
__global__ void __launch_bounds__(256)
pack_rp(const float* __restrict__ R, float* __restrict__ Rp) {
    int t = blockIdx.x * blockDim.x + threadIdx.x;   // 16*4096*8
    int kg = t & 7, row = (t >> 3) & (KK - 1), h = t >> 15;
    const float* src = R + (size_t)row * D_MODEL + h * D_HEADc + kg * 8;
    float* dst = Rp + ((size_t)h * KK + row) * 64 + kg * 8;
    *(float4*)dst       = make_float4(tf32r(src[0]), tf32r(src[4]), tf32r(src[1]), tf32r(src[5]));
    *(float4*)(dst + 4) = make_float4(tf32r(src[2]), tf32r(src[6]), tf32r(src[3]), tf32r(src[7]));
}

// V: transpose 64-key tile then pack pairs along key axis: out[(b,h)][jt][d][64]
__global__ void __launch_bounds__(256)
pack_vp(const float* __restrict__ v, float* __restrict__ vp) {
    __shared__ float ts[64][65];
    const int tid = threadIdx.x;
    const int jt = blockIdx.x, h = blockIdx.y, b = blockIdx.z;
    const int t0 = jt * 64, bh = b * N_HEADc + h;
#pragma unroll
    for (int p = 0; p < 4; p++) {
        int idx = tid + p * 256;
        int tr = idx >> 4, c4 = (idx & 15) << 2;
        float4 vv = *(const float4*)&v[(size_t)(b * KK + t0 + tr) * D_MODEL + h * D_HEADc + c4];
        ts[c4 + 0][tr] = vv.x; ts[c4 + 1][tr] = vv.y;
        ts[c4 + 2][tr] = vv.z; ts[c4 + 3][tr] = vv.w;
    }
    __syncthreads();
    int d = tid >> 2, g = tid & 3;
    float* dst = vp + (((size_t)bh * 64 + jt) * 64 + d) * 64 + g * 16;
    float buf[16];
#pragma unroll
    for (int sp = 0; sp < 8; sp++) {
        int kk = g * 2 + (sp >> 2), kc = sp & 3;
        buf[sp * 2 + 0] = tf32r(ts[d][kk * 8 + kc]);
        buf[sp * 2 + 1] = tf32r(ts[d][kk * 8 + kc + 4]);
    }
#pragma unroll
    for (int q4 = 0; q4 < 4; q4++)
        *(float4*)(dst + q4 * 4) = *(float4*)(buf + q4 * 4);
}

// ---------------- positional tables ----------------
__global__ void fill_invf(float* __restrict__ invf) {
    int f = threadIdx.x;
    if (f < 512) {
        double v = exp(-((double)(2 * f) / (double)D_MODEL) * log(10000.0));
        invf[f] = (float)v;
    }
}

__global__ void fill_pos_packed(float* __restrict__ P, const float* __restrict__ invf) {
    int idx = blockIdx.x * blockDim.x + threadIdx.x;
    if (idx >= KK * D_MODEL) return;
    int elem = idx & 3, lane = (idx >> 2) & 31, cell = idx >> 7;
    int kg = cell & 127;
    int mg = cell >> 7;
    int m   = mg * 16 + (lane >> 2) + ((elem & 1) << 3);
    int col = kg * 8 + (lane & 3) + ((elem >> 1) << 2);
    float pos = (float)(KK - 1 - m);
    int f = (col < D_MODEL / 2) ? col : col - D_MODEL / 2;
    float ang = pos * __ldg(&invf[f]);
    P[idx] = tf32r((col < D_MODEL / 2) ? sinf(ang) : cosf(ang));
}

// ---------------- concat c = [mem, x] along seq ----------------
__global__ void concat_kernel(const float* __restrict__ x, const float* __restrict__ mem,
                              float* __restrict__ c) {
    int idx = blockIdx.x * blockDim.x + threadIdx.x;
    const int row_f4 = D_MODEL / 4;
    if (idx >= ROWS_C * row_f4) return;
    int row = idx / row_f4;
    int col = idx - row * row_f4;
    int b = row / KK;
    int t = row - b * KK;
    const float4* src;
    if (t < Mm) src = (const float4*)mem + ((size_t)(b * Mm + t)) * row_f4 + col;
    else        src = (const float4*)x   + ((size_t)(b * Tt + (t - Mm))) * row_f4 + col;
    ((float4*)c)[idx] = *src;
}

// ---------------- packed-operand tf32 GEMM ----------------
#define TG2_AS 4096
#define TG2_BS 4096
#define TG2_STG (TG2_AS + TG2_BS)
#define TG2_SMEM (3 * TG2_STG * 4)

template <int EPI>
__global__ void __launch_bounds__(256, 2)
tgemm(const float* __restrict__ Ap, const float* __restrict__ Wp,
      const float* __restrict__ bias, const float* __restrict__ res,
      float* __restrict__ C, int Ndim, int Kdim) {
    extern __shared__ float smx[];
    const int tid = threadIdx.x, wid = tid >> 5, lane = tid & 31;
    const int bm = blockIdx.y * 128, bn = blockIdx.x * 128;
    const int wmg = (wid >> 2) * 4, wn = (wid & 3) * 32;
    const int KT = Kdim / 32;
    const int kgdim = Kdim >> 3;
    const int mg0 = bm >> 4;

    float acc[4][4][4];
#pragma unroll
    for (int mi = 0; mi < 4; mi++)
#pragma unroll
        for (int nj = 0; nj < 4; nj++)
#pragma unroll
            for (int e = 0; e < 4; e++) acc[mi][nj][e] = 0.f;

    auto issue = [&](int kt) {
        int s = kt % 3;
        float* As = smx + s * TG2_STG;
        float* Bs = As + TG2_AS;
        int kg0 = kt * 4;
#pragma unroll
        for (int p = 0; p < 4; p++) {
            int c = tid + p * 256;
            size_t fidx = ((size_t)((mg0 + (c >> 7)) * kgdim + kg0 + ((c >> 5) & 3)) * 32
                           + (c & 31)) * 4;
            cp16(&As[c * 4], &Ap[fidx]);
        }
#pragma unroll
        for (int p = 0; p < 4; p++) {
            int c = tid + p * 256;
            int kgl = c >> 8, rest = c & 255;
            size_t fidx = ((size_t)((kg0 + kgl) * Ndim + bn + (rest >> 1))) * 8 + (rest & 1) * 4;
            cp16(&Bs[c * 4], &Wp[fidx]);
        }
        asm volatile("cp.async.commit_group;");
    };

    auto compute = [&](int s) {
        const float* As = smx + s * TG2_STG;
        const float* Bs = As + TG2_AS;
#pragma unroll
        for (int sub = 0; sub < 4; sub++) {
            uint4 af[4];
            float2 bfv[4];
#pragma unroll
            for (int mi = 0; mi < 4; mi++)
                af[mi] = *(const uint4*)&As[(((wmg + mi) * 4 + sub) * 32 + lane) * 4];
#pragma unroll
            for (int nj = 0; nj < 4; nj++)
                bfv[nj] = *(const float2*)&Bs[((size_t)(sub * 128 + wn + nj * 8 + (lane >> 2))) * 8
                                              + (lane & 3) * 2];
#pragma unroll
            for (int mi = 0; mi < 4; mi++)
#pragma unroll
                for (int nj = 0; nj < 4; nj++)
                    mma_tf32(acc[mi][nj], af[mi].x, af[mi].y, af[mi].z, af[mi].w,
                             __float_as_uint(bfv[nj].x), __float_as_uint(bfv[nj].y));
        }
    };

    issue(0);
    issue(1);
    for (int kt = 0; kt < KT; kt++) {
        if (kt == KT - 1) asm volatile("cp.async.wait_group 0;");
        else              asm volatile("cp.async.wait_group 1;");
        __syncthreads();
        if (kt + 2 < KT) issue(kt + 2);
        compute(kt % 3);
        __syncthreads();
    }

#pragma unroll
    for (int mi = 0; mi < 4; mi++) {
#pragma unroll
        for (int nj = 0; nj < 4; nj++) {
            int row = bm + (wmg + mi) * 16 + (lane >> 2);
            int col = bn + wn + nj * 8 + (lane & 3) * 2;
#pragma unroll
            for (int half = 0; half < 2; half++) {
                int r = row + half * 8;
                float v0 = acc[mi][nj][half * 2 + 0];
                float v1 = acc[mi][nj][half * 2 + 1];
                if (EPI != 3) { v0 += bias[col]; v1 += bias[col + 1]; }
                if (EPI == 1) { v0 = gelu_f(v0); v1 = gelu_f(v1); }
                if (EPI == 2) {
                    v0 += res[(size_t)r * Ndim + col];
                    v1 += res[(size_t)r * Ndim + col + 1];
                }
                float2 w = make_float2(v0, v1);
                *(float2*)&C[(size_t)r * Ndim + col] = w;
            }
        }
    }
}

// ---------------- pipelined tensor-core flash attention with XL relative term ----------------
// K/V double-buffered + R single-buffered cp.async from fragment-packed, pre-rounded globals.
// G ring: contiguous mod-192 (3 slots x 64), pitch 200 floats.
// Smem floats: KP[2][4608] VP[2][4608] RP[4608] GS[128*200] PS[128*72] = 57,856 (231,424 B)
#define FB      4608
#define FP_KP   0
#define FP_VP   (2*FB)
#define FP_RP   (4*FB)
#define FP_GS   (5*FB)
#define FP_PS   (FP_GS + 128*200)
#define FP_SMEM ((FP_PS + 128*72) * 4)

__global__ void __launch_bounds__(256, 1)
flash_xl_tc(const float* __restrict__ qg, const float* __restrict__ kpg,
            const float* __restrict__ vtp, const float* __restrict__ rpg,
            const float* __restrict__ ug, const float* __restrict__ vpg,
            const int* __restrict__ iscp, float* __restrict__ outg) {
    extern __shared__ float sm[];
    float* RP = sm + FP_RP;
    float* Gs = sm + FP_GS;
    float* Ps = sm + FP_PS;

    const int tid = threadIdx.x, lane = tid & 31, w = tid >> 5;
    const int i0 = blockIdx.x * 128, h = blockIdx.y, b = blockIdx.z;
    const int bh = b * N_HEADc + h;
    const int causal = iscp[0];
    const int r0 = w * 16 + (lane >> 2);
    const int kc = lane & 3;
    const int base0 = Tt - 128 - i0;     // >= 0 always

    // ---- load Q into Ps, build A-fragments for Q+u and Q+v (rna-rounded) ----
    {
        const float* qbase = qg + ((size_t)(b * Tt + i0)) * D_MODEL + h * D_HEADc;
#pragma unroll
        for (int p = 0; p < 8; p++) {
            int idx = tid + p * 256;
            int rl = idx >> 4, c4 = (idx & 15) << 2;
            *(float4*)&Ps[rl * 72 + c4] = *(const float4*)&qbase[(size_t)rl * D_MODEL + c4];
        }
    }
    __syncthreads();

    uint32_t aQu[8][4], aQv[8][4];
#pragma unroll
    for (int kk = 0; kk < 8; kk++) {
        int d0 = kk * 8 + kc, d1 = d0 + 4;
        float u0 = __ldg(&ug[h * D_HEADc + d0]),  u1 = __ldg(&ug[h * D_HEADc + d1]);
        float v0 = __ldg(&vpg[h * D_HEADc + d0]), v1 = __ldg(&vpg[h * D_HEADc + d1]);
        float q00 = Ps[r0 * 72 + d0],       q10 = Ps[(r0 + 8) * 72 + d0];
        float q01 = Ps[r0 * 72 + d1],       q11 = Ps[(r0 + 8) * 72 + d1];
        aQu[kk][0] = f2tf32(q00 + u0); aQu[kk][1] = f2tf32(q10 + u0);
        aQu[kk][2] = f2tf32(q01 + u1); aQu[kk][3] = f2tf32(q11 + u1);
        aQv[kk][0] = f2tf32(q00 + v0); aQv[kk][1] = f2tf32(q10 + v0);
        aQv[kk][2] = f2tf32(q01 + v1); aQv[kk][3] = f2tf32(q11 + v1);
    }
    __syncthreads();   // Ps free for P staging

    // ---- prefill G ring absolute cols [0,128) via R halves 0,1 ----
#pragma unroll
    for (int hh = 0; hh < 2; hh++) {
        int rb = base0 + hh * 64;        // rows rb..rb+63 all within [0, KK)
#pragma unroll
        for (int p = 0; p < 4; p++) {
            int c = tid + p * 256;
            int row = c >> 4, part = (c & 15) << 2;
            cp16(&RP[row * 72 + part], &rpg[((size_t)h * KK + rb + row) * 64 + part]);
        }
        asm volatile("cp.async.commit_group;");
        asm volatile("cp.async.wait_group 0;");
        __syncthreads();
#pragma unroll
        for (int nf = 0; nf < 8; nf++) {
            float gc[4] = {0.f, 0.f, 0.f, 0.f};
            int n0 = nf * 8 + (lane >> 2);
#pragma unroll
            for (int kk = 0; kk < 8; kk++) {
                float2 rv = *(const float2*)&RP[n0 * 72 + kk * 8 + kc * 2];
                mma_tf32(gc, aQv[kk][0], aQv[kk][1], aQv[kk][2], aQv[kk][3],
                         __float_as_uint(rv.x), __float_as_uint(rv.y));
            }
            int col = hh * 64 + nf * 8 + kc * 2;
            *(float2*)&Gs[r0 * 200 + col]       = make_float2(gc[0], gc[1]);
            *(float2*)&Gs[(r0 + 8) * 200 + col] = make_float2(gc[2], gc[3]);
        }
        __syncthreads();
    }

    const int njt = causal ? (i0 / 64 + 34) : (KK / 64);
    const float scale = 0.125f;

    // ---- tile-load issuer: K,V into stage jtn&1; R half jtn+2 into RP ----
    auto issue_tiles = [&](int jtn) {
        int st = jtn & 1;
        float* KPd = sm + FP_KP + st * FB;
        float* VPd = sm + FP_VP + st * FB;
        int j0n = jtn * 64;
        int rbn = base0 + j0n + 128;
#pragma unroll
        for (int p = 0; p < 4; p++) {
            int c = tid + p * 256;
            int row = c >> 4, part = (c & 15) << 2;
            cp16(&KPd[row * 72 + part], &kpg[((size_t)bh * KK + j0n + row) * 64 + part]);
        }
#pragma unroll
        for (int p = 0; p < 4; p++) {
            int c = tid + p * 256;
            int row = c >> 4, part = (c & 15) << 2;
            cp16(&VPd[row * 72 + part],
                 &vtp[(((size_t)bh * 64 + jtn) * 64 + row) * 64 + part]);
        }
#pragma unroll
        for (int p = 0; p < 4; p++) {
            int c = tid + p * 256;
            int row = c >> 4, part = (c & 15) << 2;
            int gr = rbn + row; if (gr > KK - 1) gr = KK - 1;
            cp16(&RP[row * 72 + part], &rpg[((size_t)h * KK + gr) * 64 + part]);
        }
        asm volatile("cp.async.commit_group;");
    };

    issue_tiles(0);

    // ---- main loop ----
    float mi0 = -1e30f, mi1 = -1e30f, li0 = 0.f, li1 = 0.f;
    float oc[8][4];
#pragma unroll
    for (int nf = 0; nf < 8; nf++)
#pragma unroll
        for (int e = 0; e < 4; e++) oc[nf][e] = 0.f;

    int jtb192 = 0;
    for (int jt = 0; jt < njt; jt++) {
        const int j0 = jt * 64;
        asm volatile("cp.async.wait_group 0;");
        __syncthreads();   // loads visible; all warps done with prior-stage reads

        // G fill at ring cols [gfill, gfill+64) (reads RP; Gs rows warp-private)
        {
            int gfill = jtb192 + 128; if (gfill >= 192) gfill -= 192;
#pragma unroll
            for (int nf = 0; nf < 8; nf++) {
                float gc[4] = {0.f, 0.f, 0.f, 0.f};
                int n0 = nf * 8 + (lane >> 2);
#pragma unroll
                for (int kk = 0; kk < 8; kk++) {
                    float2 rv = *(const float2*)&RP[n0 * 72 + kk * 8 + kc * 2];
                    mma_tf32(gc, aQv[kk][0], aQv[kk][1], aQv[kk][2], aQv[kk][3],
                             __float_as_uint(rv.x), __float_as_uint(rv.y));
                }
                int col = gfill + nf * 8 + kc * 2;
                *(float2*)&Gs[r0 * 200 + col]       = make_float2(gc[0], gc[1]);
                *(float2*)&Gs[(r0 + 8) * 200 + col] = make_float2(gc[2], gc[3]);
            }
        }
        __syncthreads();   // all warps done with RP -> safe to refill

        if (jt + 1 < njt) issue_tiles(jt + 1);
        __syncwarp();      // order own-warp G stores before gather

        const float* KPs = sm + FP_KP + (jt & 1) * FB;
        const float* VPs = sm + FP_VP + (jt & 1) * FB;

        // S = AC via mma
        float sc[8][4];
#pragma unroll
        for (int nf = 0; nf < 8; nf++) {
            sc[nf][0] = sc[nf][1] = sc[nf][2] = sc[nf][3] = 0.f;
            int n0 = nf * 8 + (lane >> 2);
#pragma unroll
            for (int kk = 0; kk < 8; kk++) {
                float2 kv = *(const float2*)&KPs[n0 * 72 + kk * 8 + kc * 2];
                mma_tf32(sc[nf], aQu[kk][0], aQu[kk][1], aQu[kk][2], aQu[kk][3],
                         __float_as_uint(kv.x), __float_as_uint(kv.y));
            }
        }

        // + BD gather from mod-192 ring, scale, causal mask
#pragma unroll
        for (int nf = 0; nf < 8; nf++) {
#pragma unroll
            for (int e = 0; e < 4; e++) {
                int rl = r0 + ((e >= 2) ? 8 : 0);
                int jl = nf * 8 + kc * 2 + (e & 1);
                int colA = jtb192 + jl + 127 - rl;
                if (colA >= 192) colA -= 192;
                float val = (sc[nf][e] + Gs[rl * 200 + colA]) * scale;
                if (causal && (j0 + jl) > (i0 + rl + Mm)) val = -1e30f;
                sc[nf][e] = val;
            }
        }

        // online softmax (rows within warp; reduce across lane&3)
        float rm0 = -1e30f, rm1 = -1e30f;
#pragma unroll
        for (int nf = 0; nf < 8; nf++) {
            rm0 = fmaxf(rm0, fmaxf(sc[nf][0], sc[nf][1]));
            rm1 = fmaxf(rm1, fmaxf(sc[nf][2], sc[nf][3]));
        }
        rm0 = fmaxf(rm0, __shfl_xor_sync(0xffffffffu, rm0, 1));
        rm0 = fmaxf(rm0, __shfl_xor_sync(0xffffffffu, rm0, 2));
        rm1 = fmaxf(rm1, __shfl_xor_sync(0xffffffffu, rm1, 1));
        rm1 = fmaxf(rm1, __shfl_xor_sync(0xffffffffu, rm1, 2));
        float mn0 = fmaxf(mi0, rm0), mn1 = fmaxf(mi1, rm1);
        float corr0 = __expf(mi0 - mn0), corr1 = __expf(mi1 - mn1);
        float sum0 = 0.f, sum1 = 0.f;
#pragma unroll
        for (int nf = 0; nf < 8; nf++) {
            float p0 = __expf(sc[nf][0] - mn0);
            float p1 = __expf(sc[nf][1] - mn0);
            float p2 = __expf(sc[nf][2] - mn1);
            float p3 = __expf(sc[nf][3] - mn1);
            sc[nf][0] = p0; sc[nf][1] = p1; sc[nf][2] = p2; sc[nf][3] = p3;
            sum0 += p0 + p1; sum1 += p2 + p3;
        }
        sum0 += __shfl_xor_sync(0xffffffffu, sum0, 1);
        sum0 += __shfl_xor_sync(0xffffffffu, sum0, 2);
        sum1 += __shfl_xor_sync(0xffffffffu, sum1, 1);
        sum1 += __shfl_xor_sync(0xffffffffu, sum1, 2);
        li0 = li0 * corr0 + sum0; li1 = li1 * corr1 + sum1;
        mi0 = mn0; mi1 = mn1;
#pragma unroll
        for (int nf = 0; nf < 8; nf++) {
            oc[nf][0] *= corr0; oc[nf][1] *= corr0;
            oc[nf][2] *= corr1; oc[nf][3] *= corr1;
        }

        // stage P (warp-private rows) then PV mma
#pragma unroll
        for (int nf = 0; nf < 8; nf++) {
            int col = nf * 8 + kc * 2;
            *(float2*)&Ps[r0 * 72 + col]       = make_float2(sc[nf][0], sc[nf][1]);
            *(float2*)&Ps[(r0 + 8) * 72 + col] = make_float2(sc[nf][2], sc[nf][3]);
        }
        __syncwarp();
        uint32_t pa[8][4];
#pragma unroll
        for (int kk = 0; kk < 8; kk++) {
            int d0 = kk * 8 + kc, d1 = d0 + 4;
            pa[kk][0] = f2tf32(Ps[r0 * 72 + d0]);
            pa[kk][1] = f2tf32(Ps[(r0 + 8) * 72 + d0]);
            pa[kk][2] = f2tf32(Ps[r0 * 72 + d1]);
            pa[kk][3] = f2tf32(Ps[(r0 + 8) * 72 + d1]);
        }
#pragma unroll
        for (int nf = 0; nf < 8; nf++) {
            int n0 = nf * 8 + (lane >> 2);
#pragma unroll
            for (int kk = 0; kk < 8; kk++) {
                float2 vv = *(const float2*)&VPs[n0 * 72 + kk * 8 + kc * 2];
                mma_tf32(oc[nf], pa[kk][0], pa[kk][1], pa[kk][2], pa[kk][3],
                         __float_as_uint(vv.x), __float_as_uint(vv.y));
            }
        }

        jtb192 += 64; if (jtb192 >= 192) jtb192 -= 192;
    }

    // ---- epilogue: O / l ----
    float inv0 = 1.f / li0, inv1 = 1.f / li1;
    float* ob0 = outg + ((size_t)(b * Tt + i0 + r0)) * D_MODEL + h * D_HEADc;
    float* ob1 = outg + ((size_t)(b * Tt + i0 + r0 + 8)) * D_MODEL + h * D_HEADc;
#pragma unroll
    for (int nf = 0; nf < 8; nf++) {
        int col = nf * 8 + kc * 2;
        *(float2*)&ob0[col] = make_float2(oc[nf][0] * inv0, oc[nf][1] * inv0);
        *(float2*)&ob1[col] = make_float2(oc[nf][2] * inv1, oc[nf][3] * inv1);
    }
}

// ---------------- LayerNorm over last dim (D=1024), one block per row ----------------
__global__ void __launch_bounds__(256)
layernorm_k(const float* __restrict__ in, const float* __restrict__ g,
            const float* __restrict__ be, float* __restrict__ out) {
    __shared__ float red[34];
    const int row = blockIdx.x;
    const int tid = threadIdx.x;
    float4 v = ((const float4*)(in + (size_t)row * D_MODEL))[tid];

    float s = v.x + v.y + v.z + v.w;
    int lane = tid & 31, wid = tid >> 5;
#pragma unroll
    for (int off = 16; off >= 1; off >>= 1) s += __shfl_xor_sync(0xffffffffu, s, off);
    if (lane == 0) red[wid] = s;
    __syncthreads();
    if (tid == 0) {
        float t = 0.f;
#pragma unroll
        for (int w2 = 0; w2 < 8; w2++) t += red[w2];
        red[32] = t;
    }
    __syncthreads();
    float mu = red[32] * (1.f / (float)D_MODEL);

    float dx0 = v.x - mu, dx1 = v.y - mu, dx2 = v.z - mu, dx3 = v.w - mu;
    float sq = dx0 * dx0 + dx1 * dx1 + dx2 * dx2 + dx3 * dx3;
#pragma unroll
    for (int off = 16; off >= 1; off >>= 1) sq += __shfl_xor_sync(0xffffffffu, sq, off);
    if (lane == 0) red[wid] = sq;
    __syncthreads();
    if (tid == 0) {
        float t = 0.f;
#pragma unroll
        for (int w2 = 0; w2 < 8; w2++) t += red[w2];
        red[33] = t;
    }
    __syncthreads();
    float rstd = rsqrtf(red[33] * (1.f / (float)D_MODEL) + 1e-5f);

    float4 gv = ((const float4*)g)[tid];
    float4 bv = ((const float4*)be)[tid];
    float4 o;
    o.x = dx0 * rstd * gv.x + bv.x;
    o.y = dx1 * rstd * gv.y + bv.y;
    o.z = dx2 * rstd * gv.z + bv.z;
    o.w = dx3 * rstd * gv.w + bv.w;
    ((float4*)(out + (size_t)row * D_MODEL))[tid] = o;
}

// ---------------- launch ----------------
extern "C" void kernel_launch(void* const* d_in, const int* in_sizes, int n_in,
                              void* d_out, int out_size) {
    const float* x    = (const float*)d_in[0];
    const float* mem  = (const float*)d_in[1];
    const float* Wq   = (const float*)d_in[2];
    const float* bq   = (const float*)d_in[3];
    const float* Wk   = (const float*)d_in[4];
    const float* bk   = (const float*)d_in[5];
    const float* Wv   = (const float*)d_in[6];
    const float* bv   = (const float*)d_in[7];
    const float* Wo   = (const float*)d_in[8];
    const float* bo   = (const float*)d_in[9];
    const float* Wr   = (const float*)d_in[10];
    const float* u    = (const float*)d_in[11];
    const float* vpar = (const float*)d_in[12];
    const float* g1   = (const float*)d_in[13];
    const float* be1  = (const float*)d_in[14];
    const float* g2   = (const float*)d_in[15];
    const float* be2  = (const float*)d_in[16];
    const float* W1   = (const float*)d_in[17];
    const float* b1   = (const float*)d_in[18];
    const float* W2   = (const float*)d_in[19];
    const float* b2   = (const float*)d_in[20];
    const int*   isc  = (const int*)d_in[21];
    float* out = (float*)d_out;

    float *P, *r, *q, *c, *k, *vv, *attn, *s, *h, *f1, *invf;
    float *xp, *cp, *ap, *hp, *f1p;
    float *wqp, *wkp, *wvp, *wrp, *wop, *w1p, *w2p;
    float *kp, *vp, *rp;
    cudaGetSymbolAddress((void**)&P,    g_P);
    cudaGetSymbolAddress((void**)&r,    g_r);
    cudaGetSymbolAddress((void**)&q,    g_q);
    cudaGetSymbolAddress((void**)&c,    g_c);
    cudaGetSymbolAddress((void**)&k,    g_k);
    cudaGetSymbolAddress((void**)&vv,   g_v);
    cudaGetSymbolAddress((void**)&attn, g_attn);
    cudaGetSymbolAddress((void**)&s,    g_s);
    cudaGetSymbolAddress((void**)&h,    g_h);
    cudaGetSymbolAddress((void**)&f1,   g_f1);
    cudaGetSymbolAddress((void**)&invf, g_invf);
    cudaGetSymbolAddress((void**)&xp,   g_xp);
    cudaGetSymbolAddress((void**)&cp,   g_cp);
    cudaGetSymbolAddress((void**)&ap,   g_ap);
    cudaGetSymbolAddress((void**)&hp,   g_hp);
    cudaGetSymbolAddress((void**)&f1p,  g_f1p);
    cudaGetSymbolAddress((void**)&wqp,  g_wqp);
    cudaGetSymbolAddress((void**)&wkp,  g_wkp);
    cudaGetSymbolAddress((void**)&wvp,  g_wvp);
    cudaGetSymbolAddress((void**)&wrp,  g_wrp);
    cudaGetSymbolAddress((void**)&wop,  g_wop);
    cudaGetSymbolAddress((void**)&w1p,  g_w1p);
    cudaGetSymbolAddress((void**)&w2p,  g_w2p);
    cudaGetSymbolAddress((void**)&kp,   g_kp);
    cudaGetSymbolAddress((void**)&vp,   g_vp);
    cudaGetSymbolAddress((void**)&rp,   g_rp);

    cudaFuncSetAttribute(tgemm<0>, cudaFuncAttributeMaxDynamicSharedMemorySize, TG2_SMEM);
    cudaFuncSetAttribute(tgemm<1>, cudaFuncAttributeMaxDynamicSharedMemorySize, TG2_SMEM);
    cudaFuncSetAttribute(tgemm<2>, cudaFuncAttributeMaxDynamicSharedMemorySize, TG2_SMEM);
    cudaFuncSetAttribute(tgemm<3>, cudaFuncAttributeMaxDynamicSharedMemorySize, TG2_SMEM);
    cudaFuncSetAttribute(flash_xl_tc, cudaFuncAttributeMaxDynamicSharedMemorySize, FP_SMEM);

    const int TPB = 256;
    fill_invf<<<1, 512>>>(invf);
    fill_pos_packed<<<(KK * D_MODEL + TPB - 1) / TPB, TPB>>>(P, invf);
    concat_kernel<<<(ROWS_C * (D_MODEL / 4) + TPB - 1) / TPB, TPB>>>(x, mem, c);

    pack_w<<<((D_MODEL / 8) * D_MODEL + TPB - 1) / TPB, TPB>>>(Wq, wqp, D_MODEL, D_MODEL);
    pack_w<<<((D_MODEL / 8) * D_MODEL + TPB - 1) / TPB, TPB>>>(Wk, wkp, D_MODEL, D_MODEL);
    pack_w<<<((D_MODEL / 8) * D_MODEL + TPB - 1) / TPB, TPB>>>(Wv, wvp, D_MODEL, D_MODEL);
    pack_w<<<((D_MODEL / 8) * D_MODEL + TPB - 1) / TPB, TPB>>>(Wr, wrp, D_MODEL, D_MODEL);
    pack_w<<<((D_MODEL / 8) * D_MODEL + TPB - 1) / TPB, TPB>>>(Wo, wop, D_MODEL, D_MODEL);
    pack_w<<<((D_MODEL / 8) * FFN_H + TPB - 1) / TPB, TPB>>>(W1, w1p, FFN_H, D_MODEL);
    pack_w<<<((FFN_H / 8) * D_MODEL + TPB - 1) / TPB, TPB>>>(W2, w2p, D_MODEL, FFN_H);

    pack_a<<<((ROWS_X / 16) * (D_MODEL / 8) * 32 + TPB - 1) / TPB, TPB>>>(x, xp, ROWS_X, D_MODEL);
    pack_a<<<((ROWS_C / 16) * (D_MODEL / 8) * 32 + TPB - 1) / TPB, TPB>>>(c, cp, ROWS_C, D_MODEL);

    // projections (packed-operand tf32 tensor cores)
    tgemm<0><<<dim3(D_MODEL / 128, ROWS_X / 128), 256, TG2_SMEM>>>(xp, wqp, bq, nullptr, q, D_MODEL, D_MODEL);
    tgemm<0><<<dim3(D_MODEL / 128, ROWS_C / 128), 256, TG2_SMEM>>>(cp, wkp, bk, nullptr, k, D_MODEL, D_MODEL);
    tgemm<0><<<dim3(D_MODEL / 128, ROWS_C / 128), 256, TG2_SMEM>>>(cp, wvp, bv, nullptr, vv, D_MODEL, D_MODEL);
    tgemm<3><<<dim3(D_MODEL / 128, KK / 128), 256, TG2_SMEM>>>(P, wrp, nullptr, nullptr, r, D_MODEL, D_MODEL);

    // pack flash operands (pre-rounded, fragment-packed)
    pack_kp<<<(Bb * N_HEADc * KK * 8) / TPB, TPB>>>(k, kp);
    pack_vp<<<dim3(KK / 64, N_HEADc, Bb), 256>>>(vv, vp);
    pack_rp<<<(N_HEADc * KK * 8) / TPB, TPB>>>(r, rp);

    // attention (pipelined tensor-core flash)
    flash_xl_tc<<<dim3(Tt / 128, N_HEADc, Bb), 256, FP_SMEM>>>(q, kp, vp, rp, u, vpar, isc, attn);

    // o-proj + residual, LN1
    pack_a<<<((ROWS_X / 16) * (D_MODEL / 8) * 32 + TPB - 1) / TPB, TPB>>>(attn, ap, ROWS_X, D_MODEL);
    tgemm<2><<<dim3(D_MODEL / 128, ROWS_X / 128), 256, TG2_SMEM>>>(ap, wop, bo, x, s, D_MODEL, D_MODEL);
    layernorm_k<<<ROWS_X, 256>>>(s, g1, be1, h);

    // FFN
    pack_a<<<((ROWS_X / 16) * (D_MODEL / 8) * 32 + TPB - 1) / TPB, TPB>>>(h, hp, ROWS_X, D_MODEL);
    tgemm<1><<<dim3(FFN_H / 128, ROWS_X / 128), 256, TG2_SMEM>>>(hp, w1p, b1, nullptr, f1, FFN_H, D_MODEL);
    pack_a<<<((ROWS_X / 16) * (FFN_H / 8) * 32 + TPB - 1) / TPB, TPB>>>(f1, f1p, ROWS_X, FFN_H);
    tgemm<2><<<dim3(D_MODEL / 128, ROWS_X / 128), 256, TG2_SMEM>>>(f1p, w2p, b2, h, s, D_MODEL, FFN_H);
    layernorm_k<<<ROWS_X, 256>>>(s, g2, be2, out);
}

// round 14
// speedup vs baseline: 5.5507x; 1.0257x over previous
#include <cuda_runtime.h>
#include <math.h>
#include <stdint.h>

// ---------------- problem constants ----------------
#define D_MODEL 1024
#define N_HEADc 16
#define D_HEADc 64
#define FFN_H   4096
#define Bb      4
#define Tt      2048
#define Mm      2048
#define KK      4096            // M + T
#define ROWS_X  (Bb*Tt)         // 8192
#define ROWS_C  (Bb*KK)         // 16384

// ---------------- scratch (static device memory; no runtime alloc) ----------------
static __device__ float g_P   [(size_t)KK*D_MODEL];        // packed-A layout
static __device__ float g_r   [(size_t)KK*D_MODEL];
static __device__ float g_q   [(size_t)ROWS_X*D_MODEL];
static __device__ float g_k   [(size_t)ROWS_C*D_MODEL];
static __device__ float g_v   [(size_t)ROWS_C*D_MODEL];
static __device__ float g_s   [(size_t)ROWS_X*D_MODEL];
static __device__ float g_h   [(size_t)ROWS_X*D_MODEL];
static __device__ float g_invf[512];
// packed-A activation copies
static __device__ float g_xp  [(size_t)ROWS_X*D_MODEL];
static __device__ float g_cp  [(size_t)ROWS_C*D_MODEL];
static __device__ float g_ap  [(size_t)ROWS_X*D_MODEL];    // flash writes packed
static __device__ float g_hp  [(size_t)ROWS_X*D_MODEL];
static __device__ float g_f1p [(size_t)ROWS_X*FFN_H];      // FFN1 writes packed
// packed weights
static __device__ float g_wqp[(size_t)D_MODEL*D_MODEL];
static __device__ float g_wkp[(size_t)D_MODEL*D_MODEL];
static __device__ float g_wvp[(size_t)D_MODEL*D_MODEL];
static __device__ float g_wrp[(size_t)D_MODEL*D_MODEL];
static __device__ float g_wop[(size_t)D_MODEL*D_MODEL];
static __device__ float g_w1p[(size_t)D_MODEL*FFN_H];
static __device__ float g_w2p[(size_t)FFN_H*D_MODEL];
// fragment-packed flash operands (tf32 pre-rounded)
static __device__ float g_kp [(size_t)Bb*N_HEADc*KK*D_HEADc];
static __device__ float g_vp [(size_t)Bb*N_HEADc*KK*D_HEADc];
static __device__ float g_rp [(size_t)N_HEADc*KK*D_HEADc];

// ---------------- helpers ----------------
__device__ __forceinline__ float gelu_f(float x) {
    float x3 = x * x * x;
    float t  = tanhf(0.7978845608028654f * (x + 0.044715f * x3));
    return 0.5f * x * (1.0f + t);
}

__device__ __forceinline__ uint32_t f2tf32(float x) {
    uint32_t r;
    asm("cvt.rna.tf32.f32 %0, %1;" : "=r"(r) : "f"(x));
    return r;
}
__device__ __forceinline__ float tf32r(float x) {
    return __uint_as_float(f2tf32(x));
}

__device__ __forceinline__ void mma_tf32(float c[4], uint32_t a0, uint32_t a1,
                                         uint32_t a2, uint32_t a3,
                                         uint32_t b0, uint32_t b1) {
    asm volatile(
        "mma.sync.aligned.m16n8k8.row.col.f32.tf32.tf32.f32 "
        "{%0,%1,%2,%3},{%4,%5,%6,%7},{%8,%9},{%0,%1,%2,%3};"
        : "+f"(c[0]), "+f"(c[1]), "+f"(c[2]), "+f"(c[3])
        : "r"(a0), "r"(a1), "r"(a2), "r"(a3), "r"(b0), "r"(b1));
}

__device__ __forceinline__ void cp16(void* smem, const void* g) {
    uint32_t s = (uint32_t)__cvta_generic_to_shared(smem);
    asm volatile("cp.async.cg.shared.global [%0], [%1], 16;" :: "r"(s), "l"(g));
}

// ---------------- operand pack kernels ----------------
__global__ void __launch_bounds__(256)
pack_a(const float* __restrict__ A, float* __restrict__ Ap, int Mdim, int Kdim) {
    int t = blockIdx.x * blockDim.x + threadIdx.x;
    int kgdim = Kdim >> 3;
    int total = (Mdim >> 4) * kgdim * 32;
    if (t >= total) return;
    int lane = t & 31, cell = t >> 5;
    int mg = cell / kgdim, kg = cell - mg * kgdim;
    int m0 = mg * 16 + (lane >> 2);
    int k0 = kg * 8 + (lane & 3);
    float4 v;
    v.x = tf32r(A[(size_t)m0 * Kdim + k0]);
    v.y = tf32r(A[(size_t)(m0 + 8) * Kdim + k0]);
    v.z = tf32r(A[(size_t)m0 * Kdim + k0 + 4]);
    v.w = tf32r(A[(size_t)(m0 + 8) * Kdim + k0 + 4]);
    *(float4*)&Ap[(size_t)t * 4] = v;
}

// pack concat([mem,x]) directly (Mm % 16 == 0 so a 16-row cell never straddles)
__global__ void __launch_bounds__(256)
pack_ac(const float* __restrict__ x, const float* __restrict__ mem,
        float* __restrict__ Ap) {
    int t = blockIdx.x * blockDim.x + threadIdx.x;
    const int total = (ROWS_C >> 4) * 128 * 32;
    if (t >= total) return;
    int lane = t & 31, cell = t >> 5;
    int mg = cell >> 7, kg = cell & 127;
    int m0 = mg * 16 + (lane >> 2);
    int k0 = kg * 8 + (lane & 3);
    int b0 = m0 >> 12, tt0 = m0 & 4095;
    const float* row0 = (tt0 < Mm)
        ? mem + ((size_t)(b0 * Mm + tt0)) * D_MODEL
        : x   + ((size_t)(b0 * Tt + tt0 - Mm)) * D_MODEL;
    int m8 = m0 + 8;
    int b8 = m8 >> 12, tt8 = m8 & 4095;
    const float* row8 = (tt8 < Mm)
        ? mem + ((size_t)(b8 * Mm + tt8)) * D_MODEL
        : x   + ((size_t)(b8 * Tt + tt8 - Mm)) * D_MODEL;
    float4 v;
    v.x = tf32r(row0[k0]);
    v.y = tf32r(row8[k0]);
    v.z = tf32r(row0[k0 + 4]);
    v.w = tf32r(row8[k0 + 4]);
    *(float4*)&Ap[(size_t)t * 4] = v;
}

// all 7 weight packs fused (per-cell: 8 floats of (k,k+4) pairs, tf32)
__global__ void __launch_bounds__(256)
pack_w_all(const float* __restrict__ Wq, const float* __restrict__ Wk,
           const float* __restrict__ Wv, const float* __restrict__ Wr,
           const float* __restrict__ Wo, const float* __restrict__ W1,
           const float* __restrict__ W2,
           float* __restrict__ wqp, float* __restrict__ wkp,
           float* __restrict__ wvp, float* __restrict__ wrp,
           float* __restrict__ wop, float* __restrict__ w1p,
           float* __restrict__ w2p) {
    int t = blockIdx.x * blockDim.x + threadIdx.x;
    const int S = 128 * 1024;                 // cells per 1024x1024 weight
    const float* W; float* Wp; int Ndim, local;
    if (t < 5 * S) {
        int ws = t / S; local = t - ws * S; Ndim = 1024;
        W  = (ws == 0) ? Wq  : (ws == 1) ? Wk  : (ws == 2) ? Wv  : (ws == 3) ? Wr  : Wo;
        Wp = (ws == 0) ? wqp : (ws == 1) ? wkp : (ws == 2) ? wvp : (ws == 3) ? wrp : wop;
    } else if (t < 5 * S + 128 * 4096) {
        local = t - 5 * S; Ndim = 4096; W = W1; Wp = w1p;
    } else {
        local = t - 5 * S - 128 * 4096;
        if (local >= 512 * 1024) return;
        Ndim = 1024; W = W2; Wp = w2p;
    }
    int kg = local / Ndim, n = local - kg * Ndim;
    float* dst = Wp + (size_t)local * 8;
    *(float4*)dst = make_float4(
        tf32r(W[(size_t)(kg * 8 + 0) * Ndim + n]), tf32r(W[(size_t)(kg * 8 + 4) * Ndim + n]),
        tf32r(W[(size_t)(kg * 8 + 1) * Ndim + n]), tf32r(W[(size_t)(kg * 8 + 5) * Ndim + n]));
    *(float4*)(dst + 4) = make_float4(
        tf32r(W[(size_t)(kg * 8 + 2) * Ndim + n]), tf32r(W[(size_t)(kg * 8 + 6) * Ndim + n]),
        tf32r(W[(size_t)(kg * 8 + 3) * Ndim + n]), tf32r(W[(size_t)(kg * 8 + 7) * Ndim + n]));
}

// K and R flash packs fused: pairs along d per 64-wide row
__global__ void __launch_bounds__(256)
pack_krp(const float* __restrict__ K, const float* __restrict__ R,
         float* __restrict__ Kp, float* __restrict__ Rp) {
    int t = blockIdx.x * blockDim.x + threadIdx.x;
    const int NK = Bb * N_HEADc * KK * 8;      // 2,097,152
    const float* src; float* dst;
    if (t < NK) {
        int kg = t & 7, j = (t >> 3) & (KK - 1), bh = t >> 15;
        int b = bh >> 4, h = bh & 15;
        src = K + ((size_t)(b * KK + j)) * D_MODEL + h * D_HEADc + kg * 8;
        dst = Kp + (size_t)t * 8;
    } else {
        int t2 = t - NK;
        if (t2 >= N_HEADc * KK * 8) return;
        int kg = t2 & 7, row = (t2 >> 3) & (KK - 1), h = t2 >> 15;
        src = R + (size_t)row * D_MODEL + h * D_HEADc + kg * 8;
        dst = Rp + (size_t)t2 * 8;
    }
    *(float4*)dst       = make_float4(tf32r(src[0]), tf32r(src[4]), tf32r(src[1]), tf32r(src[5]));
    *(float4*)(dst + 4) = make_float4(tf32r(src[2]), tf32r(src[6]), tf32r(src[3]), tf32r(src[7]));
}

// V: transpose 64-key tile then pack pairs along key axis: out[(b,h)][jt][d][64]
__global__ void __launch_bounds__(256)
pack_vp(const float* __restrict__ v, float* __restrict__ vp) {
    __shared__ float ts[64][65];
    const int tid = threadIdx.x;
    const int jt = blockIdx.x, h = blockIdx.y, b = blockIdx.z;
    const int t0 = jt * 64, bh = b * N_HEADc + h;
#pragma unroll
    for (int p = 0; p < 4; p++) {
        int idx = tid + p * 256;
        int tr = idx >> 4, c4 = (idx & 15) << 2;
        float4 vv = *(const float4*)&v[(size_t)(b * KK + t0 + tr) * D_MODEL + h * D_HEADc + c4];
        ts[c4 + 0][tr] = vv.x; ts[c4 + 1][tr] = vv.y;
        ts[c4 + 2][tr] = vv.z; ts[c4 + 3][tr] = vv.w;
    }
    __syncthreads();
    int d = tid >> 2, g = tid & 3;
    float* dst = vp + (((size_t)bh * 64 + jt) * 64 + d) * 64 + g * 16;
    float buf[16];
#pragma unroll
    for (int sp = 0; sp < 8; sp++) {
        int kk = g * 2 + (sp >> 2), kc = sp & 3;
        buf[sp * 2 + 0] = tf32r(ts[d][kk * 8 + kc]);
        buf[sp * 2 + 1] = tf32r(ts[d][kk * 8 + kc + 4]);
    }
#pragma unroll
    for (int q4 = 0; q4 < 4; q4++)
        *(float4*)(dst + q4 * 4) = *(float4*)(buf + q4 * 4);
}

// ---------------- positional tables ----------------
__global__ void fill_invf(float* __restrict__ invf) {
    int f = threadIdx.x;
    if (f < 512) {
        double v = exp(-((double)(2 * f) / (double)D_MODEL) * log(10000.0));
        invf[f] = (float)v;
    }
}

__global__ void fill_pos_packed(float* __restrict__ P, const float* __restrict__ invf) {
    int idx = blockIdx.x * blockDim.x + threadIdx.x;
    if (idx >= KK * D_MODEL) return;
    int elem = idx & 3, lane = (idx >> 2) & 31, cell = idx >> 7;
    int kg = cell & 127;
    int mg = cell >> 7;
    int m   = mg * 16 + (lane >> 2) + ((elem & 1) << 3);
    int col = kg * 8 + (lane & 3) + ((elem >> 1) << 2);
    float pos = (float)(KK - 1 - m);
    int f = (col < D_MODEL / 2) ? col : col - D_MODEL / 2;
    float ang = pos * __ldg(&invf[f]);
    P[idx] = tf32r((col < D_MODEL / 2) ? sinf(ang) : cosf(ang));
}

// ---------------- packed-operand tf32 GEMM ----------------
// EPI: 0 = +bias ; 1 = gelu(+bias) ; 2 = +bias +res ; 3 = plain ; 4 = gelu(+bias) packed-store
#define TG2_AS 4096
#define TG2_BS 4096
#define TG2_STG (TG2_AS + TG2_BS)
#define TG2_SMEM (3 * TG2_STG * 4)

template <int EPI>
__global__ void __launch_bounds__(256, 2)
tgemm(const float* __restrict__ Ap, const float* __restrict__ Wp,
      const float* __restrict__ bias, const float* __restrict__ res,
      float* __restrict__ C, int Ndim, int Kdim) {
    extern __shared__ float smx[];
    const int tid = threadIdx.x, wid = tid >> 5, lane = tid & 31;
    const int bm = blockIdx.y * 128, bn = blockIdx.x * 128;
    const int wmg = (wid >> 2) * 4, wn = (wid & 3) * 32;
    const int KT = Kdim / 32;
    const int kgdim = Kdim >> 3;
    const int mg0 = bm >> 4;

    float acc[4][4][4];
#pragma unroll
    for (int mi = 0; mi < 4; mi++)
#pragma unroll
        for (int nj = 0; nj < 4; nj++)
#pragma unroll
            for (int e = 0; e < 4; e++) acc[mi][nj][e] = 0.f;

    auto issue = [&](int kt) {
        int s = kt % 3;
        float* As = smx + s * TG2_STG;
        float* Bs = As + TG2_AS;
        int kg0 = kt * 4;
#pragma unroll
        for (int p = 0; p < 4; p++) {
            int c = tid + p * 256;
            size_t fidx = ((size_t)((mg0 + (c >> 7)) * kgdim + kg0 + ((c >> 5) & 3)) * 32
                           + (c & 31)) * 4;
            cp16(&As[c * 4], &Ap[fidx]);
        }
#pragma unroll
        for (int p = 0; p < 4; p++) {
            int c = tid + p * 256;
            int kgl = c >> 8, rest = c & 255;
            size_t fidx = ((size_t)((kg0 + kgl) * Ndim + bn + (rest >> 1))) * 8 + (rest & 1) * 4;
            cp16(&Bs[c * 4], &Wp[fidx]);
        }
        asm volatile("cp.async.commit_group;");
    };

    auto compute = [&](int s) {
        const float* As = smx + s * TG2_STG;
        const float* Bs = As + TG2_AS;
#pragma unroll
        for (int sub = 0; sub < 4; sub++) {
            uint4 af[4];
            float2 bfv[4];
#pragma unroll
            for (int mi = 0; mi < 4; mi++)
                af[mi] = *(const uint4*)&As[(((wmg + mi) * 4 + sub) * 32 + lane) * 4];
#pragma unroll
            for (int nj = 0; nj < 4; nj++)
                bfv[nj] = *(const float2*)&Bs[((size_t)(sub * 128 + wn + nj * 8 + (lane >> 2))) * 8
                                              + (lane & 3) * 2];
#pragma unroll
            for (int mi = 0; mi < 4; mi++)
#pragma unroll
                for (int nj = 0; nj < 4; nj++)
                    mma_tf32(acc[mi][nj], af[mi].x, af[mi].y, af[mi].z, af[mi].w,
                             __float_as_uint(bfv[nj].x), __float_as_uint(bfv[nj].y));
        }
    };

    issue(0);
    issue(1);
    for (int kt = 0; kt < KT; kt++) {
        if (kt == KT - 1) asm volatile("cp.async.wait_group 0;");
        else              asm volatile("cp.async.wait_group 1;");
        __syncthreads();
        if (kt + 2 < KT) issue(kt + 2);
        compute(kt % 3);
        // trailing sync removed: compute(kt) vs issue(kt+3) hazard is ordered
        // by the NEXT iteration's top barrier (R5 precedent).
    }

    if (EPI == 4) {
        // gelu(+bias) then store directly in packed-A layout via per-warp staging
        __syncthreads();                       // all stages dead; smx reusable
        float* st = smx + wid * (64 * 36);
#pragma unroll
        for (int mi = 0; mi < 4; mi++) {
#pragma unroll
            for (int nj = 0; nj < 4; nj++) {
                int col = bn + wn + nj * 8 + (lane & 3) * 2;
#pragma unroll
                for (int half = 0; half < 2; half++) {
                    float v0 = gelu_f(acc[mi][nj][half * 2 + 0] + bias[col]);
                    float v1 = gelu_f(acc[mi][nj][half * 2 + 1] + bias[col + 1]);
                    int rl = mi * 16 + (lane >> 2) + half * 8;
                    *(float2*)&st[rl * 36 + nj * 8 + (lane & 3) * 2] = make_float2(v0, v1);
                }
            }
        }
        __syncwarp();
        const int kgdim_out = Ndim >> 3;
#pragma unroll
        for (int mi = 0; mi < 4; mi++) {
#pragma unroll
            for (int ck = 0; ck < 4; ck++) {
                int rb = mi * 16 + (lane >> 2);
                int cb = ck * 8 + (lane & 3);
                float4 vv;
                vv.x = st[rb * 36 + cb];
                vv.y = st[(rb + 8) * 36 + cb];
                vv.z = st[rb * 36 + cb + 4];
                vv.w = st[(rb + 8) * 36 + cb + 4];
                int mg_out = mg0 + wmg + mi;
                int kg_out = ((bn + wn) >> 3) + ck;
                *(float4*)&C[(((size_t)mg_out * kgdim_out + kg_out) * 32 + lane) * 4] = vv;
            }
        }
        return;
    }

#pragma unroll
    for (int mi = 0; mi < 4; mi++) {
#pragma unroll
        for (int nj = 0; nj < 4; nj++) {
            int row = bm + (wmg + mi) * 16 + (lane >> 2);
            int col = bn + wn + nj * 8 + (lane & 3) * 2;
#pragma unroll
            for (int half = 0; half < 2; half++) {
                int r = row + half * 8;
                float v0 = acc[mi][nj][half * 2 + 0];
                float v1 = acc[mi][nj][half * 2 + 1];
                if (EPI != 3) { v0 += bias[col]; v1 += bias[col + 1]; }
                if (EPI == 1) { v0 = gelu_f(v0); v1 = gelu_f(v1); }
                if (EPI == 2) {
                    v0 += res[(size_t)r * Ndim + col];
                    v1 += res[(size_t)r * Ndim + col + 1];
                }
                float2 w = make_float2(v0, v1);
                *(float2*)&C[(size_t)r * Ndim + col] = w;
            }
        }
    }
}

// ---------------- pipelined tensor-core flash attention with XL relative term ----------------
// Output written directly in packed-A layout (for the o-proj GEMM).
#define FB      4608
#define FP_KP   0
#define FP_VP   (2*FB)
#define FP_RP   (4*FB)
#define FP_GS   (5*FB)
#define FP_PS   (FP_GS + 128*200)
#define FP_SMEM ((FP_PS + 128*72) * 4)

__global__ void __launch_bounds__(256, 1)
flash_xl_tc(const float* __restrict__ qg, const float* __restrict__ kpg,
            const float* __restrict__ vtp, const float* __restrict__ rpg,
            const float* __restrict__ ug, const float* __restrict__ vpg,
            const int* __restrict__ iscp, float* __restrict__ apg) {
    extern __shared__ float sm[];
    float* RP = sm + FP_RP;
    float* Gs = sm + FP_GS;
    float* Ps = sm + FP_PS;

    const int tid = threadIdx.x, lane = tid & 31, w = tid >> 5;
    const int i0 = (gridDim.x - 1 - blockIdx.x) * 128;   // longest blocks first
    const int h = blockIdx.y, b = blockIdx.z;
    const int bh = b * N_HEADc + h;
    const int causal = iscp[0];
    const int r0 = w * 16 + (lane >> 2);
    const int kc = lane & 3;
    const int base0 = Tt - 128 - i0;

    {
        const float* qbase = qg + ((size_t)(b * Tt + i0)) * D_MODEL + h * D_HEADc;
#pragma unroll
        for (int p = 0; p < 8; p++) {
            int idx = tid + p * 256;
            int rl = idx >> 4, c4 = (idx & 15) << 2;
            *(float4*)&Ps[rl * 72 + c4] = *(const float4*)&qbase[(size_t)rl * D_MODEL + c4];
        }
    }
    __syncthreads();

    uint32_t aQu[8][4], aQv[8][4];
#pragma unroll
    for (int kk = 0; kk < 8; kk++) {
        int d0 = kk * 8 + kc, d1 = d0 + 4;
        float u0 = __ldg(&ug[h * D_HEADc + d0]),  u1 = __ldg(&ug[h * D_HEADc + d1]);
        float v0 = __ldg(&vpg[h * D_HEADc + d0]), v1 = __ldg(&vpg[h * D_HEADc + d1]);
        float q00 = Ps[r0 * 72 + d0],       q10 = Ps[(r0 + 8) * 72 + d0];
        float q01 = Ps[r0 * 72 + d1],       q11 = Ps[(r0 + 8) * 72 + d1];
        aQu[kk][0] = f2tf32(q00 + u0); aQu[kk][1] = f2tf32(q10 + u0);
        aQu[kk][2] = f2tf32(q01 + u1); aQu[kk][3] = f2tf32(q11 + u1);
        aQv[kk][0] = f2tf32(q00 + v0); aQv[kk][1] = f2tf32(q10 + v0);
        aQv[kk][2] = f2tf32(q01 + v1); aQv[kk][3] = f2tf32(q11 + v1);
    }
    __syncthreads();

#pragma unroll
    for (int hh = 0; hh < 2; hh++) {
        int rb = base0 + hh * 64;
#pragma unroll
        for (int p = 0; p < 4; p++) {
            int c = tid + p * 256;
            int row = c >> 4, part = (c & 15) << 2;
            cp16(&RP[row * 72 + part], &rpg[((size_t)h * KK + rb + row) * 64 + part]);
        }
        asm volatile("cp.async.commit_group;");
        asm volatile("cp.async.wait_group 0;");
        __syncthreads();
#pragma unroll
        for (int nf = 0; nf < 8; nf++) {
            float gc[4] = {0.f, 0.f, 0.f, 0.f};
            int n0 = nf * 8 + (lane >> 2);
#pragma unroll
            for (int kk = 0; kk < 8; kk++) {
                float2 rv = *(const float2*)&RP[n0 * 72 + kk * 8 + kc * 2];
                mma_tf32(gc, aQv[kk][0], aQv[kk][1], aQv[kk][2], aQv[kk][3],
                         __float_as_uint(rv.x), __float_as_uint(rv.y));
            }
            int col = hh * 64 + nf * 8 + kc * 2;
            *(float2*)&Gs[r0 * 200 + col]       = make_float2(gc[0], gc[1]);
            *(float2*)&Gs[(r0 + 8) * 200 + col] = make_float2(gc[2], gc[3]);
        }
        __syncthreads();
    }

    const int njt = causal ? (i0 / 64 + 34) : (KK / 64);
    const float scale = 0.125f;

    auto issue_tiles = [&](int jtn) {
        int st = jtn & 1;
        float* KPd = sm + FP_KP + st * FB;
        float* VPd = sm + FP_VP + st * FB;
        int j0n = jtn * 64;
        int rbn = base0 + j0n + 128;
#pragma unroll
        for (int p = 0; p < 4; p++) {
            int c = tid + p * 256;
            int row = c >> 4, part = (c & 15) << 2;
            cp16(&KPd[row * 72 + part], &kpg[((size_t)bh * KK + j0n + row) * 64 + part]);
        }
#pragma unroll
        for (int p = 0; p < 4; p++) {
            int c = tid + p * 256;
            int row = c >> 4, part = (c & 15) << 2;
            cp16(&VPd[row * 72 + part],
                 &vtp[(((size_t)bh * 64 + jtn) * 64 + row) * 64 + part]);
        }
#pragma unroll
        for (int p = 0; p < 4; p++) {
            int c = tid + p * 256;
            int row = c >> 4, part = (c & 15) << 2;
            int gr = rbn + row; if (gr > KK - 1) gr = KK - 1;
            cp16(&RP[row * 72 + part], &rpg[((size_t)h * KK + gr) * 64 + part]);
        }
        asm volatile("cp.async.commit_group;");
    };

    issue_tiles(0);

    float mi0 = -1e30f, mi1 = -1e30f, li0 = 0.f, li1 = 0.f;
    float oc[8][4];
#pragma unroll
    for (int nf = 0; nf < 8; nf++)
#pragma unroll
        for (int e = 0; e < 4; e++) oc[nf][e] = 0.f;

    int jtb192 = 0;
    for (int jt = 0; jt < njt; jt++) {
        const int j0 = jt * 64;
        asm volatile("cp.async.wait_group 0;");
        __syncthreads();

        {
            int gfill = jtb192 + 128; if (gfill >= 192) gfill -= 192;
#pragma unroll
            for (int nf = 0; nf < 8; nf++) {
                float gc[4] = {0.f, 0.f, 0.f, 0.f};
                int n0 = nf * 8 + (lane >> 2);
#pragma unroll
                for (int kk = 0; kk < 8; kk++) {
                    float2 rv = *(const float2*)&RP[n0 * 72 + kk * 8 + kc * 2];
                    mma_tf32(gc, aQv[kk][0], aQv[kk][1], aQv[kk][2], aQv[kk][3],
                             __float_as_uint(rv.x), __float_as_uint(rv.y));
                }
                int col = gfill + nf * 8 + kc * 2;
                *(float2*)&Gs[r0 * 200 + col]       = make_float2(gc[0], gc[1]);
                *(float2*)&Gs[(r0 + 8) * 200 + col] = make_float2(gc[2], gc[3]);
            }
        }
        __syncthreads();

        if (jt + 1 < njt) issue_tiles(jt + 1);
        __syncwarp();

        const float* KPs = sm + FP_KP + (jt & 1) * FB;
        const float* VPs = sm + FP_VP + (jt & 1) * FB;

        float sc[8][4];
#pragma unroll
        for (int nf = 0; nf < 8; nf++) {
            sc[nf][0] = sc[nf][1] = sc[nf][2] = sc[nf][3] = 0.f;
            int n0 = nf * 8 + (lane >> 2);
#pragma unroll
            for (int kk = 0; kk < 8; kk++) {
                float2 kv = *(const float2*)&KPs[n0 * 72 + kk * 8 + kc * 2];
                mma_tf32(sc[nf], aQu[kk][0], aQu[kk][1], aQu[kk][2], aQu[kk][3],
                         __float_as_uint(kv.x), __float_as_uint(kv.y));
            }
        }

#pragma unroll
        for (int nf = 0; nf < 8; nf++) {
#pragma unroll
            for (int e = 0; e < 4; e++) {
                int rl = r0 + ((e >= 2) ? 8 : 0);
                int jl = nf * 8 + kc * 2 + (e & 1);
                int colA = jtb192 + jl + 127 - rl;
                if (colA >= 192) colA -= 192;
                float val = (sc[nf][e] + Gs[rl * 200 + colA]) * scale;
                if (causal && (j0 + jl) > (i0 + rl + Mm)) val = -1e30f;
                sc[nf][e] = val;
            }
        }

        float rm0 = -1e30f, rm1 = -1e30f;
#pragma unroll
        for (int nf = 0; nf < 8; nf++) {
            rm0 = fmaxf(rm0, fmaxf(sc[nf][0], sc[nf][1]));
            rm1 = fmaxf(rm1, fmaxf(sc[nf][2], sc[nf][3]));
        }
        rm0 = fmaxf(rm0, __shfl_xor_sync(0xffffffffu, rm0, 1));
        rm0 = fmaxf(rm0, __shfl_xor_sync(0xffffffffu, rm0, 2));
        rm1 = fmaxf(rm1, __shfl_xor_sync(0xffffffffu, rm1, 1));
        rm1 = fmaxf(rm1, __shfl_xor_sync(0xffffffffu, rm1, 2));
        float mn0 = fmaxf(mi0, rm0), mn1 = fmaxf(mi1, rm1);
        float corr0 = __expf(mi0 - mn0), corr1 = __expf(mi1 - mn1);
        float sum0 = 0.f, sum1 = 0.f;
#pragma unroll
        for (int nf = 0; nf < 8; nf++) {
            float p0 = __expf(sc[nf][0] - mn0);
            float p1 = __expf(sc[nf][1] - mn0);
            float p2 = __expf(sc[nf][2] - mn1);
            float p3 = __expf(sc[nf][3] - mn1);
            sc[nf][0] = p0; sc[nf][1] = p1; sc[nf][2] = p2; sc[nf][3] = p3;
            sum0 += p0 + p1; sum1 += p2 + p3;
        }
        sum0 += __shfl_xor_sync(0xffffffffu, sum0, 1);
        sum0 += __shfl_xor_sync(0xffffffffu, sum0, 2);
        sum1 += __shfl_xor_sync(0xffffffffu, sum1, 1);
        sum1 += __shfl_xor_sync(0xffffffffu, sum1, 2);
        li0 = li0 * corr0 + sum0; li1 = li1 * corr1 + sum1;
        mi0 = mn0; mi1 = mn1;
#pragma unroll
        for (int nf = 0; nf < 8; nf++) {
            oc[nf][0] *= corr0; oc[nf][1] *= corr0;
            oc[nf][2] *= corr1; oc[nf][3] *= corr1;
        }

#pragma unroll
        for (int nf = 0; nf < 8; nf++) {
            int col = nf * 8 + kc * 2;
            *(float2*)&Ps[r0 * 72 + col]       = make_float2(sc[nf][0], sc[nf][1]);
            *(float2*)&Ps[(r0 + 8) * 72 + col] = make_float2(sc[nf][2], sc[nf][3]);
        }
        __syncwarp();
        uint32_t pa[8][4];
#pragma unroll
        for (int kk = 0; kk < 8; kk++) {
            int d0 = kk * 8 + kc, d1 = d0 + 4;
            pa[kk][0] = f2tf32(Ps[r0 * 72 + d0]);
            pa[kk][1] = f2tf32(Ps[(r0 + 8) * 72 + d0]);
            pa[kk][2] = f2tf32(Ps[r0 * 72 + d1]);
            pa[kk][3] = f2tf32(Ps[(r0 + 8) * 72 + d1]);
        }
#pragma unroll
        for (int nf = 0; nf < 8; nf++) {
            int n0 = nf * 8 + (lane >> 2);
#pragma unroll
            for (int kk = 0; kk < 8; kk++) {
                float2 vv = *(const float2*)&VPs[n0 * 72 + kk * 8 + kc * 2];
                mma_tf32(oc[nf], pa[kk][0], pa[kk][1], pa[kk][2], pa[kk][3],
                         __float_as_uint(vv.x), __float_as_uint(vv.y));
            }
        }

        jtb192 += 64; if (jtb192 >= 192) jtb192 -= 192;
    }

    // ---- epilogue: O/l written directly in packed-A layout via Ps restage ----
    float inv0 = 1.f / li0, inv1 = 1.f / li1;
#pragma unroll
    for (int nf = 0; nf < 8; nf++) {
        int col = nf * 8 + kc * 2;
        *(float2*)&Ps[r0 * 72 + col]       = make_float2(oc[nf][0] * inv0, oc[nf][1] * inv0);
        *(float2*)&Ps[(r0 + 8) * 72 + col] = make_float2(oc[nf][2] * inv1, oc[nf][3] * inv1);
    }
    __syncwarp();
    const int mg_out = ((b * Tt + i0) >> 4) + w;   // FIX: include batch offset
#pragma unroll
    for (int kk = 0; kk < 8; kk++) {
        float4 vv;
        vv.x = Ps[r0 * 72 + kk * 8 + kc];
        vv.y = Ps[(r0 + 8) * 72 + kk * 8 + kc];
        vv.z = Ps[r0 * 72 + kk * 8 + kc + 4];
        vv.w = Ps[(r0 + 8) * 72 + kk * 8 + kc + 4];
        int kg_out = h * 8 + kk;
        *(float4*)&apg[(((size_t)mg_out * 128 + kg_out) * 32 + lane) * 4] = vv;
    }
}

// ---------------- LayerNorm over last dim (D=1024), one block per row ----------------
__global__ void __launch_bounds__(256)
layernorm_k(const float* __restrict__ in, const float* __restrict__ g,
            const float* __restrict__ be, float* __restrict__ out) {
    __shared__ float red[34];
    const int row = blockIdx.x;
    const int tid = threadIdx.x;
    float4 v = ((const float4*)(in + (size_t)row * D_MODEL))[tid];

    float s = v.x + v.y + v.z + v.w;
    int lane = tid & 31, wid = tid >> 5;
#pragma unroll
    for (int off = 16; off >= 1; off >>= 1) s += __shfl_xor_sync(0xffffffffu, s, off);
    if (lane == 0) red[wid] = s;
    __syncthreads();
    if (tid == 0) {
        float t = 0.f;
#pragma unroll
        for (int w2 = 0; w2 < 8; w2++) t += red[w2];
        red[32] = t;
    }
    __syncthreads();
    float mu = red[32] * (1.f / (float)D_MODEL);

    float dx0 = v.x - mu, dx1 = v.y - mu, dx2 = v.z - mu, dx3 = v.w - mu;
    float sq = dx0 * dx0 + dx1 * dx1 + dx2 * dx2 + dx3 * dx3;
#pragma unroll
    for (int off = 16; off >= 1; off >>= 1) sq += __shfl_xor_sync(0xffffffffu, sq, off);
    if (lane == 0) red[wid] = sq;
    __syncthreads();
    if (tid == 0) {
        float t = 0.f;
#pragma unroll
        for (int w2 = 0; w2 < 8; w2++) t += red[w2];
        red[33] = t;
    }
    __syncthreads();
    float rstd = rsqrtf(red[33] * (1.f / (float)D_MODEL) + 1e-5f);

    float4 gv = ((const float4*)g)[tid];
    float4 bv = ((const float4*)be)[tid];
    float4 o;
    o.x = dx0 * rstd * gv.x + bv.x;
    o.y = dx1 * rstd * gv.y + bv.y;
    o.z = dx2 * rstd * gv.z + bv.z;
    o.w = dx3 * rstd * gv.w + bv.w;
    ((float4*)(out + (size_t)row * D_MODEL))[tid] = o;
}

// ---------------- launch ----------------
extern "C" void kernel_launch(void* const* d_in, const int* in_sizes, int n_in,
                              void* d_out, int out_size) {
    const float* x    = (const float*)d_in[0];
    const float* mem  = (const float*)d_in[1];
    const float* Wq   = (const float*)d_in[2];
    const float* bq   = (const float*)d_in[3];
    const float* Wk   = (const float*)d_in[4];
    const float* bk   = (const float*)d_in[5];
    const float* Wv   = (const float*)d_in[6];
    const float* bv   = (const float*)d_in[7];
    const float* Wo   = (const float*)d_in[8];
    const float* bo   = (const float*)d_in[9];
    const float* Wr   = (const float*)d_in[10];
    const float* u    = (const float*)d_in[11];
    const float* vpar = (const float*)d_in[12];
    const float* g1   = (const float*)d_in[13];
    const float* be1  = (const float*)d_in[14];
    const float* g2   = (const float*)d_in[15];
    const float* be2  = (const float*)d_in[16];
    const float* W1   = (const float*)d_in[17];
    const float* b1   = (const float*)d_in[18];
    const float* W2   = (const float*)d_in[19];
    const float* b2   = (const float*)d_in[20];
    const int*   isc  = (const int*)d_in[21];
    float* out = (float*)d_out;

    float *P, *r, *q, *k, *vv, *s, *h, *invf;
    float *xp, *cp, *ap, *hp, *f1p;
    float *wqp, *wkp, *wvp, *wrp, *wop, *w1p, *w2p;
    float *kp, *vp, *rp;
    cudaGetSymbolAddress((void**)&P,    g_P);
    cudaGetSymbolAddress((void**)&r,    g_r);
    cudaGetSymbolAddress((void**)&q,    g_q);
    cudaGetSymbolAddress((void**)&k,    g_k);
    cudaGetSymbolAddress((void**)&vv,   g_v);
    cudaGetSymbolAddress((void**)&s,    g_s);
    cudaGetSymbolAddress((void**)&h,    g_h);
    cudaGetSymbolAddress((void**)&invf, g_invf);
    cudaGetSymbolAddress((void**)&xp,   g_xp);
    cudaGetSymbolAddress((void**)&cp,   g_cp);
    cudaGetSymbolAddress((void**)&ap,   g_ap);
    cudaGetSymbolAddress((void**)&hp,   g_hp);
    cudaGetSymbolAddress((void**)&f1p,  g_f1p);
    cudaGetSymbolAddress((void**)&wqp,  g_wqp);
    cudaGetSymbolAddress((void**)&wkp,  g_wkp);
    cudaGetSymbolAddress((void**)&wvp,  g_wvp);
    cudaGetSymbolAddress((void**)&wrp,  g_wrp);
    cudaGetSymbolAddress((void**)&wop,  g_wop);
    cudaGetSymbolAddress((void**)&w1p,  g_w1p);
    cudaGetSymbolAddress((void**)&w2p,  g_w2p);
    cudaGetSymbolAddress((void**)&kp,   g_kp);
    cudaGetSymbolAddress((void**)&vp,   g_vp);
    cudaGetSymbolAddress((void**)&rp,   g_rp);

    cudaFuncSetAttribute(tgemm<0>, cudaFuncAttributeMaxDynamicSharedMemorySize, TG2_SMEM);
    cudaFuncSetAttribute(tgemm<2>, cudaFuncAttributeMaxDynamicSharedMemorySize, TG2_SMEM);
    cudaFuncSetAttribute(tgemm<3>, cudaFuncAttributeMaxDynamicSharedMemorySize, TG2_SMEM);
    cudaFuncSetAttribute(tgemm<4>, cudaFuncAttributeMaxDynamicSharedMemorySize, TG2_SMEM);
    cudaFuncSetAttribute(flash_xl_tc, cudaFuncAttributeMaxDynamicSharedMemorySize, FP_SMEM);

    const int TPB = 256;
    fill_invf<<<1, 512>>>(invf);
    fill_pos_packed<<<(KK * D_MODEL + TPB - 1) / TPB, TPB>>>(P, invf);

    // fused packs
    {
        int total_w = 5 * (128 * 1024) + 128 * 4096 + 512 * 1024;
        pack_w_all<<<(total_w + TPB - 1) / TPB, TPB>>>(Wq, Wk, Wv, Wr, Wo, W1, W2,
                                                       wqp, wkp, wvp, wrp, wop, w1p, w2p);
    }
    pack_a<<<((ROWS_X / 16) * (D_MODEL / 8) * 32 + TPB - 1) / TPB, TPB>>>(x, xp, ROWS_X, D_MODEL);
    pack_ac<<<((ROWS_C / 16) * (D_MODEL / 8) * 32 + TPB - 1) / TPB, TPB>>>(x, mem, cp);

    // projections (packed-operand tf32 tensor cores)
    tgemm<0><<<dim3(D_MODEL / 128, ROWS_X / 128), 256, TG2_SMEM>>>(xp, wqp, bq, nullptr, q, D_MODEL, D_MODEL);
    tgemm<0><<<dim3(D_MODEL / 128, ROWS_C / 128), 256, TG2_SMEM>>>(cp, wkp, bk, nullptr, k, D_MODEL, D_MODEL);
    tgemm<0><<<dim3(D_MODEL / 128, ROWS_C / 128), 256, TG2_SMEM>>>(cp, wvp, bv, nullptr, vv, D_MODEL, D_MODEL);
    tgemm<3><<<dim3(D_MODEL / 128, KK / 128), 256, TG2_SMEM>>>(P, wrp, nullptr, nullptr, r, D_MODEL, D_MODEL);

    // pack flash operands
    {
        int total_kr = Bb * N_HEADc * KK * 8 + N_HEADc * KK * 8;
        pack_krp<<<(total_kr + TPB - 1) / TPB, TPB>>>(k, r, kp, rp);
    }
    pack_vp<<<dim3(KK / 64, N_HEADc, Bb), 256>>>(vv, vp);

    // attention (pipelined tensor-core flash; writes packed attn)
    flash_xl_tc<<<dim3(Tt / 128, N_HEADc, Bb), 256, FP_SMEM>>>(q, kp, vp, rp, u, vpar, isc, ap);

    // o-proj + residual, LN1
    tgemm<2><<<dim3(D_MODEL / 128, ROWS_X / 128), 256, TG2_SMEM>>>(ap, wop, bo, x, s, D_MODEL, D_MODEL);
    layernorm_k<<<ROWS_X, 256>>>(s, g1, be1, h);

    // FFN (FFN1 writes packed directly)
    pack_a<<<((ROWS_X / 16) * (D_MODEL / 8) * 32 + TPB - 1) / TPB, TPB>>>(h, hp, ROWS_X, D_MODEL);
    tgemm<4><<<dim3(FFN_H / 128, ROWS_X / 128), 256, TG2_SMEM>>>(hp, w1p, b1, nullptr, f1p, FFN_H, D_MODEL);
    tgemm<2><<<dim3(D_MODEL / 128, ROWS_X / 128), 256, TG2_SMEM>>>(f1p, w2p, b2, h, s, D_MODEL, FFN_H);
    layernorm_k<<<ROWS_X, 256>>>(s, g2, be2, out);
}

// round 17
// speedup vs baseline: 5.6396x; 1.0160x over previous
#include <cuda_runtime.h>
#include <math.h>
#include <stdint.h>

// ---------------- problem constants ----------------
#define D_MODEL 1024
#define N_HEADc 16
#define D_HEADc 64
#define FFN_H   4096
#define Bb      4
#define Tt      2048
#define Mm      2048
#define KK      4096            // M + T
#define ROWS_X  (Bb*Tt)         // 8192
#define ROWS_C  (Bb*KK)         // 16384

// ---------------- scratch (static device memory; no runtime alloc) ----------------
static __device__ float g_P   [(size_t)KK*D_MODEL];        // packed-A layout
static __device__ float g_q   [(size_t)ROWS_X*D_MODEL];
static __device__ float g_s   [(size_t)ROWS_X*D_MODEL];
static __device__ float g_h   [(size_t)ROWS_X*D_MODEL];
static __device__ float g_invf[512];
// packed-A activation copies
static __device__ float g_xp  [(size_t)ROWS_X*D_MODEL];
static __device__ float g_cp  [(size_t)ROWS_C*D_MODEL];
static __device__ float g_ap  [(size_t)ROWS_X*D_MODEL];    // flash writes packed
static __device__ float g_hp  [(size_t)ROWS_X*D_MODEL];
static __device__ float g_f1p [(size_t)ROWS_X*FFN_H];      // FFN1 writes packed
// packed weights
static __device__ float g_wqp[(size_t)D_MODEL*D_MODEL];
static __device__ float g_wkp[(size_t)D_MODEL*D_MODEL];
static __device__ float g_wvp[(size_t)D_MODEL*D_MODEL];
static __device__ float g_wrp[(size_t)D_MODEL*D_MODEL];
static __device__ float g_wop[(size_t)D_MODEL*D_MODEL];
static __device__ float g_w1p[(size_t)D_MODEL*FFN_H];
static __device__ float g_w2p[(size_t)FFN_H*D_MODEL];
// fragment-packed flash operands (written directly by projection epilogues)
static __device__ float g_kp [(size_t)Bb*N_HEADc*KK*D_HEADc];
static __device__ float g_vp [(size_t)Bb*N_HEADc*KK*D_HEADc];
static __device__ float g_rp [(size_t)N_HEADc*KK*D_HEADc];

// ---------------- helpers ----------------
__device__ __forceinline__ float gelu_f(float x) {
    float x3 = x * x * x;
    float t  = tanhf(0.7978845608028654f * (x + 0.044715f * x3));
    return 0.5f * x * (1.0f + t);
}

__device__ __forceinline__ uint32_t f2tf32(float x) {
    uint32_t r;
    asm("cvt.rna.tf32.f32 %0, %1;" : "=r"(r) : "f"(x));
    return r;
}
__device__ __forceinline__ float tf32r(float x) {
    return __uint_as_float(f2tf32(x));
}

__device__ __forceinline__ void mma_tf32(float c[4], uint32_t a0, uint32_t a1,
                                         uint32_t a2, uint32_t a3,
                                         uint32_t b0, uint32_t b1) {
    asm volatile(
        "mma.sync.aligned.m16n8k8.row.col.f32.tf32.tf32.f32 "
        "{%0,%1,%2,%3},{%4,%5,%6,%7},{%8,%9},{%0,%1,%2,%3};"
        : "+f"(c[0]), "+f"(c[1]), "+f"(c[2]), "+f"(c[3])
        : "r"(a0), "r"(a1), "r"(a2), "r"(a3), "r"(b0), "r"(b1));
}

__device__ __forceinline__ void cp16(void* smem, const void* g) {
    uint32_t s = (uint32_t)__cvta_generic_to_shared(smem);
    asm volatile("cp.async.cg.shared.global [%0], [%1], 16;" :: "r"(s), "l"(g));
}

// ---------------- operand pack kernels ----------------
__global__ void __launch_bounds__(256)
pack_a(const float* __restrict__ A, float* __restrict__ Ap, int Mdim, int Kdim) {
    int t = blockIdx.x * blockDim.x + threadIdx.x;
    int kgdim = Kdim >> 3;
    int total = (Mdim >> 4) * kgdim * 32;
    if (t >= total) return;
    int lane = t & 31, cell = t >> 5;
    int mg = cell / kgdim, kg = cell - mg * kgdim;
    int m0 = mg * 16 + (lane >> 2);
    int k0 = kg * 8 + (lane & 3);
    float4 v;
    v.x = tf32r(A[(size_t)m0 * Kdim + k0]);
    v.y = tf32r(A[(size_t)(m0 + 8) * Kdim + k0]);
    v.z = tf32r(A[(size_t)m0 * Kdim + k0 + 4]);
    v.w = tf32r(A[(size_t)(m0 + 8) * Kdim + k0 + 4]);
    *(float4*)&Ap[(size_t)t * 4] = v;
}

// pack concat([mem,x]) directly (Mm % 16 == 0 so a 16-row cell never straddles)
__global__ void __launch_bounds__(256)
pack_ac(const float* __restrict__ x, const float* __restrict__ mem,
        float* __restrict__ Ap) {
    int t = blockIdx.x * blockDim.x + threadIdx.x;
    const int total = (ROWS_C >> 4) * 128 * 32;
    if (t >= total) return;
    int lane = t & 31, cell = t >> 5;
    int mg = cell >> 7, kg = cell & 127;
    int m0 = mg * 16 + (lane >> 2);
    int k0 = kg * 8 + (lane & 3);
    int b0 = m0 >> 12, tt0 = m0 & 4095;
    const float* row0 = (tt0 < Mm)
        ? mem + ((size_t)(b0 * Mm + tt0)) * D_MODEL
        : x   + ((size_t)(b0 * Tt + tt0 - Mm)) * D_MODEL;
    int m8 = m0 + 8;
    int b8 = m8 >> 12, tt8 = m8 & 4095;
    const float* row8 = (tt8 < Mm)
        ? mem + ((size_t)(b8 * Mm + tt8)) * D_MODEL
        : x   + ((size_t)(b8 * Tt + tt8 - Mm)) * D_MODEL;
    float4 v;
    v.x = tf32r(row0[k0]);
    v.y = tf32r(row8[k0]);
    v.z = tf32r(row0[k0 + 4]);
    v.w = tf32r(row8[k0 + 4]);
    *(float4*)&Ap[(size_t)t * 4] = v;
}

// all 7 weight packs fused (per-cell: 8 floats of (k,k+4) pairs, tf32)
__global__ void __launch_bounds__(256)
pack_w_all(const float* __restrict__ Wq, const float* __restrict__ Wk,
           const float* __restrict__ Wv, const float* __restrict__ Wr,
           const float* __restrict__ Wo, const float* __restrict__ W1,
           const float* __restrict__ W2,
           float* __restrict__ wqp, float* __restrict__ wkp,
           float* __restrict__ wvp, float* __restrict__ wrp,
           float* __restrict__ wop, float* __restrict__ w1p,
           float* __restrict__ w2p) {
    int t = blockIdx.x * blockDim.x + threadIdx.x;
    const int S = 128 * 1024;                 // cells per 1024x1024 weight
    const float* W; float* Wp; int Ndim, local;
    if (t < 5 * S) {
        int ws = t / S; local = t - ws * S; Ndim = 1024;
        W  = (ws == 0) ? Wq  : (ws == 1) ? Wk  : (ws == 2) ? Wv  : (ws == 3) ? Wr  : Wo;
        Wp = (ws == 0) ? wqp : (ws == 1) ? wkp : (ws == 2) ? wvp : (ws == 3) ? wrp : wop;
    } else if (t < 5 * S + 128 * 4096) {
        local = t - 5 * S; Ndim = 4096; W = W1; Wp = w1p;
    } else {
        local = t - 5 * S - 128 * 4096;
        if (local >= 512 * 1024) return;
        Ndim = 1024; W = W2; Wp = w2p;
    }
    int kg = local / Ndim, n = local - kg * Ndim;
    float* dst = Wp + (size_t)local * 8;
    *(float4*)dst = make_float4(
        tf32r(W[(size_t)(kg * 8 + 0) * Ndim + n]), tf32r(W[(size_t)(kg * 8 + 4) * Ndim + n]),
        tf32r(W[(size_t)(kg * 8 + 1) * Ndim + n]), tf32r(W[(size_t)(kg * 8 + 5) * Ndim + n]));
    *(float4*)(dst + 4) = make_float4(
        tf32r(W[(size_t)(kg * 8 + 2) * Ndim + n]), tf32r(W[(size_t)(kg * 8 + 6) * Ndim + n]),
        tf32r(W[(size_t)(kg * 8 + 3) * Ndim + n]), tf32r(W[(size_t)(kg * 8 + 7) * Ndim + n]));
}

// ---------------- positional tables ----------------
__global__ void fill_invf(float* __restrict__ invf) {
    int f = threadIdx.x;
    if (f < 512) {
        double v = exp(-((double)(2 * f) / (double)D_MODEL) * log(10000.0));
        invf[f] = (float)v;
    }
}

__global__ void fill_pos_packed(float* __restrict__ P, const float* __restrict__ invf) {
    int idx = blockIdx.x * blockDim.x + threadIdx.x;
    if (idx >= KK * D_MODEL) return;
    int elem = idx & 3, lane = (idx >> 2) & 31, cell = idx >> 7;
    int kg = cell & 127;
    int mg = cell >> 7;
    int m   = mg * 16 + (lane >> 2) + ((elem & 1) << 3);
    int col = kg * 8 + (lane & 3) + ((elem >> 1) << 2);
    float pos = (float)(KK - 1 - m);
    int f = (col < D_MODEL / 2) ? col : col - D_MODEL / 2;
    float ang = pos * __ldg(&invf[f]);
    P[idx] = tf32r((col < D_MODEL / 2) ? sinf(ang) : cosf(ang));
}

// ---------------- packed-operand tf32 GEMM ----------------
// EPI: 0 = +bias ; 2 = +bias +res ; 3 = plain ; 4 = gelu(+bias) packed-A store
//      5 = (+bias) store in kp/rp layout ; 6 = (+bias) store in vp layout
#define TG2_AS 4096
#define TG2_BS 4096
#define TG2_STG (TG2_AS + TG2_BS)
#define TG2_SMEM (3 * TG2_STG * 4)

template <int EPI>
__global__ void __launch_bounds__(256, 2)
tgemm(const float* __restrict__ Ap, const float* __restrict__ Wp,
      const float* __restrict__ bias, const float* __restrict__ res,
      float* __restrict__ C, int Ndim, int Kdim) {
    extern __shared__ float smx[];
    const int tid = threadIdx.x, wid = tid >> 5, lane = tid & 31;
    const int bm = blockIdx.y * 128, bn = blockIdx.x * 128;
    const int wmg = (wid >> 2) * 4, wn = (wid & 3) * 32;
    const int KT = Kdim / 32;
    const int kgdim = Kdim >> 3;
    const int mg0 = bm >> 4;

    float acc[4][4][4];
#pragma unroll
    for (int mi = 0; mi < 4; mi++)
#pragma unroll
        for (int nj = 0; nj < 4; nj++)
#pragma unroll
            for (int e = 0; e < 4; e++) acc[mi][nj][e] = 0.f;

    auto issue = [&](int kt) {
        int s = kt % 3;
        float* As = smx + s * TG2_STG;
        float* Bs = As + TG2_AS;
        int kg0 = kt * 4;
#pragma unroll
        for (int p = 0; p < 4; p++) {
            int c = tid + p * 256;
            size_t fidx = ((size_t)((mg0 + (c >> 7)) * kgdim + kg0 + ((c >> 5) & 3)) * 32
                           + (c & 31)) * 4;
            cp16(&As[c * 4], &Ap[fidx]);
        }
#pragma unroll
        for (int p = 0; p < 4; p++) {
            int c = tid + p * 256;
            int kgl = c >> 8, rest = c & 255;
            size_t fidx = ((size_t)((kg0 + kgl) * Ndim + bn + (rest >> 1))) * 8 + (rest & 1) * 4;
            cp16(&Bs[c * 4], &Wp[fidx]);
        }
        asm volatile("cp.async.commit_group;");
    };

    auto compute = [&](int s) {
        const float* As = smx + s * TG2_STG;
        const float* Bs = As + TG2_AS;
#pragma unroll
        for (int sub = 0; sub < 4; sub++) {
            uint4 af[4];
            float2 bfv[4];
#pragma unroll
            for (int mi = 0; mi < 4; mi++)
                af[mi] = *(const uint4*)&As[(((wmg + mi) * 4 + sub) * 32 + lane) * 4];
#pragma unroll
            for (int nj = 0; nj < 4; nj++)
                bfv[nj] = *(const float2*)&Bs[((size_t)(sub * 128 + wn + nj * 8 + (lane >> 2))) * 8
                                              + (lane & 3) * 2];
#pragma unroll
            for (int mi = 0; mi < 4; mi++)
#pragma unroll
                for (int nj = 0; nj < 4; nj++)
                    mma_tf32(acc[mi][nj], af[mi].x, af[mi].y, af[mi].z, af[mi].w,
                             __float_as_uint(bfv[nj].x), __float_as_uint(bfv[nj].y));
        }
    };

    issue(0);
    issue(1);
    for (int kt = 0; kt < KT; kt++) {
        if (kt == KT - 1) asm volatile("cp.async.wait_group 0;");
        else              asm volatile("cp.async.wait_group 1;");
        __syncthreads();
        if (kt + 2 < KT) issue(kt + 2);
        compute(kt % 3);
    }

    if (EPI == 4) {
        __syncthreads();
        float* st = smx + wid * (64 * 36);
#pragma unroll
        for (int mi = 0; mi < 4; mi++) {
#pragma unroll
            for (int nj = 0; nj < 4; nj++) {
                int col = bn + wn + nj * 8 + (lane & 3) * 2;
#pragma unroll
                for (int half = 0; half < 2; half++) {
                    float v0 = gelu_f(acc[mi][nj][half * 2 + 0] + bias[col]);
                    float v1 = gelu_f(acc[mi][nj][half * 2 + 1] + bias[col + 1]);
                    int rl = mi * 16 + (lane >> 2) + half * 8;
                    *(float2*)&st[rl * 36 + nj * 8 + (lane & 3) * 2] = make_float2(v0, v1);
                }
            }
        }
        __syncwarp();
        const int kgdim_out = Ndim >> 3;
#pragma unroll
        for (int mi = 0; mi < 4; mi++) {
#pragma unroll
            for (int ck = 0; ck < 4; ck++) {
                int rb = mi * 16 + (lane >> 2);
                int cb = ck * 8 + (lane & 3);
                float4 vv;
                vv.x = st[rb * 36 + cb];
                vv.y = st[(rb + 8) * 36 + cb];
                vv.z = st[rb * 36 + cb + 4];
                vv.w = st[(rb + 8) * 36 + cb + 4];
                int mg_out = mg0 + wmg + mi;
                int kg_out = ((bn + wn) >> 3) + ck;
                *(float4*)&C[(((size_t)mg_out * kgdim_out + kg_out) * 32 + lane) * 4] = vv;
            }
        }
        return;
    }

    if (EPI == 5) {
        __syncthreads();
        float* st = smx + wid * (64 * 36);
#pragma unroll
        for (int mi = 0; mi < 4; mi++) {
#pragma unroll
            for (int nj = 0; nj < 4; nj++) {
                int col = bn + wn + nj * 8 + (lane & 3) * 2;
#pragma unroll
                for (int half = 0; half < 2; half++) {
                    float v0 = acc[mi][nj][half * 2 + 0];
                    float v1 = acc[mi][nj][half * 2 + 1];
                    if (bias) { v0 += bias[col]; v1 += bias[col + 1]; }
                    int rl = mi * 16 + (lane >> 2) + half * 8;
                    st[rl * 36 + nj * 8 + (lane & 3) * 2]     = tf32r(v0);
                    st[rl * 36 + nj * 8 + (lane & 3) * 2 + 1] = tf32r(v1);
                }
            }
        }
        __syncwarp();
        const int wm = (wid >> 2) * 64;
        const int hh = (bn + wn) >> 6;
        const int cellb = ((bn + wn) & 63) >> 3;
#pragma unroll
        for (int it = 0; it < 16; it++) {
            int i = it * 32 + lane;
            int jl = i >> 3, cell = i & 7, kg = cell >> 1, half = cell & 1;
            int rg = bm + wm + jl;
            int bb = rg >> 12, jj = rg & 4095;
            int c0 = kg * 8 + half * 2;
            float4 vv = make_float4(st[jl * 36 + c0],     st[jl * 36 + c0 + 4],
                                    st[jl * 36 + c0 + 1], st[jl * 36 + c0 + 5]);
            size_t dst = ((size_t)(bb * 16 + hh) * KK + jj) * 64 + (cellb + kg) * 8 + half * 4;
            *(float4*)&C[dst] = vv;
        }
        return;
    }

    if (EPI == 6) {
        __syncthreads();
        float* st = smx + wid * (64 * 37);
#pragma unroll
        for (int mi = 0; mi < 4; mi++) {
#pragma unroll
            for (int nj = 0; nj < 4; nj++) {
                int col = bn + wn + nj * 8 + (lane & 3) * 2;
#pragma unroll
                for (int half = 0; half < 2; half++) {
                    float v0 = acc[mi][nj][half * 2 + 0];
                    float v1 = acc[mi][nj][half * 2 + 1];
                    if (bias) { v0 += bias[col]; v1 += bias[col + 1]; }
                    int rl = mi * 16 + (lane >> 2) + half * 8;
                    st[rl * 37 + nj * 8 + (lane & 3) * 2]     = tf32r(v0);
                    st[rl * 37 + nj * 8 + (lane & 3) * 2 + 1] = tf32r(v1);
                }
            }
        }
        __syncwarp();
        const int wm = (wid >> 2) * 64;
        const int hh = (bn + wn) >> 6;
        const int db = (bn + wn) & 63;
        int rg = bm + wm;
        int bb = rg >> 12, jloc = rg & 4095, jt = jloc >> 6;
        int r = ((lane >> 2) << 3) + (lane & 3);
        size_t base = ((size_t)(bb * 16 + hh) * 64 + jt) * 4096;
#pragma unroll
        for (int c = 0; c < 32; c++) {
            float2 vv = make_float2(st[r * 37 + c], st[(r + 4) * 37 + c]);
            *(float2*)&C[base + (size_t)(db + c) * 64 + lane * 2] = vv;
        }
        return;
    }

#pragma unroll
    for (int mi = 0; mi < 4; mi++) {
#pragma unroll
        for (int nj = 0; nj < 4; nj++) {
            int row = bm + (wmg + mi) * 16 + (lane >> 2);
            int col = bn + wn + nj * 8 + (lane & 3) * 2;
#pragma unroll
            for (int half = 0; half < 2; half++) {
                int rr = row + half * 8;
                float v0 = acc[mi][nj][half * 2 + 0];
                float v1 = acc[mi][nj][half * 2 + 1];
                if (EPI != 3) { v0 += bias[col]; v1 += bias[col + 1]; }
                if (EPI == 2) {
                    v0 += res[(size_t)rr * Ndim + col];
                    v1 += res[(size_t)rr * Ndim + col + 1];
                }
                float2 w = make_float2(v0, v1);
                *(float2*)&C[(size_t)rr * Ndim + col] = w;
            }
        }
    }
}

// ---------------- pipelined tensor-core flash attention with XL relative term ----------------
#define FB      4608
#define FP_KP   0
#define FP_VP   (2*FB)
#define FP_RP   (4*FB)
#define FP_GS   (5*FB)
#define FP_PS   (FP_GS + 128*200)
#define FP_SMEM ((FP_PS + 128*72) * 4)

__global__ void __launch_bounds__(256, 1)
flash_xl_tc(const float* __restrict__ qg, const float* __restrict__ kpg,
            const float* __restrict__ vtp, const float* __restrict__ rpg,
            const float* __restrict__ ug, const float* __restrict__ vpg,
            const int* __restrict__ iscp, float* __restrict__ apg) {
    extern __shared__ float sm[];
    float* RP = sm + FP_RP;
    float* Gs = sm + FP_GS;
    float* Ps = sm + FP_PS;

    const int tid = threadIdx.x, lane = tid & 31, w = tid >> 5;
    const int i0 = (gridDim.x - 1 - blockIdx.x) * 128;   // longest blocks first
    const int h = blockIdx.y, b = blockIdx.z;
    const int bh = b * N_HEADc + h;
    const int causal = iscp[0];
    const int r0 = w * 16 + (lane >> 2);
    const int kc = lane & 3;
    const int base0 = Tt - 128 - i0;

    {
        const float* qbase = qg + ((size_t)(b * Tt + i0)) * D_MODEL + h * D_HEADc;
#pragma unroll
        for (int p = 0; p < 8; p++) {
            int idx = tid + p * 256;
            int rl = idx >> 4, c4 = (idx & 15) << 2;
            *(float4*)&Ps[rl * 72 + c4] = *(const float4*)&qbase[(size_t)rl * D_MODEL + c4];
        }
    }
    __syncthreads();

    uint32_t aQu[8][4], aQv[8][4];
#pragma unroll
    for (int kk = 0; kk < 8; kk++) {
        int d0 = kk * 8 + kc, d1 = d0 + 4;
        float u0 = __ldg(&ug[h * D_HEADc + d0]),  u1 = __ldg(&ug[h * D_HEADc + d1]);
        float v0 = __ldg(&vpg[h * D_HEADc + d0]), v1 = __ldg(&vpg[h * D_HEADc + d1]);
        float q00 = Ps[r0 * 72 + d0],       q10 = Ps[(r0 + 8) * 72 + d0];
        float q01 = Ps[r0 * 72 + d1],       q11 = Ps[(r0 + 8) * 72 + d1];
        aQu[kk][0] = f2tf32(q00 + u0); aQu[kk][1] = f2tf32(q10 + u0);
        aQu[kk][2] = f2tf32(q01 + u1); aQu[kk][3] = f2tf32(q11 + u1);
        aQv[kk][0] = f2tf32(q00 + v0); aQv[kk][1] = f2tf32(q10 + v0);
        aQv[kk][2] = f2tf32(q01 + v1); aQv[kk][3] = f2tf32(q11 + v1);
    }
    __syncthreads();

#pragma unroll
    for (int hh = 0; hh < 2; hh++) {
        int rb = base0 + hh * 64;
#pragma unroll
        for (int p = 0; p < 4; p++) {
            int c = tid + p * 256;
            int row = c >> 4, part = (c & 15) << 2;
            cp16(&RP[row * 72 + part], &rpg[((size_t)h * KK + rb + row) * 64 + part]);
        }
        asm volatile("cp.async.commit_group;");
        asm volatile("cp.async.wait_group 0;");
        __syncthreads();
#pragma unroll
        for (int nf = 0; nf < 8; nf++) {
            float gc[4] = {0.f, 0.f, 0.f, 0.f};
            int n0 = nf * 8 + (lane >> 2);
#pragma unroll
            for (int kk = 0; kk < 8; kk++) {
                float2 rv = *(const float2*)&RP[n0 * 72 + kk * 8 + kc * 2];
                mma_tf32(gc, aQv[kk][0], aQv[kk][1], aQv[kk][2], aQv[kk][3],
                         __float_as_uint(rv.x), __float_as_uint(rv.y));
            }
            int col = hh * 64 + nf * 8 + kc * 2;
            *(float2*)&Gs[r0 * 200 + col]       = make_float2(gc[0], gc[1]);
            *(float2*)&Gs[(r0 + 8) * 200 + col] = make_float2(gc[2], gc[3]);
        }
        __syncthreads();
    }

    const int njt = causal ? (i0 / 64 + 34) : (KK / 64);
    const float scale = 0.125f;

    auto issue_tiles = [&](int jtn) {
        int st = jtn & 1;
        float* KPd = sm + FP_KP + st * FB;
        float* VPd = sm + FP_VP + st * FB;
        int j0n = jtn * 64;
        int rbn = base0 + j0n + 128;
#pragma unroll
        for (int p = 0; p < 4; p++) {
            int c = tid + p * 256;
            int row = c >> 4, part = (c & 15) << 2;
            cp16(&KPd[row * 72 + part], &kpg[((size_t)bh * KK + j0n + row) * 64 + part]);
        }
#pragma unroll
        for (int p = 0; p < 4; p++) {
            int c = tid + p * 256;
            int row = c >> 4, part = (c & 15) << 2;
            cp16(&VPd[row * 72 + part],
                 &vtp[(((size_t)bh * 64 + jtn) * 64 + row) * 64 + part]);
        }
#pragma unroll
        for (int p = 0; p < 4; p++) {
            int c = tid + p * 256;
            int row = c >> 4, part = (c & 15) << 2;
            int gr = rbn + row; if (gr > KK - 1) gr = KK - 1;
            cp16(&RP[row * 72 + part], &rpg[((size_t)h * KK + gr) * 64 + part]);
        }
        asm volatile("cp.async.commit_group;");
    };

    issue_tiles(0);

    float mi0 = -1e30f, mi1 = -1e30f, li0 = 0.f, li1 = 0.f;
    float oc[8][4];
#pragma unroll
    for (int nf = 0; nf < 8; nf++)
#pragma unroll
        for (int e = 0; e < 4; e++) oc[nf][e] = 0.f;

    int jtb192 = 0;
    for (int jt = 0; jt < njt; jt++) {
        const int j0 = jt * 64;
        asm volatile("cp.async.wait_group 0;");
        __syncthreads();

        {
            int gfill = jtb192 + 128; if (gfill >= 192) gfill -= 192;
#pragma unroll
            for (int nf = 0; nf < 8; nf++) {
                float gc[4] = {0.f, 0.f, 0.f, 0.f};
                int n0 = nf * 8 + (lane >> 2);
#pragma unroll
                for (int kk = 0; kk < 8; kk++) {
                    float2 rv = *(const float2*)&RP[n0 * 72 + kk * 8 + kc * 2];
                    mma_tf32(gc, aQv[kk][0], aQv[kk][1], aQv[kk][2], aQv[kk][3],
                             __float_as_uint(rv.x), __float_as_uint(rv.y));
                }
                int col = gfill + nf * 8 + kc * 2;
                *(float2*)&Gs[r0 * 200 + col]       = make_float2(gc[0], gc[1]);
                *(float2*)&Gs[(r0 + 8) * 200 + col] = make_float2(gc[2], gc[3]);
            }
        }
        __syncthreads();

        if (jt + 1 < njt) issue_tiles(jt + 1);
        __syncwarp();

        const float* KPs = sm + FP_KP + (jt & 1) * FB;
        const float* VPs = sm + FP_VP + (jt & 1) * FB;

        float sc[8][4];
#pragma unroll
        for (int nf = 0; nf < 8; nf++) {
            sc[nf][0] = sc[nf][1] = sc[nf][2] = sc[nf][3] = 0.f;
            int n0 = nf * 8 + (lane >> 2);
#pragma unroll
            for (int kk = 0; kk < 8; kk++) {
                float2 kv = *(const float2*)&KPs[n0 * 72 + kk * 8 + kc * 2];
                mma_tf32(sc[nf], aQu[kk][0], aQu[kk][1], aQu[kk][2], aQu[kk][3],
                         __float_as_uint(kv.x), __float_as_uint(kv.y));
            }
        }

#pragma unroll
        for (int nf = 0; nf < 8; nf++) {
#pragma unroll
            for (int e = 0; e < 4; e++) {
                int rl = r0 + ((e >= 2) ? 8 : 0);
                int jl = nf * 8 + kc * 2 + (e & 1);
                int colA = jtb192 + jl + 127 - rl;
                if (colA >= 192) colA -= 192;
                float val = (sc[nf][e] + Gs[rl * 200 + colA]) * scale;
                if (causal && (j0 + jl) > (i0 + rl + Mm)) val = -1e30f;
                sc[nf][e] = val;
            }
        }

        float rm0 = -1e30f, rm1 = -1e30f;
#pragma unroll
        for (int nf = 0; nf < 8; nf++) {
            rm0 = fmaxf(rm0, fmaxf(sc[nf][0], sc[nf][1]));
            rm1 = fmaxf(rm1, fmaxf(sc[nf][2], sc[nf][3]));
        }
        rm0 = fmaxf(rm0, __shfl_xor_sync(0xffffffffu, rm0, 1));
        rm0 = fmaxf(rm0, __shfl_xor_sync(0xffffffffu, rm0, 2));
        rm1 = fmaxf(rm1, __shfl_xor_sync(0xffffffffu, rm1, 1));
        rm1 = fmaxf(rm1, __shfl_xor_sync(0xffffffffu, rm1, 2));
        float mn0 = fmaxf(mi0, rm0), mn1 = fmaxf(mi1, rm1);
        float corr0 = __expf(mi0 - mn0), corr1 = __expf(mi1 - mn1);
        float sum0 = 0.f, sum1 = 0.f;
#pragma unroll
        for (int nf = 0; nf < 8; nf++) {
            float p0 = __expf(sc[nf][0] - mn0);
            float p1 = __expf(sc[nf][1] - mn0);
            float p2 = __expf(sc[nf][2] - mn1);
            float p3 = __expf(sc[nf][3] - mn1);
            sc[nf][0] = p0; sc[nf][1] = p1; sc[nf][2] = p2; sc[nf][3] = p3;
            sum0 += p0 + p1; sum1 += p2 + p3;
        }
        sum0 += __shfl_xor_sync(0xffffffffu, sum0, 1);
        sum0 += __shfl_xor_sync(0xffffffffu, sum0, 2);
        sum1 += __shfl_xor_sync(0xffffffffu, sum1, 1);
        sum1 += __shfl_xor_sync(0xffffffffu, sum1, 2);
        li0 = li0 * corr0 + sum0; li1 = li1 * corr1 + sum1;
        mi0 = mn0; mi1 = mn1;
#pragma unroll
        for (int nf = 0; nf < 8; nf++) {
            oc[nf][0] *= corr0; oc[nf][1] *= corr0;
            oc[nf][2] *= corr1; oc[nf][3] *= corr1;
        }

#pragma unroll
        for (int nf = 0; nf < 8; nf++) {
            int col = nf * 8 + kc * 2;
            *(float2*)&Ps[r0 * 72 + col]       = make_float2(sc[nf][0], sc[nf][1]);
            *(float2*)&Ps[(r0 + 8) * 72 + col] = make_float2(sc[nf][2], sc[nf][3]);
        }
        __syncwarp();
        uint32_t pa[8][4];
#pragma unroll
        for (int kk = 0; kk < 8; kk++) {
            int d0 = kk * 8 + kc, d1 = d0 + 4;
            pa[kk][0] = f2tf32(Ps[r0 * 72 + d0]);
            pa[kk][1] = f2tf32(Ps[(r0 + 8) * 72 + d0]);
            pa[kk][2] = f2tf32(Ps[r0 * 72 + d1]);
            pa[kk][3] = f2tf32(Ps[(r0 + 8) * 72 + d1]);
        }
#pragma unroll
        for (int nf = 0; nf < 8; nf++) {
            int n0 = nf * 8 + (lane >> 2);
#pragma unroll
            for (int kk = 0; kk < 8; kk++) {
                float2 vv = *(const float2*)&VPs[n0 * 72 + kk * 8 + kc * 2];
                mma_tf32(oc[nf], pa[kk][0], pa[kk][1], pa[kk][2], pa[kk][3],
                         __float_as_uint(vv.x), __float_as_uint(vv.y));
            }
        }

        jtb192 += 64; if (jtb192 >= 192) jtb192 -= 192;
    }

    float inv0 = 1.f / li0, inv1 = 1.f / li1;
#pragma unroll
    for (int nf = 0; nf < 8; nf++) {
        int col = nf * 8 + kc * 2;
        *(float2*)&Ps[r0 * 72 + col]       = make_float2(oc[nf][0] * inv0, oc[nf][1] * inv0);
        *(float2*)&Ps[(r0 + 8) * 72 + col] = make_float2(oc[nf][2] * inv1, oc[nf][3] * inv1);
    }
    __syncwarp();
    const int mg_out = ((b * Tt + i0) >> 4) + w;
#pragma unroll
    for (int kk = 0; kk < 8; kk++) {
        float4 vv;
        vv.x = Ps[r0 * 72 + kk * 8 + kc];
        vv.y = Ps[(r0 + 8) * 72 + kk * 8 + kc];
        vv.z = Ps[r0 * 72 + kk * 8 + kc + 4];
        vv.w = Ps[(r0 + 8) * 72 + kk * 8 + kc + 4];
        int kg_out = h * 8 + kk;
        *(float4*)&apg[(((size_t)mg_out * 128 + kg_out) * 32 + lane) * 4] = vv;
    }
}

// ---------------- LayerNorm over last dim (D=1024), one block per row ----------------
__global__ void __launch_bounds__(256)
layernorm_k(const float* __restrict__ in, const float* __restrict__ g,
            const float* __restrict__ be, float* __restrict__ out) {
    __shared__ float red[34];
    const int row = blockIdx.x;
    const int tid = threadIdx.x;
    float4 v = ((const float4*)(in + (size_t)row * D_MODEL))[tid];

    float s = v.x + v.y + v.z + v.w;
    int lane = tid & 31, wid = tid >> 5;
#pragma unroll
    for (int off = 16; off >= 1; off >>= 1) s += __shfl_xor_sync(0xffffffffu, s, off);
    if (lane == 0) red[wid] = s;
    __syncthreads();
    if (tid == 0) {
        float t = 0.f;
#pragma unroll
        for (int w2 = 0; w2 < 8; w2++) t += red[w2];
        red[32] = t;
    }
    __syncthreads();
    float mu = red[32] * (1.f / (float)D_MODEL);

    float dx0 = v.x - mu, dx1 = v.y - mu, dx2 = v.z - mu, dx3 = v.w - mu;
    float sq = dx0 * dx0 + dx1 * dx1 + dx2 * dx2 + dx3 * dx3;
#pragma unroll
    for (int off = 16; off >= 1; off >>= 1) sq += __shfl_xor_sync(0xffffffffu, sq, off);
    if (lane == 0) red[wid] = sq;
    __syncthreads();
    if (tid == 0) {
        float t = 0.f;
#pragma unroll
        for (int w2 = 0; w2 < 8; w2++) t += red[w2];
        red[33] = t;
    }
    __syncthreads();
    float rstd = rsqrtf(red[33] * (1.f / (float)D_MODEL) + 1e-5f);

    float4 gv = ((const float4*)g)[tid];
    float4 bv = ((const float4*)be)[tid];
    float4 o;
    o.x = dx0 * rstd * gv.x + bv.x;
    o.y = dx1 * rstd * gv.y + bv.y;
    o.z = dx2 * rstd * gv.z + bv.z;
    o.w = dx3 * rstd * gv.w + bv.w;
    ((float4*)(out + (size_t)row * D_MODEL))[tid] = o;
}

// ---------------- launch ----------------
extern "C" void kernel_launch(void* const* d_in, const int* in_sizes, int n_in,
                              void* d_out, int out_size) {
    const float* x    = (const float*)d_in[0];
    const float* mem  = (const float*)d_in[1];
    const float* Wq   = (const float*)d_in[2];
    const float* bq   = (const float*)d_in[3];
    const float* Wk   = (const float*)d_in[4];
    const float* bk   = (const float*)d_in[5];
    const float* Wv   = (const float*)d_in[6];
    const float* bv   = (const float*)d_in[7];
    const float* Wo   = (const float*)d_in[8];
    const float* bo   = (const float*)d_in[9];
    const float* Wr   = (const float*)d_in[10];
    const float* u    = (const float*)d_in[11];
    const float* vpar = (const float*)d_in[12];
    const float* g1   = (const float*)d_in[13];
    const float* be1  = (const float*)d_in[14];
    const float* g2   = (const float*)d_in[15];
    const float* be2  = (const float*)d_in[16];
    const float* W1   = (const float*)d_in[17];
    const float* b1   = (const float*)d_in[18];
    const float* W2   = (const float*)d_in[19];
    const float* b2   = (const float*)d_in[20];
    const int*   isc  = (const int*)d_in[21];
    float* out = (float*)d_out;

    float *P, *q, *s, *h, *invf;
    float *xp, *cp, *ap, *hp, *f1p;
    float *wqp, *wkp, *wvp, *wrp, *wop, *w1p, *w2p;
    float *kp, *vp, *rp;
    cudaGetSymbolAddress((void**)&P,    g_P);
    cudaGetSymbolAddress((void**)&q,    g_q);
    cudaGetSymbolAddress((void**)&s,    g_s);
    cudaGetSymbolAddress((void**)&h,    g_h);
    cudaGetSymbolAddress((void**)&invf, g_invf);
    cudaGetSymbolAddress((void**)&xp,   g_xp);
    cudaGetSymbolAddress((void**)&cp,   g_cp);
    cudaGetSymbolAddress((void**)&ap,   g_ap);
    cudaGetSymbolAddress((void**)&hp,   g_hp);
    cudaGetSymbolAddress((void**)&f1p,  g_f1p);
    cudaGetSymbolAddress((void**)&wqp,  g_wqp);
    cudaGetSymbolAddress((void**)&wkp,  g_wkp);
    cudaGetSymbolAddress((void**)&wvp,  g_wvp);
    cudaGetSymbolAddress((void**)&wrp,  g_wrp);
    cudaGetSymbolAddress((void**)&wop,  g_wop);
    cudaGetSymbolAddress((void**)&w1p,  g_w1p);
    cudaGetSymbolAddress((void**)&w2p,  g_w2p);
    cudaGetSymbolAddress((void**)&kp,   g_kp);
    cudaGetSymbolAddress((void**)&vp,   g_vp);
    cudaGetSymbolAddress((void**)&rp,   g_rp);

    cudaFuncSetAttribute(tgemm<0>, cudaFuncAttributeMaxDynamicSharedMemorySize, TG2_SMEM);
    cudaFuncSetAttribute(tgemm<2>, cudaFuncAttributeMaxDynamicSharedMemorySize, TG2_SMEM);
    cudaFuncSetAttribute(tgemm<4>, cudaFuncAttributeMaxDynamicSharedMemorySize, TG2_SMEM);
    cudaFuncSetAttribute(tgemm<5>, cudaFuncAttributeMaxDynamicSharedMemorySize, TG2_SMEM);
    cudaFuncSetAttribute(tgemm<6>, cudaFuncAttributeMaxDynamicSharedMemorySize, TG2_SMEM);
    cudaFuncSetAttribute(flash_xl_tc, cudaFuncAttributeMaxDynamicSharedMemorySize, FP_SMEM);

    const int TPB = 256;
    fill_invf<<<1, 512>>>(invf);
    fill_pos_packed<<<(KK * D_MODEL + TPB - 1) / TPB, TPB>>>(P, invf);

    // fused packs
    {
        int total_w = 5 * (128 * 1024) + 128 * 4096 + 512 * 1024;
        pack_w_all<<<(total_w + TPB - 1) / TPB, TPB>>>(Wq, Wk, Wv, Wr, Wo, W1, W2,
                                                       wqp, wkp, wvp, wrp, wop, w1p, w2p);
    }
    pack_a<<<((ROWS_X / 16) * (D_MODEL / 8) * 32 + TPB - 1) / TPB, TPB>>>(x, xp, ROWS_X, D_MODEL);
    pack_ac<<<((ROWS_C / 16) * (D_MODEL / 8) * 32 + TPB - 1) / TPB, TPB>>>(x, mem, cp);

    // projections: q plain; k/r/v written DIRECTLY in flash-packed layouts
    tgemm<0><<<dim3(D_MODEL / 128, ROWS_X / 128), 256, TG2_SMEM>>>(xp, wqp, bq, nullptr, q, D_MODEL, D_MODEL);
    tgemm<5><<<dim3(D_MODEL / 128, ROWS_C / 128), 256, TG2_SMEM>>>(cp, wkp, bk, nullptr, kp, D_MODEL, D_MODEL);
    tgemm<6><<<dim3(D_MODEL / 128, ROWS_C / 128), 256, TG2_SMEM>>>(cp, wvp, bv, nullptr, vp, D_MODEL, D_MODEL);
    tgemm<5><<<dim3(D_MODEL / 128, KK / 128), 256, TG2_SMEM>>>(P, wrp, nullptr, nullptr, rp, D_MODEL, D_MODEL);

    // attention (pipelined tensor-core flash; writes packed attn)
    flash_xl_tc<<<dim3(Tt / 128, N_HEADc, Bb), 256, FP_SMEM>>>(q, kp, vp, rp, u, vpar, isc, ap);

    // o-proj + residual, LN1
    tgemm<2><<<dim3(D_MODEL / 128, ROWS_X / 128), 256, TG2_SMEM>>>(ap, wop, bo, x, s, D_MODEL, D_MODEL);
    layernorm_k<<<ROWS_X, 256>>>(s, g1, be1, h);

    // FFN (FFN1 writes packed directly)
    pack_a<<<((ROWS_X / 16) * (D_MODEL / 8) * 32 + TPB - 1) / TPB, TPB>>>(h, hp, ROWS_X, D_MODEL);
    tgemm<4><<<dim3(FFN_H / 128, ROWS_X / 128), 256, TG2_SMEM>>>(hp, w1p, b1, nullptr, f1p, FFN_H, D_MODEL);
    tgemm<2><<<dim3(D_MODEL / 128, ROWS_X / 128), 256, TG2_SMEM>>>(f1p, w2p, b2, h, s, D_MODEL, FFN_H);
    layernorm_k<<<ROWS_X, 256>>>(s, g2, be2, out);
}